// round 11
// baseline (speedup 1.0000x reference)
#include <cuda_runtime.h>
#include <math.h>

#define NN 4096
#define FH 256
#define CL 128
#define MAXDEG 128
#define MAXM 128
#define MAXC 64
#define MAXR (MAXDEG + MAXC)
#define CELLCAP 32
#define NEGINF (-1e9f)
#define KS 16

// ---------- scratch ----------
__device__ int   g_adj_idx[NN * MAXDEG];
__device__ int   g_adj_cnt[NN];
__device__ int   g_mf_idx[NN * MAXM];
__device__ float g_mf_val[NN * MAXM];
__device__ int   g_mf_cnt[NN];
__device__ float g_m_thr[NN];
__device__ int   g_m_idx[NN * MAXM];
__device__ float g_m_val[NN * MAXM];
__device__ int   g_m_cnt[NN];
__device__ float g_dinvM[NN];
__device__ float g_Wx[NN * FH];
__device__ float g_XWM[NN * FH];
__device__ float g_as[NN * 2];
__device__ float g_ad[NN * 2];
__device__ float g_h[NN * FH];
__device__ float g_pu[NN], g_pv[NN], g_ru[NN], g_rv[NN];
__device__ int   g_cell_cnt[4096];
__device__ int   g_cell_nodes[4096 * CELLCAP];
__device__ int   g_cand_idx[NN * MAXC];
__device__ float g_cand_z[NN * MAXC];
__device__ int   g_cand_cnt[NN];
__device__ float g_thr2[NN];
__device__ int   g_ref_idx[NN * MAXR];
__device__ float g_ref_w[NN * MAXR];
__device__ int   g_ref_cnt[NN];
__device__ float g_dinv_ref[NN];
__device__ float g_HW[NN * CL];
__device__ float g_S[NN * CL];
__device__ float g_T[NN * CL];
__device__ float g_Cpart[KS * 128 * 256];
__device__ float g_Ac[128 * 128];
__device__ float g_cthr[128];

// ---------- helpers ----------
__device__ __forceinline__ float hc_gate(float logit, float tau) {
    float t = fmaxf(tau, 0.1f);
    float s = 1.f / (1.f + expf(-logit / t));
    s = s * 1.2f - 0.1f;
    return fminf(fmaxf(s, 0.f), 1.f);
}
__device__ __forceinline__ float mhat_bs(int i, int j) {
    int c = g_m_cnt[i];
    const int* ip = &g_m_idx[i * MAXM];
    int lo = 0, hi = c;
    while (lo < hi) { int mid = (lo + hi) >> 1; if (ip[mid] < j) lo = mid + 1; else hi = mid; }
    return (lo < c && ip[lo] == j) ? g_m_val[i * MAXM + lo] : 0.f;
}

// ---------- scan bodies ----------
__device__ void adj_row_body(const float* __restrict__ A, int gw, int lane) {
    const float4* row = (const float4*)(A + (size_t)gw * NN);
    unsigned below = (1u << lane) - 1;
    int c = 0;
    #pragma unroll 4
    for (int b = 0; b < NN / 4; b += 32) {
        float4 v = row[b + lane];
        bool p0 = v.x > 0.f, p1 = v.y > 0.f, p2 = v.z > 0.f, p3 = v.w > 0.f;
        unsigned m0 = __ballot_sync(~0u, p0), m1 = __ballot_sync(~0u, p1);
        unsigned m2 = __ballot_sync(~0u, p2), m3 = __ballot_sync(~0u, p3);
        int base = c + __popc(m0 & below) + __popc(m1 & below) + __popc(m2 & below) + __popc(m3 & below);
        int col = (b + lane) * 4, o = 0;
        if (p0 && base + o < MAXDEG) g_adj_idx[gw * MAXDEG + base + o] = col;
        if (p0) o++;
        if (p1 && base + o < MAXDEG) g_adj_idx[gw * MAXDEG + base + o] = col + 1;
        if (p1) o++;
        if (p2 && base + o < MAXDEG) g_adj_idx[gw * MAXDEG + base + o] = col + 2;
        if (p2) o++;
        if (p3 && base + o < MAXDEG) g_adj_idx[gw * MAXDEG + base + o] = col + 3;
        c += __popc(m0) + __popc(m1) + __popc(m2) + __popc(m3);
    }
    if (lane == 0) g_adj_cnt[gw] = min(c, MAXDEG);
}

__device__ void motif_row_body(const float* __restrict__ A, int gw, int lane) {
    const float4* row = (const float4*)(A + (size_t)gw * NN);
    unsigned below = (1u << lane) - 1;
    int c = 0;
    #pragma unroll 4
    for (int b = 0; b < NN / 4; b += 32) {
        float4 v = row[b + lane];
        bool p0 = v.x > 0.f, p1 = v.y > 0.f, p2 = v.z > 0.f, p3 = v.w > 0.f;
        unsigned m0 = __ballot_sync(~0u, p0), m1 = __ballot_sync(~0u, p1);
        unsigned m2 = __ballot_sync(~0u, p2), m3 = __ballot_sync(~0u, p3);
        int base = c + __popc(m0 & below) + __popc(m1 & below) + __popc(m2 & below) + __popc(m3 & below);
        int col = (b + lane) * 4, o = 0;
        if (p0 && base + o < MAXM) { g_mf_idx[gw * MAXM + base + o] = col;     g_mf_val[gw * MAXM + base + o] = v.x; }
        if (p0) o++;
        if (p1 && base + o < MAXM) { g_mf_idx[gw * MAXM + base + o] = col + 1; g_mf_val[gw * MAXM + base + o] = v.y; }
        if (p1) o++;
        if (p2 && base + o < MAXM) { g_mf_idx[gw * MAXM + base + o] = col + 2; g_mf_val[gw * MAXM + base + o] = v.z; }
        if (p2) o++;
        if (p3 && base + o < MAXM) { g_mf_idx[gw * MAXM + base + o] = col + 3; g_mf_val[gw * MAXM + base + o] = v.w; }
        c += __popc(m0) + __popc(m1) + __popc(m2) + __popc(m3);
    }
    c = min(c, MAXM);
    __syncwarp();
    float vv[4];
    #pragma unroll
    for (int s = 0; s < 4; s++) {
        int t = s * 32 + lane;
        vv[s] = (t < c) ? g_mf_val[gw * MAXM + t] : -2.f;
    }
    float thr = 0.f;
    if (c > 8) {
        for (int r = 0; r < 8; r++) {
            float lm = fmaxf(fmaxf(vv[0], vv[1]), fmaxf(vv[2], vv[3]));
            float wm = lm;
            for (int o = 16; o; o >>= 1) wm = fmaxf(wm, __shfl_xor_sync(~0u, wm, o));
            unsigned who = __ballot_sync(~0u, lm == wm);
            if (lane == (__ffs(who) - 1)) {
                #pragma unroll
                for (int s = 0; s < 4; s++) if (vv[s] == wm) { vv[s] = -2.f; break; }
            }
            thr = wm;
        }
    }
    if (lane == 0) { g_mf_cnt[gw] = c; g_m_thr[gw] = thr; }
}

// fused balanced scan: blocks 0-511 adj (0-15 also zero cells), 512-1023 motif
__global__ void k_scan(const float* __restrict__ A_in, const float* __restrict__ A_motif) {
    int b = blockIdx.x, lane = threadIdx.x & 31, wid = threadIdx.x >> 5;
    if (b < 16) g_cell_cnt[b * 256 + threadIdx.x] = 0;
    if (b < 512) adj_row_body(A_in, b * 8 + wid, lane);
    else         motif_row_body(A_motif, (b - 512) * 8 + wid, lane);
}

__global__ void k_mfilter() {
    int gw = (blockIdx.x * blockDim.x + threadIdx.x) >> 5;
    int lane = threadIdx.x & 31;
    if (gw >= NN) return;
    int i = gw, cnt = g_mf_cnt[i], out = 0;
    float thrI = g_m_thr[i], wsum = 0.f;
    for (int base = 0; base < cnt; base += 32) {
        int t = base + lane; bool ok = t < cnt; int j = 0; float v = 0.f;
        if (ok) {
            j = g_mf_idx[i * MAXM + t]; v = g_mf_val[i * MAXM + t];
            ok = (v >= thrI) || (v >= g_m_thr[j]);
        }
        unsigned m = __ballot_sync(0xffffffffu, ok);
        int pos = out + __popc(m & ((1u << lane) - 1));
        if (ok) { g_m_idx[i * MAXM + pos] = j; g_m_val[i * MAXM + pos] = v; wsum += v; }
        out += __popc(m);
    }
    for (int o = 16; o; o >>= 1) wsum += __shfl_down_sync(0xffffffffu, wsum, o);
    if (lane == 0) { g_m_cnt[i] = out; g_dinvM[i] = (wsum > 0.f) ? rsqrtf(wsum) : 0.f; }
}

// C[M,Nc] = A[M,K] @ B[K,Nc]; 64x64 tile, 4x4 micro, double-buffered,
// LDS.128 vectorized smem reads (pad 68 -> 16B-aligned rows).
__global__ void k_gemm(const float* __restrict__ A, const float* __restrict__ B,
                       float* __restrict__ C, int M, int Nc, int K) {
    __shared__ float As[2][16][68], Bs[2][16][68];
    int bm = blockIdx.y * 64, bn = blockIdx.x * 64;
    int tid = threadIdx.x, tr = tid >> 4, tc = tid & 15;
    int am[4], ak[4], bk[4], bnn[4];
    float ra[4], rb[4];
    #pragma unroll
    for (int l = 0; l < 4; l++) {
        int e = tid + l * 256;
        am[l] = e >> 4; ak[l] = e & 15;
        bk[l] = e >> 6; bnn[l] = e & 63;
    }
    int nP = K / 16;
    #pragma unroll
    for (int l = 0; l < 4; l++) {
        ra[l] = A[(size_t)(bm + am[l]) * K + ak[l]];
        rb[l] = B[(size_t)bk[l] * Nc + bn + bnn[l]];
    }
    #pragma unroll
    for (int l = 0; l < 4; l++) {
        As[0][ak[l]][am[l]] = ra[l];
        Bs[0][bk[l]][bnn[l]] = rb[l];
    }
    __syncthreads();
    float acc[4][4] = {};
    for (int p = 0; p < nP; p++) {
        int cur = p & 1;
        if (p + 1 < nP) {
            int k0 = (p + 1) * 16;
            #pragma unroll
            for (int l = 0; l < 4; l++) {
                ra[l] = A[(size_t)(bm + am[l]) * K + k0 + ak[l]];
                rb[l] = B[(size_t)(k0 + bk[l]) * Nc + bn + bnn[l]];
            }
        }
        #pragma unroll
        for (int kk = 0; kk < 16; kk++) {
            float4 a4 = *reinterpret_cast<const float4*>(&As[cur][kk][tr * 4]);
            float4 b4 = *reinterpret_cast<const float4*>(&Bs[cur][kk][tc * 4]);
            float a[4] = {a4.x, a4.y, a4.z, a4.w};
            float b[4] = {b4.x, b4.y, b4.z, b4.w};
            #pragma unroll
            for (int r = 0; r < 4; r++)
                #pragma unroll
                for (int c = 0; c < 4; c++) acc[r][c] += a[r] * b[c];
        }
        if (p + 1 < nP) {
            #pragma unroll
            for (int l = 0; l < 4; l++) {
                As[cur ^ 1][ak[l]][am[l]] = ra[l];
                Bs[cur ^ 1][bk[l]][bnn[l]] = rb[l];
            }
        }
        __syncthreads();
    }
    #pragma unroll
    for (int r = 0; r < 4; r++)
        #pragma unroll
        for (int c = 0; c < 4; c++)
            C[(size_t)(bm + tr * 4 + r) * Nc + bn + tc * 4 + c] = acc[r][c];
}

// Cpart[ks][M,Nc] = A[kslice,M]^T @ B[kslice,Nc]; double-buffered + LDS.128.
__global__ void k_gemm_tn(const float* __restrict__ A, const float* __restrict__ B,
                          float* __restrict__ Cpart, int M, int Nc, int K) {
    __shared__ float As[2][16][68], Bs[2][16][68];
    int ks = blockIdx.z, kbeg = ks * (K / KS);
    int nP = (K / KS) / 16;
    int bm = blockIdx.y * 64, bn = blockIdx.x * 64;
    int tid = threadIdx.x, tr = tid >> 4, tc = tid & 15;
    int lk[4], ln[4];
    float ra[4], rb[4];
    #pragma unroll
    for (int l = 0; l < 4; l++) {
        int e = tid + l * 256;
        lk[l] = e >> 6; ln[l] = e & 63;
    }
    #pragma unroll
    for (int l = 0; l < 4; l++) {
        ra[l] = A[(size_t)(kbeg + lk[l]) * M + bm + ln[l]];
        rb[l] = B[(size_t)(kbeg + lk[l]) * Nc + bn + ln[l]];
    }
    #pragma unroll
    for (int l = 0; l < 4; l++) {
        As[0][lk[l]][ln[l]] = ra[l];
        Bs[0][lk[l]][ln[l]] = rb[l];
    }
    __syncthreads();
    float acc[4][4] = {};
    for (int p = 0; p < nP; p++) {
        int cur = p & 1;
        if (p + 1 < nP) {
            int k0 = kbeg + (p + 1) * 16;
            #pragma unroll
            for (int l = 0; l < 4; l++) {
                ra[l] = A[(size_t)(k0 + lk[l]) * M + bm + ln[l]];
                rb[l] = B[(size_t)(k0 + lk[l]) * Nc + bn + ln[l]];
            }
        }
        #pragma unroll
        for (int kk = 0; kk < 16; kk++) {
            float4 a4 = *reinterpret_cast<const float4*>(&As[cur][kk][tr * 4]);
            float4 b4 = *reinterpret_cast<const float4*>(&Bs[cur][kk][tc * 4]);
            float a[4] = {a4.x, a4.y, a4.z, a4.w};
            float b[4] = {b4.x, b4.y, b4.z, b4.w};
            #pragma unroll
            for (int r = 0; r < 4; r++)
                #pragma unroll
                for (int c = 0; c < 4; c++) acc[r][c] += a[r] * b[c];
        }
        if (p + 1 < nP) {
            #pragma unroll
            for (int l = 0; l < 4; l++) {
                As[cur ^ 1][lk[l]][ln[l]] = ra[l];
                Bs[cur ^ 1][lk[l]][ln[l]] = rb[l];
            }
        }
        __syncthreads();
    }
    float* Cp = Cpart + (size_t)ks * M * Nc;
    #pragma unroll
    for (int r = 0; r < 4; r++)
        #pragma unroll
        for (int c = 0; c < 4; c++)
            Cp[(size_t)(bm + tr * 4 + r) * Nc + bn + tc * 4 + c] = acc[r][c];
}

__global__ void k_reduce_part(float* __restrict__ dst, int MN) {
    int t = blockIdx.x * blockDim.x + threadIdx.x;
    if (t >= MN) return;
    float s = 0.f;
    for (int z = 0; z < KS; z++) s += g_Cpart[(size_t)z * MN + t];
    dst[t] = s;
}

__global__ void k_attn_coef(const float* __restrict__ asw, const float* __restrict__ adw) {
    int gw = (blockIdx.x * blockDim.x + threadIdx.x) >> 5;
    int lane = threadIdx.x & 31;
    if (gw >= NN * 2) return;
    int node = gw >> 1, hh = gw & 1;
    const float* row = g_Wx + (size_t)node * FH + hh * 128;
    float s = 0.f, d = 0.f;
    for (int k = lane; k < 128; k += 32) {
        float w = row[k];
        s += w * asw[hh * 128 + k];
        d += w * adw[hh * 128 + k];
    }
    for (int o = 16; o; o >>= 1) {
        s += __shfl_down_sync(0xffffffffu, s, o);
        d += __shfl_down_sync(0xffffffffu, d, o);
    }
    if (lane == 0) { g_as[node * 2 + hh] = s; g_ad[node * 2 + hh] = d; }
}

__global__ void k_aggregate(
    const float* __restrict__ gat_b,
    const float* __restrict__ bnAg, const float* __restrict__ bnAb,
    const float* __restrict__ bnAm, const float* __restrict__ bnAv,
    const float* __restrict__ gcnMb,
    const float* __restrict__ bnMg, const float* __restrict__ bnMb,
    const float* __restrict__ bnMm, const float* __restrict__ bnMv,
    const float* __restrict__ mu_, const float* __restrict__ prune_w,
    const float* __restrict__ rewire_w)
{
    __shared__ int sj[MAXDEG + 1];
    __shared__ float se0[MAXDEG + 1], se1[MAXDEG + 1];
    __shared__ int smj[MAXM];
    __shared__ float smc[MAXM];
    __shared__ float rA[256], rB[256];
    int i = blockIdx.x, tid = threadIdx.x;
    int deg = g_adj_cnt[i], tot = deg + 1;
    float ad0 = g_ad[2 * i], ad1 = g_ad[2 * i + 1];
    for (int t = tid; t < tot; t += 256) {
        int j = (t < deg) ? g_adj_idx[i * MAXDEG + t] : i;
        sj[t] = j;
        float e0 = ad0 + g_as[2 * j], e1 = ad1 + g_as[2 * j + 1];
        se0[t] = (e0 > 0.f) ? e0 : 0.2f * e0;
        se1[t] = (e1 > 0.f) ? e1 : 0.2f * e1;
    }
    int mc = g_m_cnt[i];
    for (int t = tid; t < mc; t += 256) {
        int j = g_m_idx[i * MAXM + t];
        smj[t] = j;
        smc[t] = g_m_val[i * MAXM + t] * g_dinvM[j];
    }
    __syncthreads();
    float lm0 = -3.4e38f, lm1 = -3.4e38f;
    for (int t = tid; t < tot; t += 256) { lm0 = fmaxf(lm0, se0[t]); lm1 = fmaxf(lm1, se1[t]); }
    rA[tid] = lm0; rB[tid] = lm1; __syncthreads();
    for (int s = 128; s > 0; s >>= 1) {
        if (tid < s) { rA[tid] = fmaxf(rA[tid], rA[tid + s]); rB[tid] = fmaxf(rB[tid], rB[tid + s]); }
        __syncthreads();
    }
    float M0 = rA[0], M1 = rB[0]; __syncthreads();
    float ls0 = 0.f, ls1 = 0.f;
    for (int t = tid; t < tot; t += 256) {
        float e0 = expf(se0[t] - M0); se0[t] = e0; ls0 += e0;
        float e1 = expf(se1[t] - M1); se1[t] = e1; ls1 += e1;
    }
    rA[tid] = ls0; rB[tid] = ls1; __syncthreads();
    for (int s = 128; s > 0; s >>= 1) {
        if (tid < s) { rA[tid] += rA[tid + s]; rB[tid] += rB[tid + s]; }
        __syncthreads();
    }
    float D0 = rA[0], D1 = rB[0]; __syncthreads();

    int d = tid, head = d >> 7;
    float Dh = head ? D1 : D0;
    const float* se = head ? se1 : se0;
    float accA = 0.f;
    #pragma unroll 4
    for (int k = 0; k < tot; k++) accA += se[k] * g_Wx[(size_t)sj[k] * FH + d];
    float hA = accA / Dh + gat_b[d];
    hA = (hA - bnAm[d]) * bnAg[d] * rsqrtf(bnAv[d] + 1e-5f) + bnAb[d];
    hA = (hA > 0.f) ? hA : expm1f(hA);

    float accM = 0.f;
    #pragma unroll 4
    for (int k = 0; k < mc; k++) accM += smc[k] * g_XWM[(size_t)smj[k] * FH + d];
    float hM = g_dinvM[i] * accM + gcnMb[d];
    hM = (hM - bnMm[d]) * bnMg[d] * rsqrtf(bnMv[d] + 1e-5f) + bnMb[d];
    hM = (hM > 0.f) ? hM : expm1f(hM);

    float mu = mu_[0];
    float sp = (mu > 20.f) ? mu : log1pf(expf(mu));
    float hv = hA + sp * hM;
    g_h[(size_t)i * FH + d] = hv;

    rA[tid] = hv * prune_w[d]; rB[tid] = hv * prune_w[256 + d]; __syncthreads();
    for (int s = 128; s > 0; s >>= 1) {
        if (tid < s) { rA[tid] += rA[tid + s]; rB[tid] += rB[tid + s]; }
        __syncthreads();
    }
    float r0 = rA[0], r1 = rB[0]; __syncthreads();
    rA[tid] = hv * rewire_w[d]; rB[tid] = hv * rewire_w[256 + d]; __syncthreads();
    for (int s = 128; s > 0; s >>= 1) {
        if (tid < s) { rA[tid] += rA[tid + s]; rB[tid] += rB[tid + s]; }
        __syncthreads();
    }
    if (tid == 0) { g_pu[i] = r0; g_pv[i] = r1; g_ru[i] = rA[0]; g_rv[i] = rB[0]; }
}

__global__ void k_cells(const float* __restrict__ coords) {
    int i = blockIdx.x * blockDim.x + threadIdx.x;
    if (i >= NN) return;
    int cx = (int)coords[2 * i], cy = (int)coords[2 * i + 1];
    int p = atomicAdd(&g_cell_cnt[cx * 64 + cy], 1);
    if (p < CELLCAP) g_cell_nodes[(cx * 64 + cy) * CELLCAP + p] = i;
}

__global__ void k_cells_sort() {
    int c = blockIdx.x * blockDim.x + threadIdx.x;
    if (c >= 4096) return;
    int n = min(g_cell_cnt[c], CELLCAP);
    int* a = &g_cell_nodes[c * CELLCAP];
    for (int x = 1; x < n; x++) {
        int v = a[x], y = x - 1;
        while (y >= 0 && a[y] > v) { a[y + 1] = a[y]; y--; }
        a[y + 1] = v;
    }
}

__global__ void k_candidates(const float* __restrict__ coords, const float* __restrict__ A_in,
                             const float* __restrict__ rw, const float* __restrict__ rb_,
                             const float* __restrict__ tau_) {
    int gw = (blockIdx.x * blockDim.x + threadIdx.x) >> 5;
    int lane = threadIdx.x & 31;
    if (gw >= NN) return;
    int i = gw;
    float tau = tau_[0], rw2 = rw[512], rb = rb_[0];
    int cx = (int)coords[2 * i], cy = (int)coords[2 * i + 1];
    const int ox[12] = {-2,-1,-1,-1, 0, 0, 0, 0, 1, 1, 1, 2};
    const int oy[12] = { 0,-1, 0, 1,-2,-1, 1, 2,-1, 0, 1, 0};
    float rui = g_ru[i], rvi = g_rv[i];
    int cnt = 0;
    float m1 = NEGINF, m2 = NEGINF;
    for (int o = 0; o < 12; o++) {
        int nx = cx + ox[o], ny = cy + oy[o];
        if (nx < 0 || nx >= 64 || ny < 0 || ny >= 64) continue;
        int cell = nx * 64 + ny;
        int cc = min(g_cell_cnt[cell], CELLCAP);
        for (int base = 0; base < cc; base += 32) {
            int t = base + lane;
            bool ok = t < cc;
            int j = 0; float z = 0.f;
            if (ok) {
                j = g_cell_nodes[cell * CELLCAP + t];
                ok = A_in[(size_t)i * NN + j] < 1e-6f;
            }
            if (ok) {
                float ruv = (i < j) ? (rui + g_rv[j]) : (g_ru[j] + rvi);
                z = hc_gate(ruv + rw2 * mhat_bs(i, j) + rb, tau);
                if (z > m1) { m2 = m1; m1 = z; } else if (z > m2) { m2 = z; }
            }
            unsigned m = __ballot_sync(~0u, ok);
            int pos = cnt + __popc(m & ((1u << lane) - 1));
            if (ok && pos < MAXC) { g_cand_idx[i * MAXC + pos] = j; g_cand_z[i * MAXC + pos] = z; }
            cnt += __popc(m);
        }
    }
    for (int o = 16; o; o >>= 1) {
        float om1 = __shfl_xor_sync(~0u, m1, o);
        float om2 = __shfl_xor_sync(~0u, m2, o);
        float hi = fmaxf(m1, om1), lo = fminf(m1, om1);
        m2 = fmaxf(lo, fmaxf(m2, om2));
        m1 = hi;
    }
    if (lane == 0) { g_cand_cnt[i] = min(cnt, MAXC); g_thr2[i] = m2; }
}

__global__ void k_refined(const float* __restrict__ prune_w, const float* __restrict__ prune_b,
                          const float* __restrict__ tau_) {
    int gw = (blockIdx.x * blockDim.x + threadIdx.x) >> 5;
    int lane = threadIdx.x & 31;
    if (gw >= NN) return;
    int i = gw;
    float tau = tau_[0], pw2 = prune_w[512], pb = prune_b[0];
    int deg = g_adj_cnt[i];
    float wsum = 0.f;
    for (int t = lane; t < deg; t += 32) {
        int j = g_adj_idx[i * MAXDEG + t];
        float puv = (i < j) ? (g_pu[i] + g_pv[j]) : (g_pu[j] + g_pv[i]);
        float z = hc_gate(puv + pw2 * mhat_bs(i, j) + pb, tau);
        g_ref_idx[i * MAXR + t] = j;
        g_ref_w[i * MAXR + t] = z;
        wsum += z;
    }
    int cnt = deg;
    float thrI = g_thr2[i];
    int cc = g_cand_cnt[i];
    for (int base = 0; base < cc; base += 32) {
        int t = base + lane; bool ok = false; int j = 0; float z = 0.f;
        if (t < cc) {
            j = g_cand_idx[i * MAXC + t]; z = g_cand_z[i * MAXC + t];
            ok = (z >= thrI) || (z >= g_thr2[j]);
        }
        unsigned m = __ballot_sync(0xffffffffu, ok);
        int pos = cnt + __popc(m & ((1u << lane) - 1));
        if (ok) { g_ref_idx[i * MAXR + pos] = j; g_ref_w[i * MAXR + pos] = 0.5f * z; wsum += 0.5f * z; }
        cnt += __popc(m);
    }
    for (int o = 16; o; o >>= 1) wsum += __shfl_down_sync(0xffffffffu, wsum, o);
    if (lane == 0) { g_ref_cnt[i] = cnt; g_dinv_ref[i] = rsqrtf(wsum + 1.f); }
}

__global__ void k_pool(const float* __restrict__ pool_b) {
    __shared__ float red[128];
    int i = blockIdx.x, c = threadIdx.x;
    float di = g_dinv_ref[i];
    int cnt = g_ref_cnt[i];
    float acc = di * g_HW[(size_t)i * CL + c];
    #pragma unroll 4
    for (int t = 0; t < cnt; t++) {
        int j = g_ref_idx[i * MAXR + t];
        acc += g_ref_w[i * MAXR + t] * g_dinv_ref[j] * g_HW[(size_t)j * CL + c];
    }
    float pre = di * acc + pool_b[c];
    red[c] = pre; __syncthreads();
    for (int s = 64; s > 0; s >>= 1) { if (c < s) red[c] = fmaxf(red[c], red[c + s]); __syncthreads(); }
    float mx = red[0]; __syncthreads();
    float e = expf(pre - mx);
    red[c] = e; __syncthreads();
    for (int s = 64; s > 0; s >>= 1) { if (c < s) red[c] += red[c + s]; __syncthreads(); }
    g_S[(size_t)i * CL + c] = e / red[0];
}

__global__ void k_spmmT() {
    int i = blockIdx.x, c = threadIdx.x;
    int cnt = g_ref_cnt[i];
    float acc = 0.f;
    #pragma unroll 4
    for (int t = 0; t < cnt; t++)
        acc += g_ref_w[i * MAXR + t] * g_S[(size_t)g_ref_idx[i * MAXR + t] * CL + c];
    g_T[(size_t)i * CL + c] = acc;
}

__global__ void k_coarse_thr() {
    int gw = (blockIdx.x * blockDim.x + threadIdx.x) >> 5;
    int lane = threadIdx.x & 31;
    if (gw >= 128) return;
    float vv[4];
    #pragma unroll
    for (int s = 0; s < 4; s++) {
        int j = s * 32 + lane;
        vv[s] = (j == gw) ? 0.f : g_Ac[gw * 128 + j];
    }
    float thr = 0.f;
    for (int r = 0; r < 8; r++) {
        float lm = fmaxf(fmaxf(vv[0], vv[1]), fmaxf(vv[2], vv[3]));
        float wm = lm;
        for (int o = 16; o; o >>= 1) wm = fmaxf(wm, __shfl_xor_sync(~0u, wm, o));
        unsigned who = __ballot_sync(~0u, lm == wm);
        if (lane == (__ffs(who) - 1)) {
            #pragma unroll
            for (int s = 0; s < 4; s++) if (vv[s] == wm) { vv[s] = -1e30f; break; }
        }
        thr = wm;
    }
    if (lane == 0) g_cthr[gw] = thr;
}

__global__ void k_coarse_write(float* __restrict__ out) {
    int t = blockIdx.x * blockDim.x + threadIdx.x;
    if (t >= 128 * 128) return;
    int i = t >> 7, j = t & 127;
    if (i == j) { out[t] = 0.f; return; }
    float vij = g_Ac[i * 128 + j];
    float vji = g_Ac[j * 128 + i];
    float a = (vij >= g_cthr[i]) ? vij : 0.f;
    float b = (vji >= g_cthr[j]) ? vji : 0.f;
    out[t] = fmaxf(a, b);
}

// ---------- host ----------
extern "C" void kernel_launch(void* const* d_in, const int* in_sizes, int n_in,
                              void* d_out, int out_size) {
    const float* x       = (const float*)d_in[0];
    const float* A_in    = (const float*)d_in[1];
    const float* A_motif = (const float*)d_in[2];
    const float* coords  = (const float*)d_in[3];
    const float* gat_w   = (const float*)d_in[4];
    const float* gat_as  = (const float*)d_in[5];
    const float* gat_ad  = (const float*)d_in[6];
    const float* gat_b   = (const float*)d_in[7];
    const float* bnAg = (const float*)d_in[8],  *bnAb = (const float*)d_in[9];
    const float* bnAm = (const float*)d_in[10], *bnAv = (const float*)d_in[11];
    const float* gcnMw = (const float*)d_in[12], *gcnMb = (const float*)d_in[13];
    const float* bnMg = (const float*)d_in[14], *bnMb = (const float*)d_in[15];
    const float* bnMm = (const float*)d_in[16], *bnMv = (const float*)d_in[17];
    const float* mu   = (const float*)d_in[18], *tau  = (const float*)d_in[19];
    const float* prune_w = (const float*)d_in[20], *prune_b = (const float*)d_in[21];
    const float* rewire_w = (const float*)d_in[22], *rewire_b = (const float*)d_in[23];
    const float* pool_w = (const float*)d_in[24], *pool_b = (const float*)d_in[25];
    float* out = (float*)d_out;

    float *Wx, *XWM, *h, *HW, *S, *T, *Cpart, *Ac;
    cudaGetSymbolAddress((void**)&Wx, g_Wx);
    cudaGetSymbolAddress((void**)&XWM, g_XWM);
    cudaGetSymbolAddress((void**)&h, g_h);
    cudaGetSymbolAddress((void**)&HW, g_HW);
    cudaGetSymbolAddress((void**)&S, g_S);
    cudaGetSymbolAddress((void**)&T, g_T);
    cudaGetSymbolAddress((void**)&Cpart, g_Cpart);
    cudaGetSymbolAddress((void**)&Ac, g_Ac);

    k_scan<<<1024, 256>>>(A_in, A_motif);   // fused balanced scans + cell zero
    k_gemm<<<dim3(FH / 64, NN / 64), 256>>>(x, gat_w, Wx, NN, FH, 128);
    k_gemm<<<dim3(FH / 64, NN / 64), 256>>>(x, gcnMw, XWM, NN, FH, 128);  // profiled slot
    k_mfilter<<<512, 256>>>();
    k_attn_coef<<<1024, 256>>>(gat_as, gat_ad);
    k_aggregate<<<NN, 256>>>(gat_b, bnAg, bnAb, bnAm, bnAv, gcnMb,
                             bnMg, bnMb, bnMm, bnMv, mu, prune_w, rewire_w);
    k_cells<<<16, 256>>>(coords);
    k_cells_sort<<<16, 256>>>();
    k_candidates<<<512, 256>>>(coords, A_in, rewire_w, rewire_b, tau);
    k_refined<<<512, 256>>>(prune_w, prune_b, tau);
    k_gemm<<<dim3(CL / 64, NN / 64), 256>>>(h, pool_w, HW, NN, CL, FH);
    k_pool<<<NN, 128>>>(pool_b);
    k_spmmT<<<NN, 128>>>();
    k_gemm_tn<<<dim3(FH / 64, 128 / 64, KS), 256>>>(S, h, Cpart, 128, FH, NN);
    k_reduce_part<<<(128 * FH + 255) / 256, 256>>>(out, 128 * FH);
    k_gemm_tn<<<dim3(CL / 64, 128 / 64, KS), 256>>>(S, T, Cpart, 128, CL, NN);
    k_reduce_part<<<(128 * CL + 255) / 256, 256>>>(Ac, 128 * CL);
    k_coarse_thr<<<16, 256>>>();
    k_coarse_write<<<64, 256>>>(out + 128 * FH);
}

// round 13
// speedup vs baseline: 1.0712x; 1.0712x over previous
#include <cuda_runtime.h>
#include <math.h>

#define NN 4096
#define FH 256
#define CL 128
#define MAXDEG 128
#define MAXM 128
#define MAXC 64
#define MAXR (MAXDEG + MAXC)
#define CELLCAP 32
#define NEGINF (-1e9f)
#define KS 16

// ---------- scratch ----------
__device__ int   g_adj_idx[NN * MAXDEG];
__device__ int   g_adj_cnt[NN];
__device__ int   g_mf_idx[NN * MAXM];
__device__ float g_mf_val[NN * MAXM];
__device__ int   g_mf_cnt[NN];
__device__ float g_m_thr[NN];
__device__ int   g_m_idx[NN * MAXM];
__device__ float g_m_val[NN * MAXM];
__device__ int   g_m_cnt[NN];
__device__ float g_dinvM[NN];
__device__ float g_Wx[NN * FH];
__device__ float g_XWM[NN * FH];
__device__ float g_as[NN * 2];
__device__ float g_ad[NN * 2];
__device__ float g_h[NN * FH];
__device__ float g_pu[NN], g_pv[NN], g_ru[NN], g_rv[NN];
__device__ int   g_cell_cnt[4096];
__device__ int   g_cell_nodes[4096 * CELLCAP];
__device__ int   g_cand_idx[NN * MAXC];
__device__ float g_cand_z[NN * MAXC];
__device__ int   g_cand_cnt[NN];
__device__ float g_thr2[NN];
__device__ int   g_ref_idx[NN * MAXR];
__device__ float g_ref_w[NN * MAXR];
__device__ int   g_ref_cnt[NN];
__device__ float g_dinv_ref[NN];
__device__ float g_HW[NN * CL];
__device__ float g_S[NN * CL];
__device__ float g_T[NN * CL];
__device__ float g_Cpart[KS * 128 * 256];
__device__ float g_Ac[128 * 128];
__device__ float g_cthr[128];

// ---------- helpers ----------
__device__ __forceinline__ float hc_gate(float logit, float tau) {
    float t = fmaxf(tau, 0.1f);
    float s = 1.f / (1.f + expf(-logit / t));
    s = s * 1.2f - 0.1f;
    return fminf(fmaxf(s, 0.f), 1.f);
}
__device__ __forceinline__ float mhat_bs(int i, int j) {
    int c = g_m_cnt[i];
    const int* ip = &g_m_idx[i * MAXM];
    int lo = 0, hi = c;
    while (lo < hi) { int mid = (lo + hi) >> 1; if (ip[mid] < j) lo = mid + 1; else hi = mid; }
    return (lo < c && ip[lo] == j) ? g_m_val[i * MAXM + lo] : 0.f;
}

// ---------- phase-1 device bodies ----------
__device__ void adj_row_body(const float* __restrict__ A, int gw, int lane) {
    const float4* row = (const float4*)(A + (size_t)gw * NN);
    unsigned below = (1u << lane) - 1;
    int c = 0;
    #pragma unroll 4
    for (int b = 0; b < NN / 4; b += 32) {
        float4 v = row[b + lane];
        bool p0 = v.x > 0.f, p1 = v.y > 0.f, p2 = v.z > 0.f, p3 = v.w > 0.f;
        unsigned m0 = __ballot_sync(~0u, p0), m1 = __ballot_sync(~0u, p1);
        unsigned m2 = __ballot_sync(~0u, p2), m3 = __ballot_sync(~0u, p3);
        int base = c + __popc(m0 & below) + __popc(m1 & below) + __popc(m2 & below) + __popc(m3 & below);
        int col = (b + lane) * 4, o = 0;
        if (p0 && base + o < MAXDEG) g_adj_idx[gw * MAXDEG + base + o] = col;
        if (p0) o++;
        if (p1 && base + o < MAXDEG) g_adj_idx[gw * MAXDEG + base + o] = col + 1;
        if (p1) o++;
        if (p2 && base + o < MAXDEG) g_adj_idx[gw * MAXDEG + base + o] = col + 2;
        if (p2) o++;
        if (p3 && base + o < MAXDEG) g_adj_idx[gw * MAXDEG + base + o] = col + 3;
        c += __popc(m0) + __popc(m1) + __popc(m2) + __popc(m3);
    }
    if (lane == 0) g_adj_cnt[gw] = min(c, MAXDEG);
}

__device__ void motif_row_body(const float* __restrict__ A, int gw, int lane) {
    const float4* row = (const float4*)(A + (size_t)gw * NN);
    unsigned below = (1u << lane) - 1;
    int c = 0;
    #pragma unroll 4
    for (int b = 0; b < NN / 4; b += 32) {
        float4 v = row[b + lane];
        bool p0 = v.x > 0.f, p1 = v.y > 0.f, p2 = v.z > 0.f, p3 = v.w > 0.f;
        unsigned m0 = __ballot_sync(~0u, p0), m1 = __ballot_sync(~0u, p1);
        unsigned m2 = __ballot_sync(~0u, p2), m3 = __ballot_sync(~0u, p3);
        int base = c + __popc(m0 & below) + __popc(m1 & below) + __popc(m2 & below) + __popc(m3 & below);
        int col = (b + lane) * 4, o = 0;
        if (p0 && base + o < MAXM) { g_mf_idx[gw * MAXM + base + o] = col;     g_mf_val[gw * MAXM + base + o] = v.x; }
        if (p0) o++;
        if (p1 && base + o < MAXM) { g_mf_idx[gw * MAXM + base + o] = col + 1; g_mf_val[gw * MAXM + base + o] = v.y; }
        if (p1) o++;
        if (p2 && base + o < MAXM) { g_mf_idx[gw * MAXM + base + o] = col + 2; g_mf_val[gw * MAXM + base + o] = v.z; }
        if (p2) o++;
        if (p3 && base + o < MAXM) { g_mf_idx[gw * MAXM + base + o] = col + 3; g_mf_val[gw * MAXM + base + o] = v.w; }
        c += __popc(m0) + __popc(m1) + __popc(m2) + __popc(m3);
    }
    c = min(c, MAXM);
    __syncwarp();
    float vv[4];
    #pragma unroll
    for (int s = 0; s < 4; s++) {
        int t = s * 32 + lane;
        vv[s] = (t < c) ? g_mf_val[gw * MAXM + t] : -2.f;
    }
    float thr = 0.f;
    if (c > 8) {
        for (int r = 0; r < 8; r++) {
            float lm = fmaxf(fmaxf(vv[0], vv[1]), fmaxf(vv[2], vv[3]));
            float wm = lm;
            for (int o = 16; o; o >>= 1) wm = fmaxf(wm, __shfl_xor_sync(~0u, wm, o));
            unsigned who = __ballot_sync(~0u, lm == wm);
            if (lane == (__ffs(who) - 1)) {
                #pragma unroll
                for (int s = 0; s < 4; s++) if (vv[s] == wm) { vv[s] = -2.f; break; }
            }
            thr = wm;
        }
    }
    if (lane == 0) { g_mf_cnt[gw] = c; g_m_thr[gw] = thr; }
}

// R9 double-buffered 64x64 GEMM tile body (scalar LDS; bit-identical K order)
__device__ void gemm_tile_body(const float* __restrict__ A, const float* __restrict__ B,
                               float* __restrict__ C, int M, int Nc, int K,
                               int bm, int bn, float (*As)[16][65], float (*Bs)[16][65]) {
    int tid = threadIdx.x, tr = tid >> 4, tc = tid & 15;
    int am[4], ak[4], bk[4], bnn[4];
    float ra[4], rb[4];
    #pragma unroll
    for (int l = 0; l < 4; l++) {
        int e = tid + l * 256;
        am[l] = e >> 4; ak[l] = e & 15;
        bk[l] = e >> 6; bnn[l] = e & 63;
    }
    int nP = K / 16;
    #pragma unroll
    for (int l = 0; l < 4; l++) {
        ra[l] = A[(size_t)(bm + am[l]) * K + ak[l]];
        rb[l] = B[(size_t)bk[l] * Nc + bn + bnn[l]];
    }
    #pragma unroll
    for (int l = 0; l < 4; l++) {
        As[0][ak[l]][am[l]] = ra[l];
        Bs[0][bk[l]][bnn[l]] = rb[l];
    }
    __syncthreads();
    float acc[4][4] = {};
    for (int p = 0; p < nP; p++) {
        int cur = p & 1;
        if (p + 1 < nP) {
            int k0 = (p + 1) * 16;
            #pragma unroll
            for (int l = 0; l < 4; l++) {
                ra[l] = A[(size_t)(bm + am[l]) * K + k0 + ak[l]];
                rb[l] = B[(size_t)(k0 + bk[l]) * Nc + bn + bnn[l]];
            }
        }
        #pragma unroll
        for (int kk = 0; kk < 16; kk++) {
            float a[4], b[4];
            #pragma unroll
            for (int r = 0; r < 4; r++) a[r] = As[cur][kk][tr * 4 + r];
            #pragma unroll
            for (int c = 0; c < 4; c++) b[c] = Bs[cur][kk][tc * 4 + c];
            #pragma unroll
            for (int r = 0; r < 4; r++)
                #pragma unroll
                for (int c = 0; c < 4; c++) acc[r][c] += a[r] * b[c];
        }
        if (p + 1 < nP) {
            #pragma unroll
            for (int l = 0; l < 4; l++) {
                As[cur ^ 1][ak[l]][am[l]] = ra[l];
                Bs[cur ^ 1][bk[l]][bnn[l]] = rb[l];
            }
        }
        __syncthreads();
    }
    #pragma unroll
    for (int r = 0; r < 4; r++)
        #pragma unroll
        for (int c = 0; c < 4; c++)
            C[(size_t)(bm + tr * 4 + r) * Nc + bn + tc * 4 + c] = acc[r][c];
}

// ---------- Phase 1 fused: adj-scan | motif-scan | GEMM Wx | GEMM XWM ----------
__global__ void k_phase1(const float* __restrict__ A_in, const float* __restrict__ A_motif,
                         const float* __restrict__ x, const float* __restrict__ gat_w,
                         const float* __restrict__ gcnMw, float* __restrict__ Wx,
                         float* __restrict__ XWM) {
    __shared__ float As[2][16][65], Bs[2][16][65];
    int b = blockIdx.x;
    int lane = threadIdx.x & 31, wid = threadIdx.x >> 5;
    if (b < 512) {
        if (b < 16) g_cell_cnt[b * 256 + threadIdx.x] = 0;
        adj_row_body(A_in, b * 8 + wid, lane);
    } else if (b < 1024) {
        motif_row_body(A_motif, (b - 512) * 8 + wid, lane);
    } else if (b < 1280) {
        int t = b - 1024;                       // grid was (4, 64): x=t&3, y=t>>2
        gemm_tile_body(x, gat_w, Wx, NN, FH, 128, (t >> 2) * 64, (t & 3) * 64, As, Bs);
    } else {
        int t = b - 1280;
        gemm_tile_body(x, gcnMw, XWM, NN, FH, 128, (t >> 2) * 64, (t & 3) * 64, As, Bs);
    }
}

// ---------- standalone GEMMs (R9) ----------
__global__ void k_gemm(const float* __restrict__ A, const float* __restrict__ B,
                       float* __restrict__ C, int M, int Nc, int K) {
    __shared__ float As[2][16][65], Bs[2][16][65];
    gemm_tile_body(A, B, C, M, Nc, K, blockIdx.y * 64, blockIdx.x * 64, As, Bs);
}

__global__ void k_gemm_tn(const float* __restrict__ A, const float* __restrict__ B,
                          float* __restrict__ Cpart, int M, int Nc, int K) {
    __shared__ float As[2][16][65], Bs[2][16][65];
    int ks = blockIdx.z, kbeg = ks * (K / KS);
    int nP = (K / KS) / 16;
    int bm = blockIdx.y * 64, bn = blockIdx.x * 64;
    int tid = threadIdx.x, tr = tid >> 4, tc = tid & 15;
    int lk[4], ln[4];
    float ra[4], rb[4];
    #pragma unroll
    for (int l = 0; l < 4; l++) {
        int e = tid + l * 256;
        lk[l] = e >> 6; ln[l] = e & 63;
    }
    #pragma unroll
    for (int l = 0; l < 4; l++) {
        ra[l] = A[(size_t)(kbeg + lk[l]) * M + bm + ln[l]];
        rb[l] = B[(size_t)(kbeg + lk[l]) * Nc + bn + ln[l]];
    }
    #pragma unroll
    for (int l = 0; l < 4; l++) {
        As[0][lk[l]][ln[l]] = ra[l];
        Bs[0][lk[l]][ln[l]] = rb[l];
    }
    __syncthreads();
    float acc[4][4] = {};
    for (int p = 0; p < nP; p++) {
        int cur = p & 1;
        if (p + 1 < nP) {
            int k0 = kbeg + (p + 1) * 16;
            #pragma unroll
            for (int l = 0; l < 4; l++) {
                ra[l] = A[(size_t)(k0 + lk[l]) * M + bm + ln[l]];
                rb[l] = B[(size_t)(k0 + lk[l]) * Nc + bn + ln[l]];
            }
        }
        #pragma unroll
        for (int kk = 0; kk < 16; kk++) {
            float a[4], b[4];
            #pragma unroll
            for (int r = 0; r < 4; r++) a[r] = As[cur][kk][tr * 4 + r];
            #pragma unroll
            for (int c = 0; c < 4; c++) b[c] = Bs[cur][kk][tc * 4 + c];
            #pragma unroll
            for (int r = 0; r < 4; r++)
                #pragma unroll
                for (int c = 0; c < 4; c++) acc[r][c] += a[r] * b[c];
        }
        if (p + 1 < nP) {
            #pragma unroll
            for (int l = 0; l < 4; l++) {
                As[cur ^ 1][lk[l]][ln[l]] = ra[l];
                Bs[cur ^ 1][lk[l]][ln[l]] = rb[l];
            }
        }
        __syncthreads();
    }
    float* Cp = Cpart + (size_t)ks * M * Nc;
    #pragma unroll
    for (int r = 0; r < 4; r++)
        #pragma unroll
        for (int c = 0; c < 4; c++)
            Cp[(size_t)(bm + tr * 4 + r) * Nc + bn + tc * 4 + c] = acc[r][c];
}

__global__ void k_reduce_part(float* __restrict__ dst, int MN) {
    int t = blockIdx.x * blockDim.x + threadIdx.x;
    if (t >= MN) return;
    float s = 0.f;
    for (int z = 0; z < KS; z++) s += g_Cpart[(size_t)z * MN + t];
    dst[t] = s;
}

__global__ void k_mfilter() {
    int gw = (blockIdx.x * blockDim.x + threadIdx.x) >> 5;
    int lane = threadIdx.x & 31;
    if (gw >= NN) return;
    int i = gw, cnt = g_mf_cnt[i], out = 0;
    float thrI = g_m_thr[i], wsum = 0.f;
    for (int base = 0; base < cnt; base += 32) {
        int t = base + lane; bool ok = t < cnt; int j = 0; float v = 0.f;
        if (ok) {
            j = g_mf_idx[i * MAXM + t]; v = g_mf_val[i * MAXM + t];
            ok = (v >= thrI) || (v >= g_m_thr[j]);
        }
        unsigned m = __ballot_sync(0xffffffffu, ok);
        int pos = out + __popc(m & ((1u << lane) - 1));
        if (ok) { g_m_idx[i * MAXM + pos] = j; g_m_val[i * MAXM + pos] = v; wsum += v; }
        out += __popc(m);
    }
    for (int o = 16; o; o >>= 1) wsum += __shfl_down_sync(0xffffffffu, wsum, o);
    if (lane == 0) { g_m_cnt[i] = out; g_dinvM[i] = (wsum > 0.f) ? rsqrtf(wsum) : 0.f; }
}

__global__ void k_attn_coef(const float* __restrict__ asw, const float* __restrict__ adw) {
    int gw = (blockIdx.x * blockDim.x + threadIdx.x) >> 5;
    int lane = threadIdx.x & 31;
    if (gw >= NN * 2) return;
    int node = gw >> 1, hh = gw & 1;
    const float* row = g_Wx + (size_t)node * FH + hh * 128;
    float s = 0.f, d = 0.f;
    for (int k = lane; k < 128; k += 32) {
        float w = row[k];
        s += w * asw[hh * 128 + k];
        d += w * adw[hh * 128 + k];
    }
    for (int o = 16; o; o >>= 1) {
        s += __shfl_down_sync(0xffffffffu, s, o);
        d += __shfl_down_sync(0xffffffffu, d, o);
    }
    if (lane == 0) { g_as[node * 2 + hh] = s; g_ad[node * 2 + hh] = d; }
}

__global__ void k_aggregate(
    const float* __restrict__ gat_b,
    const float* __restrict__ bnAg, const float* __restrict__ bnAb,
    const float* __restrict__ bnAm, const float* __restrict__ bnAv,
    const float* __restrict__ gcnMb,
    const float* __restrict__ bnMg, const float* __restrict__ bnMb,
    const float* __restrict__ bnMm, const float* __restrict__ bnMv,
    const float* __restrict__ mu_, const float* __restrict__ prune_w,
    const float* __restrict__ rewire_w)
{
    __shared__ int sj[MAXDEG + 1];
    __shared__ float se0[MAXDEG + 1], se1[MAXDEG + 1];
    __shared__ int smj[MAXM];
    __shared__ float smc[MAXM];
    __shared__ float rA[256], rB[256];
    int i = blockIdx.x, tid = threadIdx.x;
    int deg = g_adj_cnt[i], tot = deg + 1;
    float ad0 = g_ad[2 * i], ad1 = g_ad[2 * i + 1];
    for (int t = tid; t < tot; t += 256) {
        int j = (t < deg) ? g_adj_idx[i * MAXDEG + t] : i;
        sj[t] = j;
        float e0 = ad0 + g_as[2 * j], e1 = ad1 + g_as[2 * j + 1];
        se0[t] = (e0 > 0.f) ? e0 : 0.2f * e0;
        se1[t] = (e1 > 0.f) ? e1 : 0.2f * e1;
    }
    int mc = g_m_cnt[i];
    for (int t = tid; t < mc; t += 256) {
        int j = g_m_idx[i * MAXM + t];
        smj[t] = j;
        smc[t] = g_m_val[i * MAXM + t] * g_dinvM[j];
    }
    __syncthreads();
    float lm0 = -3.4e38f, lm1 = -3.4e38f;
    for (int t = tid; t < tot; t += 256) { lm0 = fmaxf(lm0, se0[t]); lm1 = fmaxf(lm1, se1[t]); }
    rA[tid] = lm0; rB[tid] = lm1; __syncthreads();
    for (int s = 128; s > 0; s >>= 1) {
        if (tid < s) { rA[tid] = fmaxf(rA[tid], rA[tid + s]); rB[tid] = fmaxf(rB[tid], rB[tid + s]); }
        __syncthreads();
    }
    float M0 = rA[0], M1 = rB[0]; __syncthreads();
    float ls0 = 0.f, ls1 = 0.f;
    for (int t = tid; t < tot; t += 256) {
        float e0 = expf(se0[t] - M0); se0[t] = e0; ls0 += e0;
        float e1 = expf(se1[t] - M1); se1[t] = e1; ls1 += e1;
    }
    rA[tid] = ls0; rB[tid] = ls1; __syncthreads();
    for (int s = 128; s > 0; s >>= 1) {
        if (tid < s) { rA[tid] += rA[tid + s]; rB[tid] += rB[tid + s]; }
        __syncthreads();
    }
    float D0 = rA[0], D1 = rB[0]; __syncthreads();

    int d = tid, head = d >> 7;
    float Dh = head ? D1 : D0;
    const float* se = head ? se1 : se0;
    float accA = 0.f;
    #pragma unroll 4
    for (int k = 0; k < tot; k++) accA += se[k] * g_Wx[(size_t)sj[k] * FH + d];
    float hA = accA / Dh + gat_b[d];
    hA = (hA - bnAm[d]) * bnAg[d] * rsqrtf(bnAv[d] + 1e-5f) + bnAb[d];
    hA = (hA > 0.f) ? hA : expm1f(hA);

    float accM = 0.f;
    #pragma unroll 4
    for (int k = 0; k < mc; k++) accM += smc[k] * g_XWM[(size_t)smj[k] * FH + d];
    float hM = g_dinvM[i] * accM + gcnMb[d];
    hM = (hM - bnMm[d]) * bnMg[d] * rsqrtf(bnMv[d] + 1e-5f) + bnMb[d];
    hM = (hM > 0.f) ? hM : expm1f(hM);

    float mu = mu_[0];
    float sp = (mu > 20.f) ? mu : log1pf(expf(mu));
    float hv = hA + sp * hM;
    g_h[(size_t)i * FH + d] = hv;

    rA[tid] = hv * prune_w[d]; rB[tid] = hv * prune_w[256 + d]; __syncthreads();
    for (int s = 128; s > 0; s >>= 1) {
        if (tid < s) { rA[tid] += rA[tid + s]; rB[tid] += rB[tid + s]; }
        __syncthreads();
    }
    float r0 = rA[0], r1 = rB[0]; __syncthreads();
    rA[tid] = hv * rewire_w[d]; rB[tid] = hv * rewire_w[256 + d]; __syncthreads();
    for (int s = 128; s > 0; s >>= 1) {
        if (tid < s) { rA[tid] += rA[tid + s]; rB[tid] += rB[tid + s]; }
        __syncthreads();
    }
    if (tid == 0) { g_pu[i] = r0; g_pv[i] = r1; g_ru[i] = rA[0]; g_rv[i] = rB[0]; }
}

__global__ void k_cells(const float* __restrict__ coords) {
    int i = blockIdx.x * blockDim.x + threadIdx.x;
    if (i >= NN) return;
    int cx = (int)coords[2 * i], cy = (int)coords[2 * i + 1];
    int p = atomicAdd(&g_cell_cnt[cx * 64 + cy], 1);
    if (p < CELLCAP) g_cell_nodes[(cx * 64 + cy) * CELLCAP + p] = i;
}

__global__ void k_cells_sort() {
    int c = blockIdx.x * blockDim.x + threadIdx.x;
    if (c >= 4096) return;
    int n = min(g_cell_cnt[c], CELLCAP);
    int* a = &g_cell_nodes[c * CELLCAP];
    for (int x = 1; x < n; x++) {
        int v = a[x], y = x - 1;
        while (y >= 0 && a[y] > v) { a[y + 1] = a[y]; y--; }
        a[y + 1] = v;
    }
}

__global__ void k_candidates(const float* __restrict__ coords, const float* __restrict__ A_in,
                             const float* __restrict__ rw, const float* __restrict__ rb_,
                             const float* __restrict__ tau_) {
    int gw = (blockIdx.x * blockDim.x + threadIdx.x) >> 5;
    int lane = threadIdx.x & 31;
    if (gw >= NN) return;
    int i = gw;
    float tau = tau_[0], rw2 = rw[512], rb = rb_[0];
    int cx = (int)coords[2 * i], cy = (int)coords[2 * i + 1];
    const int ox[12] = {-2,-1,-1,-1, 0, 0, 0, 0, 1, 1, 1, 2};
    const int oy[12] = { 0,-1, 0, 1,-2,-1, 1, 2,-1, 0, 1, 0};
    float rui = g_ru[i], rvi = g_rv[i];
    int cnt = 0;
    float m1 = NEGINF, m2 = NEGINF;
    for (int o = 0; o < 12; o++) {
        int nx = cx + ox[o], ny = cy + oy[o];
        if (nx < 0 || nx >= 64 || ny < 0 || ny >= 64) continue;
        int cell = nx * 64 + ny;
        int cc = min(g_cell_cnt[cell], CELLCAP);
        for (int base = 0; base < cc; base += 32) {
            int t = base + lane;
            bool ok = t < cc;
            int j = 0; float z = 0.f;
            if (ok) {
                j = g_cell_nodes[cell * CELLCAP + t];
                ok = A_in[(size_t)i * NN + j] < 1e-6f;
            }
            if (ok) {
                float ruv = (i < j) ? (rui + g_rv[j]) : (g_ru[j] + rvi);
                z = hc_gate(ruv + rw2 * mhat_bs(i, j) + rb, tau);
                if (z > m1) { m2 = m1; m1 = z; } else if (z > m2) { m2 = z; }
            }
            unsigned m = __ballot_sync(~0u, ok);
            int pos = cnt + __popc(m & ((1u << lane) - 1));
            if (ok && pos < MAXC) { g_cand_idx[i * MAXC + pos] = j; g_cand_z[i * MAXC + pos] = z; }
            cnt += __popc(m);
        }
    }
    for (int o = 16; o; o >>= 1) {
        float om1 = __shfl_xor_sync(~0u, m1, o);
        float om2 = __shfl_xor_sync(~0u, m2, o);
        float hi = fmaxf(m1, om1), lo = fminf(m1, om1);
        m2 = fmaxf(lo, fmaxf(m2, om2));
        m1 = hi;
    }
    if (lane == 0) { g_cand_cnt[i] = min(cnt, MAXC); g_thr2[i] = m2; }
}

__global__ void k_refined(const float* __restrict__ prune_w, const float* __restrict__ prune_b,
                          const float* __restrict__ tau_) {
    int gw = (blockIdx.x * blockDim.x + threadIdx.x) >> 5;
    int lane = threadIdx.x & 31;
    if (gw >= NN) return;
    int i = gw;
    float tau = tau_[0], pw2 = prune_w[512], pb = prune_b[0];
    int deg = g_adj_cnt[i];
    float wsum = 0.f;
    for (int t = lane; t < deg; t += 32) {
        int j = g_adj_idx[i * MAXDEG + t];
        float puv = (i < j) ? (g_pu[i] + g_pv[j]) : (g_pu[j] + g_pv[i]);
        float z = hc_gate(puv + pw2 * mhat_bs(i, j) + pb, tau);
        g_ref_idx[i * MAXR + t] = j;
        g_ref_w[i * MAXR + t] = z;
        wsum += z;
    }
    int cnt = deg;
    float thrI = g_thr2[i];
    int cc = g_cand_cnt[i];
    for (int base = 0; base < cc; base += 32) {
        int t = base + lane; bool ok = false; int j = 0; float z = 0.f;
        if (t < cc) {
            j = g_cand_idx[i * MAXC + t]; z = g_cand_z[i * MAXC + t];
            ok = (z >= thrI) || (z >= g_thr2[j]);
        }
        unsigned m = __ballot_sync(0xffffffffu, ok);
        int pos = cnt + __popc(m & ((1u << lane) - 1));
        if (ok) { g_ref_idx[i * MAXR + pos] = j; g_ref_w[i * MAXR + pos] = 0.5f * z; wsum += 0.5f * z; }
        cnt += __popc(m);
    }
    for (int o = 16; o; o >>= 1) wsum += __shfl_down_sync(0xffffffffu, wsum, o);
    if (lane == 0) { g_ref_cnt[i] = cnt; g_dinv_ref[i] = rsqrtf(wsum + 1.f); }
}

__global__ void k_pool(const float* __restrict__ pool_b) {
    __shared__ float red[128];
    int i = blockIdx.x, c = threadIdx.x;
    float di = g_dinv_ref[i];
    int cnt = g_ref_cnt[i];
    float acc = di * g_HW[(size_t)i * CL + c];
    #pragma unroll 4
    for (int t = 0; t < cnt; t++) {
        int j = g_ref_idx[i * MAXR + t];
        acc += g_ref_w[i * MAXR + t] * g_dinv_ref[j] * g_HW[(size_t)j * CL + c];
    }
    float pre = di * acc + pool_b[c];
    red[c] = pre; __syncthreads();
    for (int s = 64; s > 0; s >>= 1) { if (c < s) red[c] = fmaxf(red[c], red[c + s]); __syncthreads(); }
    float mx = red[0]; __syncthreads();
    float e = expf(pre - mx);
    red[c] = e; __syncthreads();
    for (int s = 64; s > 0; s >>= 1) { if (c < s) red[c] += red[c + s]; __syncthreads(); }
    g_S[(size_t)i * CL + c] = e / red[0];
}

__global__ void k_spmmT() {
    int i = blockIdx.x, c = threadIdx.x;
    int cnt = g_ref_cnt[i];
    float acc = 0.f;
    #pragma unroll 4
    for (int t = 0; t < cnt; t++)
        acc += g_ref_w[i * MAXR + t] * g_S[(size_t)g_ref_idx[i * MAXR + t] * CL + c];
    g_T[(size_t)i * CL + c] = acc;
}

__global__ void k_coarse_thr() {
    int gw = (blockIdx.x * blockDim.x + threadIdx.x) >> 5;
    int lane = threadIdx.x & 31;
    if (gw >= 128) return;
    float vv[4];
    #pragma unroll
    for (int s = 0; s < 4; s++) {
        int j = s * 32 + lane;
        vv[s] = (j == gw) ? 0.f : g_Ac[gw * 128 + j];
    }
    float thr = 0.f;
    for (int r = 0; r < 8; r++) {
        float lm = fmaxf(fmaxf(vv[0], vv[1]), fmaxf(vv[2], vv[3]));
        float wm = lm;
        for (int o = 16; o; o >>= 1) wm = fmaxf(wm, __shfl_xor_sync(~0u, wm, o));
        unsigned who = __ballot_sync(~0u, lm == wm);
        if (lane == (__ffs(who) - 1)) {
            #pragma unroll
            for (int s = 0; s < 4; s++) if (vv[s] == wm) { vv[s] = -1e30f; break; }
        }
        thr = wm;
    }
    if (lane == 0) g_cthr[gw] = thr;
}

__global__ void k_coarse_write(float* __restrict__ out) {
    int t = blockIdx.x * blockDim.x + threadIdx.x;
    if (t >= 128 * 128) return;
    int i = t >> 7, j = t & 127;
    if (i == j) { out[t] = 0.f; return; }
    float vij = g_Ac[i * 128 + j];
    float vji = g_Ac[j * 128 + i];
    float a = (vij >= g_cthr[i]) ? vij : 0.f;
    float b = (vji >= g_cthr[j]) ? vji : 0.f;
    out[t] = fmaxf(a, b);
}

// ---------- host ----------
extern "C" void kernel_launch(void* const* d_in, const int* in_sizes, int n_in,
                              void* d_out, int out_size) {
    const float* x       = (const float*)d_in[0];
    const float* A_in    = (const float*)d_in[1];
    const float* A_motif = (const float*)d_in[2];
    const float* coords  = (const float*)d_in[3];
    const float* gat_w   = (const float*)d_in[4];
    const float* gat_as  = (const float*)d_in[5];
    const float* gat_ad  = (const float*)d_in[6];
    const float* gat_b   = (const float*)d_in[7];
    const float* bnAg = (const float*)d_in[8],  *bnAb = (const float*)d_in[9];
    const float* bnAm = (const float*)d_in[10], *bnAv = (const float*)d_in[11];
    const float* gcnMw = (const float*)d_in[12], *gcnMb = (const float*)d_in[13];
    const float* bnMg = (const float*)d_in[14], *bnMb = (const float*)d_in[15];
    const float* bnMm = (const float*)d_in[16], *bnMv = (const float*)d_in[17];
    const float* mu   = (const float*)d_in[18], *tau  = (const float*)d_in[19];
    const float* prune_w = (const float*)d_in[20], *prune_b = (const float*)d_in[21];
    const float* rewire_w = (const float*)d_in[22], *rewire_b = (const float*)d_in[23];
    const float* pool_w = (const float*)d_in[24], *pool_b = (const float*)d_in[25];
    float* out = (float*)d_out;

    float *Wx, *XWM, *h, *HW, *S, *T, *Cpart, *Ac;
    cudaGetSymbolAddress((void**)&Wx, g_Wx);
    cudaGetSymbolAddress((void**)&XWM, g_XWM);
    cudaGetSymbolAddress((void**)&h, g_h);
    cudaGetSymbolAddress((void**)&HW, g_HW);
    cudaGetSymbolAddress((void**)&S, g_S);
    cudaGetSymbolAddress((void**)&T, g_T);
    cudaGetSymbolAddress((void**)&Cpart, g_Cpart);
    cudaGetSymbolAddress((void**)&Ac, g_Ac);

    // Phase 1 fused: adj | motif | GEMM Wx | GEMM XWM (complementary mem/compute)
    k_phase1<<<1536, 256>>>(A_in, A_motif, x, gat_w, gcnMw, Wx, XWM);
    k_mfilter<<<512, 256>>>();
    k_attn_coef<<<1024, 256>>>(gat_as, gat_ad);
    k_aggregate<<<NN, 256>>>(gat_b, bnAg, bnAb, bnAm, bnAv, gcnMb,
                             bnMg, bnMb, bnMm, bnMv, mu, prune_w, rewire_w);
    k_cells<<<16, 256>>>(coords);
    k_cells_sort<<<16, 256>>>();
    k_candidates<<<512, 256>>>(coords, A_in, rewire_w, rewire_b, tau);
    k_refined<<<512, 256>>>(prune_w, prune_b, tau);
    k_gemm<<<dim3(CL / 64, NN / 64), 256>>>(h, pool_w, HW, NN, CL, FH);
    k_pool<<<NN, 128>>>(pool_b);
    k_spmmT<<<NN, 128>>>();
    k_gemm_tn<<<dim3(FH / 64, 128 / 64, KS), 256>>>(S, h, Cpart, 128, FH, NN);
    k_reduce_part<<<(128 * FH + 255) / 256, 256>>>(out, 128 * FH);
    k_gemm_tn<<<dim3(CL / 64, 128 / 64, KS), 256>>>(S, T, Cpart, 128, CL, NN);
    k_reduce_part<<<(128 * CL + 255) / 256, 256>>>(Ac, 128 * CL);
    k_coarse_thr<<<16, 256>>>();
    k_coarse_write<<<64, 256>>>(out + 128 * FH);
}

// round 14
// speedup vs baseline: 1.1576x; 1.0807x over previous
#include <cuda_runtime.h>
#include <math.h>

#define NN 4096
#define FH 256
#define CL 128
#define MAXDEG 128
#define MAXM 128
#define MAXC 64
#define MAXR (MAXDEG + MAXC)
#define CELLCAP 32
#define NEGINF (-1e9f)
#define KS 16

// ---------- scratch ----------
__device__ int   g_adj_idx[NN * MAXDEG];
__device__ int   g_adj_cnt[NN];
__device__ int   g_mf_idx[NN * MAXM];
__device__ float g_mf_val[NN * MAXM];
__device__ int   g_mf_cnt[NN];
__device__ float g_m_thr[NN];
__device__ int   g_m_idx[NN * MAXM];
__device__ float g_m_val[NN * MAXM];
__device__ int   g_m_cnt[NN];
__device__ float g_dinvM[NN];
__device__ float g_Wx[NN * FH];
__device__ float g_XWM[NN * FH];
__device__ float g_as[NN * 2];
__device__ float g_ad[NN * 2];
__device__ float g_h[NN * FH];
__device__ float g_pu[NN], g_pv[NN], g_ru[NN], g_rv[NN];
__device__ int   g_cell_cnt[4096];
__device__ int   g_cell_nodes[4096 * CELLCAP];
__device__ int   g_cand_idx[NN * MAXC];
__device__ float g_cand_z[NN * MAXC];
__device__ int   g_cand_cnt[NN];
__device__ float g_thr2[NN];
__device__ int   g_ref_idx[NN * MAXR];
__device__ float g_ref_w[NN * MAXR];
__device__ int   g_ref_cnt[NN];
__device__ float g_dinv_ref[NN];
__device__ float g_HW[NN * CL];
__device__ float g_S[NN * CL];
__device__ float g_T[NN * CL];
__device__ float g_Cpart[KS * 128 * 256];
__device__ float g_Ac[128 * 128];
__device__ float g_cthr[128];

// ---------- helpers ----------
__device__ __forceinline__ float hc_gate(float logit, float tau) {
    float t = fmaxf(tau, 0.1f);
    float s = 1.f / (1.f + expf(-logit / t));
    s = s * 1.2f - 0.1f;
    return fminf(fmaxf(s, 0.f), 1.f);
}
__device__ __forceinline__ float mhat_bs(int i, int j) {
    int c = g_m_cnt[i];
    const int* ip = &g_m_idx[i * MAXM];
    int lo = 0, hi = c;
    while (lo < hi) { int mid = (lo + hi) >> 1; if (ip[mid] < j) lo = mid + 1; else hi = mid; }
    return (lo < c && ip[lo] == j) ? g_m_val[i * MAXM + lo] : 0.f;
}

// ---------- phase-1 device bodies ----------
__device__ void adj_row_body(const float* __restrict__ A, int gw, int lane) {
    const float4* row = (const float4*)(A + (size_t)gw * NN);
    unsigned below = (1u << lane) - 1;
    int c = 0;
    #pragma unroll 4
    for (int b = 0; b < NN / 4; b += 32) {
        float4 v = row[b + lane];
        bool p0 = v.x > 0.f, p1 = v.y > 0.f, p2 = v.z > 0.f, p3 = v.w > 0.f;
        unsigned m0 = __ballot_sync(~0u, p0), m1 = __ballot_sync(~0u, p1);
        unsigned m2 = __ballot_sync(~0u, p2), m3 = __ballot_sync(~0u, p3);
        int base = c + __popc(m0 & below) + __popc(m1 & below) + __popc(m2 & below) + __popc(m3 & below);
        int col = (b + lane) * 4, o = 0;
        if (p0 && base + o < MAXDEG) g_adj_idx[gw * MAXDEG + base + o] = col;
        if (p0) o++;
        if (p1 && base + o < MAXDEG) g_adj_idx[gw * MAXDEG + base + o] = col + 1;
        if (p1) o++;
        if (p2 && base + o < MAXDEG) g_adj_idx[gw * MAXDEG + base + o] = col + 2;
        if (p2) o++;
        if (p3 && base + o < MAXDEG) g_adj_idx[gw * MAXDEG + base + o] = col + 3;
        c += __popc(m0) + __popc(m1) + __popc(m2) + __popc(m3);
    }
    if (lane == 0) g_adj_cnt[gw] = min(c, MAXDEG);
}

__device__ void motif_row_body(const float* __restrict__ A, int gw, int lane) {
    const float4* row = (const float4*)(A + (size_t)gw * NN);
    unsigned below = (1u << lane) - 1;
    int c = 0;
    #pragma unroll 4
    for (int b = 0; b < NN / 4; b += 32) {
        float4 v = row[b + lane];
        bool p0 = v.x > 0.f, p1 = v.y > 0.f, p2 = v.z > 0.f, p3 = v.w > 0.f;
        unsigned m0 = __ballot_sync(~0u, p0), m1 = __ballot_sync(~0u, p1);
        unsigned m2 = __ballot_sync(~0u, p2), m3 = __ballot_sync(~0u, p3);
        int base = c + __popc(m0 & below) + __popc(m1 & below) + __popc(m2 & below) + __popc(m3 & below);
        int col = (b + lane) * 4, o = 0;
        if (p0 && base + o < MAXM) { g_mf_idx[gw * MAXM + base + o] = col;     g_mf_val[gw * MAXM + base + o] = v.x; }
        if (p0) o++;
        if (p1 && base + o < MAXM) { g_mf_idx[gw * MAXM + base + o] = col + 1; g_mf_val[gw * MAXM + base + o] = v.y; }
        if (p1) o++;
        if (p2 && base + o < MAXM) { g_mf_idx[gw * MAXM + base + o] = col + 2; g_mf_val[gw * MAXM + base + o] = v.z; }
        if (p2) o++;
        if (p3 && base + o < MAXM) { g_mf_idx[gw * MAXM + base + o] = col + 3; g_mf_val[gw * MAXM + base + o] = v.w; }
        c += __popc(m0) + __popc(m1) + __popc(m2) + __popc(m3);
    }
    c = min(c, MAXM);
    __syncwarp();
    float vv[4];
    #pragma unroll
    for (int s = 0; s < 4; s++) {
        int t = s * 32 + lane;
        vv[s] = (t < c) ? g_mf_val[gw * MAXM + t] : -2.f;
    }
    float thr = 0.f;
    if (c > 8) {
        for (int r = 0; r < 8; r++) {
            float lm = fmaxf(fmaxf(vv[0], vv[1]), fmaxf(vv[2], vv[3]));
            float wm = lm;
            for (int o = 16; o; o >>= 1) wm = fmaxf(wm, __shfl_xor_sync(~0u, wm, o));
            unsigned who = __ballot_sync(~0u, lm == wm);
            if (lane == (__ffs(who) - 1)) {
                #pragma unroll
                for (int s = 0; s < 4; s++) if (vv[s] == wm) { vv[s] = -2.f; break; }
            }
            thr = wm;
        }
    }
    if (lane == 0) { g_mf_cnt[gw] = c; g_m_thr[gw] = thr; }
}

// R9 double-buffered 64x64 GEMM tile body
__device__ void gemm_tile_body(const float* __restrict__ A, const float* __restrict__ B,
                               float* __restrict__ C, int M, int Nc, int K,
                               int bm, int bn, float (*As)[16][65], float (*Bs)[16][65]) {
    int tid = threadIdx.x, tr = tid >> 4, tc = tid & 15;
    int am[4], ak[4], bk[4], bnn[4];
    float ra[4], rb[4];
    #pragma unroll
    for (int l = 0; l < 4; l++) {
        int e = tid + l * 256;
        am[l] = e >> 4; ak[l] = e & 15;
        bk[l] = e >> 6; bnn[l] = e & 63;
    }
    int nP = K / 16;
    #pragma unroll
    for (int l = 0; l < 4; l++) {
        ra[l] = A[(size_t)(bm + am[l]) * K + ak[l]];
        rb[l] = B[(size_t)bk[l] * Nc + bn + bnn[l]];
    }
    #pragma unroll
    for (int l = 0; l < 4; l++) {
        As[0][ak[l]][am[l]] = ra[l];
        Bs[0][bk[l]][bnn[l]] = rb[l];
    }
    __syncthreads();
    float acc[4][4] = {};
    for (int p = 0; p < nP; p++) {
        int cur = p & 1;
        if (p + 1 < nP) {
            int k0 = (p + 1) * 16;
            #pragma unroll
            for (int l = 0; l < 4; l++) {
                ra[l] = A[(size_t)(bm + am[l]) * K + k0 + ak[l]];
                rb[l] = B[(size_t)(k0 + bk[l]) * Nc + bn + bnn[l]];
            }
        }
        #pragma unroll
        for (int kk = 0; kk < 16; kk++) {
            float a[4], b[4];
            #pragma unroll
            for (int r = 0; r < 4; r++) a[r] = As[cur][kk][tr * 4 + r];
            #pragma unroll
            for (int c = 0; c < 4; c++) b[c] = Bs[cur][kk][tc * 4 + c];
            #pragma unroll
            for (int r = 0; r < 4; r++)
                #pragma unroll
                for (int c = 0; c < 4; c++) acc[r][c] += a[r] * b[c];
        }
        if (p + 1 < nP) {
            #pragma unroll
            for (int l = 0; l < 4; l++) {
                As[cur ^ 1][ak[l]][am[l]] = ra[l];
                Bs[cur ^ 1][bk[l]][bnn[l]] = rb[l];
            }
        }
        __syncthreads();
    }
    #pragma unroll
    for (int r = 0; r < 4; r++)
        #pragma unroll
        for (int c = 0; c < 4; c++)
            C[(size_t)(bm + tr * 4 + r) * Nc + bn + tc * 4 + c] = acc[r][c];
}

// ---------- Phase 1 fused ----------
__global__ void k_phase1(const float* __restrict__ A_in, const float* __restrict__ A_motif,
                         const float* __restrict__ x, const float* __restrict__ gat_w,
                         const float* __restrict__ gcnMw, float* __restrict__ Wx,
                         float* __restrict__ XWM) {
    __shared__ float As[2][16][65], Bs[2][16][65];
    int b = blockIdx.x;
    int lane = threadIdx.x & 31, wid = threadIdx.x >> 5;
    if (b < 512) {
        if (b < 16) g_cell_cnt[b * 256 + threadIdx.x] = 0;
        adj_row_body(A_in, b * 8 + wid, lane);
    } else if (b < 1024) {
        motif_row_body(A_motif, (b - 512) * 8 + wid, lane);
    } else if (b < 1280) {
        int t = b - 1024;
        gemm_tile_body(x, gat_w, Wx, NN, FH, 128, (t >> 2) * 64, (t & 3) * 64, As, Bs);
    } else {
        int t = b - 1280;
        gemm_tile_body(x, gcnMw, XWM, NN, FH, 128, (t >> 2) * 64, (t & 3) * 64, As, Bs);
    }
}

__global__ void k_gemm(const float* __restrict__ A, const float* __restrict__ B,
                       float* __restrict__ C, int M, int Nc, int K) {
    __shared__ float As[2][16][65], Bs[2][16][65];
    gemm_tile_body(A, B, C, M, Nc, K, blockIdx.y * 64, blockIdx.x * 64, As, Bs);
}

__global__ void k_gemm_tn(const float* __restrict__ A, const float* __restrict__ B,
                          float* __restrict__ Cpart, int M, int Nc, int K) {
    __shared__ float As[2][16][65], Bs[2][16][65];
    int ks = blockIdx.z, kbeg = ks * (K / KS);
    int nP = (K / KS) / 16;
    int bm = blockIdx.y * 64, bn = blockIdx.x * 64;
    int tid = threadIdx.x, tr = tid >> 4, tc = tid & 15;
    int lk[4], ln[4];
    float ra[4], rb[4];
    #pragma unroll
    for (int l = 0; l < 4; l++) {
        int e = tid + l * 256;
        lk[l] = e >> 6; ln[l] = e & 63;
    }
    #pragma unroll
    for (int l = 0; l < 4; l++) {
        ra[l] = A[(size_t)(kbeg + lk[l]) * M + bm + ln[l]];
        rb[l] = B[(size_t)(kbeg + lk[l]) * Nc + bn + ln[l]];
    }
    #pragma unroll
    for (int l = 0; l < 4; l++) {
        As[0][lk[l]][ln[l]] = ra[l];
        Bs[0][lk[l]][ln[l]] = rb[l];
    }
    __syncthreads();
    float acc[4][4] = {};
    for (int p = 0; p < nP; p++) {
        int cur = p & 1;
        if (p + 1 < nP) {
            int k0 = kbeg + (p + 1) * 16;
            #pragma unroll
            for (int l = 0; l < 4; l++) {
                ra[l] = A[(size_t)(k0 + lk[l]) * M + bm + ln[l]];
                rb[l] = B[(size_t)(k0 + lk[l]) * Nc + bn + ln[l]];
            }
        }
        #pragma unroll
        for (int kk = 0; kk < 16; kk++) {
            float a[4], b[4];
            #pragma unroll
            for (int r = 0; r < 4; r++) a[r] = As[cur][kk][tr * 4 + r];
            #pragma unroll
            for (int c = 0; c < 4; c++) b[c] = Bs[cur][kk][tc * 4 + c];
            #pragma unroll
            for (int r = 0; r < 4; r++)
                #pragma unroll
                for (int c = 0; c < 4; c++) acc[r][c] += a[r] * b[c];
        }
        if (p + 1 < nP) {
            #pragma unroll
            for (int l = 0; l < 4; l++) {
                As[cur ^ 1][lk[l]][ln[l]] = ra[l];
                Bs[cur ^ 1][lk[l]][ln[l]] = rb[l];
            }
        }
        __syncthreads();
    }
    float* Cp = Cpart + (size_t)ks * M * Nc;
    #pragma unroll
    for (int r = 0; r < 4; r++)
        #pragma unroll
        for (int c = 0; c < 4; c++)
            Cp[(size_t)(bm + tr * 4 + r) * Nc + bn + tc * 4 + c] = acc[r][c];
}

__global__ void k_reduce_part(float* __restrict__ dst, int MN) {
    int t = blockIdx.x * blockDim.x + threadIdx.x;
    if (t >= MN) return;
    float s = 0.f;
    for (int z = 0; z < KS; z++) s += g_Cpart[(size_t)z * MN + t];
    dst[t] = s;
}

__global__ void k_mfilter() {
    int gw = (blockIdx.x * blockDim.x + threadIdx.x) >> 5;
    int lane = threadIdx.x & 31;
    if (gw >= NN) return;
    int i = gw, cnt = g_mf_cnt[i], out = 0;
    float thrI = g_m_thr[i], wsum = 0.f;
    for (int base = 0; base < cnt; base += 32) {
        int t = base + lane; bool ok = t < cnt; int j = 0; float v = 0.f;
        if (ok) {
            j = g_mf_idx[i * MAXM + t]; v = g_mf_val[i * MAXM + t];
            ok = (v >= thrI) || (v >= g_m_thr[j]);
        }
        unsigned m = __ballot_sync(0xffffffffu, ok);
        int pos = out + __popc(m & ((1u << lane) - 1));
        if (ok) { g_m_idx[i * MAXM + pos] = j; g_m_val[i * MAXM + pos] = v; wsum += v; }
        out += __popc(m);
    }
    for (int o = 16; o; o >>= 1) wsum += __shfl_down_sync(0xffffffffu, wsum, o);
    if (lane == 0) { g_m_cnt[i] = out; g_dinvM[i] = (wsum > 0.f) ? rsqrtf(wsum) : 0.f; }
}

__global__ void k_attn_coef(const float* __restrict__ asw, const float* __restrict__ adw) {
    int gw = (blockIdx.x * blockDim.x + threadIdx.x) >> 5;
    int lane = threadIdx.x & 31;
    if (gw >= NN * 2) return;
    int node = gw >> 1, hh = gw & 1;
    const float* row = g_Wx + (size_t)node * FH + hh * 128;
    float s = 0.f, d = 0.f;
    for (int k = lane; k < 128; k += 32) {
        float w = row[k];
        s += w * asw[hh * 128 + k];
        d += w * adw[hh * 128 + k];
    }
    for (int o = 16; o; o >>= 1) {
        s += __shfl_down_sync(0xffffffffu, s, o);
        d += __shfl_down_sync(0xffffffffu, d, o);
    }
    if (lane == 0) { g_as[node * 2 + hh] = s; g_ad[node * 2 + hh] = d; }
}

// ---------- aggregate: 128 threads, 2 dims/thread, packed (weight,idx) LDS.64 ----------
__global__ void k_aggregate(
    const float* __restrict__ gat_b,
    const float* __restrict__ bnAg, const float* __restrict__ bnAb,
    const float* __restrict__ bnAm, const float* __restrict__ bnAv,
    const float* __restrict__ gcnMb,
    const float* __restrict__ bnMg, const float* __restrict__ bnMb,
    const float* __restrict__ bnMm, const float* __restrict__ bnMv,
    const float* __restrict__ mu_, const float* __restrict__ prune_w,
    const float* __restrict__ rewire_w)
{
    __shared__ float se0[MAXDEG + 1], se1[MAXDEG + 1];
    __shared__ int   sj[MAXDEG + 1];
    __shared__ float2 ps0[MAXDEG + 1], ps1[MAXDEG + 1];   // (exp_weight, idx-as-float)
    __shared__ float2 psM[MAXM];
    __shared__ float rA[128], rB[128];
    int i = blockIdx.x, tid = threadIdx.x;   // 128 threads
    int deg = g_adj_cnt[i], tot = deg + 1;
    float ad0 = g_ad[2 * i], ad1 = g_ad[2 * i + 1];
    for (int t = tid; t < tot; t += 128) {
        int j = (t < deg) ? g_adj_idx[i * MAXDEG + t] : i;
        sj[t] = j;
        float e0 = ad0 + g_as[2 * j], e1 = ad1 + g_as[2 * j + 1];
        se0[t] = (e0 > 0.f) ? e0 : 0.2f * e0;
        se1[t] = (e1 > 0.f) ? e1 : 0.2f * e1;
    }
    int mc = g_m_cnt[i];
    for (int t = tid; t < mc; t += 128) {
        int j = g_m_idx[i * MAXM + t];
        psM[t] = make_float2(g_m_val[i * MAXM + t] * g_dinvM[j], __int_as_float(j));
    }
    __syncthreads();
    float lm0 = -3.4e38f, lm1 = -3.4e38f;
    for (int t = tid; t < tot; t += 128) { lm0 = fmaxf(lm0, se0[t]); lm1 = fmaxf(lm1, se1[t]); }
    rA[tid] = lm0; rB[tid] = lm1; __syncthreads();
    for (int s = 64; s > 0; s >>= 1) {
        if (tid < s) { rA[tid] = fmaxf(rA[tid], rA[tid + s]); rB[tid] = fmaxf(rB[tid], rB[tid + s]); }
        __syncthreads();
    }
    float M0 = rA[0], M1 = rB[0]; __syncthreads();
    float ls0 = 0.f, ls1 = 0.f;
    for (int t = tid; t < tot; t += 128) {
        float jf = __int_as_float(sj[t]);
        float e0 = expf(se0[t] - M0); ps0[t] = make_float2(e0, jf); ls0 += e0;
        float e1 = expf(se1[t] - M1); ps1[t] = make_float2(e1, jf); ls1 += e1;
    }
    rA[tid] = ls0; rB[tid] = ls1; __syncthreads();
    for (int s = 64; s > 0; s >>= 1) {
        if (tid < s) { rA[tid] += rA[tid + s]; rB[tid] += rB[tid + s]; }
        __syncthreads();
    }
    float D0 = rA[0], D1 = rB[0]; __syncthreads();

    // thread owns dims d0=2*tid, d1=2*tid+1 (same head for both)
    int head = tid >> 6;
    float Dh = head ? D1 : D0;
    const float2* ps = head ? ps1 : ps0;
    const float2* W2 = (const float2*)g_Wx;
    const float2* X2 = (const float2*)g_XWM;
    float2 accA = make_float2(0.f, 0.f);
    #pragma unroll 4
    for (int k = 0; k < tot; k++) {
        float2 p = ps[k];
        float2 v = W2[(size_t)__float_as_int(p.y) * (FH / 2) + tid];
        accA.x += p.x * v.x;
        accA.y += p.x * v.y;
    }
    const float2* gbv = (const float2*)gat_b;
    const float2* Amv = (const float2*)bnAm; const float2* Agv = (const float2*)bnAg;
    const float2* Avv = (const float2*)bnAv; const float2* Abv = (const float2*)bnAb;
    float2 gb = gbv[tid], Am = Amv[tid], Ag = Agv[tid], Av = Avv[tid], Ab = Abv[tid];
    float hA0 = accA.x / Dh + gb.x, hA1 = accA.y / Dh + gb.y;
    hA0 = (hA0 - Am.x) * Ag.x * rsqrtf(Av.x + 1e-5f) + Ab.x;
    hA1 = (hA1 - Am.y) * Ag.y * rsqrtf(Av.y + 1e-5f) + Ab.y;
    hA0 = (hA0 > 0.f) ? hA0 : expm1f(hA0);
    hA1 = (hA1 > 0.f) ? hA1 : expm1f(hA1);

    float2 accM = make_float2(0.f, 0.f);
    #pragma unroll 4
    for (int k = 0; k < mc; k++) {
        float2 p = psM[k];
        float2 v = X2[(size_t)__float_as_int(p.y) * (FH / 2) + tid];
        accM.x += p.x * v.x;
        accM.y += p.x * v.y;
    }
    const float2* Mbv = (const float2*)gcnMb;
    const float2* Mm = (const float2*)bnMm; const float2* Mg = (const float2*)bnMg;
    const float2* Mv = (const float2*)bnMv; const float2* Mb = (const float2*)bnMb;
    float2 mb = Mbv[tid], mm = Mm[tid], mg = Mg[tid], mv = Mv[tid], mbb = Mb[tid];
    float di = g_dinvM[i];
    float hM0 = di * accM.x + mb.x, hM1 = di * accM.y + mb.y;
    hM0 = (hM0 - mm.x) * mg.x * rsqrtf(mv.x + 1e-5f) + mbb.x;
    hM1 = (hM1 - mm.y) * mg.y * rsqrtf(mv.y + 1e-5f) + mbb.y;
    hM0 = (hM0 > 0.f) ? hM0 : expm1f(hM0);
    hM1 = (hM1 > 0.f) ? hM1 : expm1f(hM1);

    float mu = mu_[0];
    float sp = (mu > 20.f) ? mu : log1pf(expf(mu));
    float hv0 = hA0 + sp * hM0, hv1 = hA1 + sp * hM1;
    ((float2*)g_h)[(size_t)i * (FH / 2) + tid] = make_float2(hv0, hv1);

    const float2* pw = (const float2*)prune_w;
    const float2* rw = (const float2*)rewire_w;
    float2 p0 = pw[tid], p1 = pw[128 + tid];
    float2 r0v = rw[tid], r1v = rw[128 + tid];
    rA[tid] = hv0 * p0.x + hv1 * p0.y;
    rB[tid] = hv0 * p1.x + hv1 * p1.y;
    __syncthreads();
    for (int s = 64; s > 0; s >>= 1) {
        if (tid < s) { rA[tid] += rA[tid + s]; rB[tid] += rB[tid + s]; }
        __syncthreads();
    }
    float r0 = rA[0], r1 = rB[0]; __syncthreads();
    rA[tid] = hv0 * r0v.x + hv1 * r0v.y;
    rB[tid] = hv0 * r1v.x + hv1 * r1v.y;
    __syncthreads();
    for (int s = 64; s > 0; s >>= 1) {
        if (tid < s) { rA[tid] += rA[tid + s]; rB[tid] += rB[tid + s]; }
        __syncthreads();
    }
    if (tid == 0) { g_pu[i] = r0; g_pv[i] = r1; g_ru[i] = rA[0]; g_rv[i] = rB[0]; }
}

__global__ void k_cells(const float* __restrict__ coords) {
    int i = blockIdx.x * blockDim.x + threadIdx.x;
    if (i >= NN) return;
    int cx = (int)coords[2 * i], cy = (int)coords[2 * i + 1];
    int p = atomicAdd(&g_cell_cnt[cx * 64 + cy], 1);
    if (p < CELLCAP) g_cell_nodes[(cx * 64 + cy) * CELLCAP + p] = i;
}

__global__ void k_cells_sort() {
    int c = blockIdx.x * blockDim.x + threadIdx.x;
    if (c >= 4096) return;
    int n = min(g_cell_cnt[c], CELLCAP);
    int* a = &g_cell_nodes[c * CELLCAP];
    for (int x = 1; x < n; x++) {
        int v = a[x], y = x - 1;
        while (y >= 0 && a[y] > v) { a[y + 1] = a[y]; y--; }
        a[y + 1] = v;
    }
}

__global__ void k_candidates(const float* __restrict__ coords, const float* __restrict__ A_in,
                             const float* __restrict__ rw, const float* __restrict__ rb_,
                             const float* __restrict__ tau_) {
    int gw = (blockIdx.x * blockDim.x + threadIdx.x) >> 5;
    int lane = threadIdx.x & 31;
    if (gw >= NN) return;
    int i = gw;
    float tau = tau_[0], rw2 = rw[512], rb = rb_[0];
    int cx = (int)coords[2 * i], cy = (int)coords[2 * i + 1];
    const int ox[12] = {-2,-1,-1,-1, 0, 0, 0, 0, 1, 1, 1, 2};
    const int oy[12] = { 0,-1, 0, 1,-2,-1, 1, 2,-1, 0, 1, 0};
    float rui = g_ru[i], rvi = g_rv[i];
    int cnt = 0;
    float m1 = NEGINF, m2 = NEGINF;
    for (int o = 0; o < 12; o++) {
        int nx = cx + ox[o], ny = cy + oy[o];
        if (nx < 0 || nx >= 64 || ny < 0 || ny >= 64) continue;
        int cell = nx * 64 + ny;
        int cc = min(g_cell_cnt[cell], CELLCAP);
        for (int base = 0; base < cc; base += 32) {
            int t = base + lane;
            bool ok = t < cc;
            int j = 0; float z = 0.f;
            if (ok) {
                j = g_cell_nodes[cell * CELLCAP + t];
                ok = A_in[(size_t)i * NN + j] < 1e-6f;
            }
            if (ok) {
                float ruv = (i < j) ? (rui + g_rv[j]) : (g_ru[j] + rvi);
                z = hc_gate(ruv + rw2 * mhat_bs(i, j) + rb, tau);
                if (z > m1) { m2 = m1; m1 = z; } else if (z > m2) { m2 = z; }
            }
            unsigned m = __ballot_sync(~0u, ok);
            int pos = cnt + __popc(m & ((1u << lane) - 1));
            if (ok && pos < MAXC) { g_cand_idx[i * MAXC + pos] = j; g_cand_z[i * MAXC + pos] = z; }
            cnt += __popc(m);
        }
    }
    for (int o = 16; o; o >>= 1) {
        float om1 = __shfl_xor_sync(~0u, m1, o);
        float om2 = __shfl_xor_sync(~0u, m2, o);
        float hi = fmaxf(m1, om1), lo = fminf(m1, om1);
        m2 = fmaxf(lo, fmaxf(m2, om2));
        m1 = hi;
    }
    if (lane == 0) { g_cand_cnt[i] = min(cnt, MAXC); g_thr2[i] = m2; }
}

__global__ void k_refined(const float* __restrict__ prune_w, const float* __restrict__ prune_b,
                          const float* __restrict__ tau_) {
    int gw = (blockIdx.x * blockDim.x + threadIdx.x) >> 5;
    int lane = threadIdx.x & 31;
    if (gw >= NN) return;
    int i = gw;
    float tau = tau_[0], pw2 = prune_w[512], pb = prune_b[0];
    int deg = g_adj_cnt[i];
    float wsum = 0.f;
    for (int t = lane; t < deg; t += 32) {
        int j = g_adj_idx[i * MAXDEG + t];
        float puv = (i < j) ? (g_pu[i] + g_pv[j]) : (g_pu[j] + g_pv[i]);
        float z = hc_gate(puv + pw2 * mhat_bs(i, j) + pb, tau);
        g_ref_idx[i * MAXR + t] = j;
        g_ref_w[i * MAXR + t] = z;
        wsum += z;
    }
    int cnt = deg;
    float thrI = g_thr2[i];
    int cc = g_cand_cnt[i];
    for (int base = 0; base < cc; base += 32) {
        int t = base + lane; bool ok = false; int j = 0; float z = 0.f;
        if (t < cc) {
            j = g_cand_idx[i * MAXC + t]; z = g_cand_z[i * MAXC + t];
            ok = (z >= thrI) || (z >= g_thr2[j]);
        }
        unsigned m = __ballot_sync(0xffffffffu, ok);
        int pos = cnt + __popc(m & ((1u << lane) - 1));
        if (ok) { g_ref_idx[i * MAXR + pos] = j; g_ref_w[i * MAXR + pos] = 0.5f * z; wsum += 0.5f * z; }
        cnt += __popc(m);
    }
    for (int o = 16; o; o >>= 1) wsum += __shfl_down_sync(0xffffffffu, wsum, o);
    if (lane == 0) { g_ref_cnt[i] = cnt; g_dinv_ref[i] = rsqrtf(wsum + 1.f); }
}

__global__ void k_pool(const float* __restrict__ pool_b) {
    __shared__ float red[128];
    int i = blockIdx.x, c = threadIdx.x;
    float di = g_dinv_ref[i];
    int cnt = g_ref_cnt[i];
    float acc = di * g_HW[(size_t)i * CL + c];
    #pragma unroll 4
    for (int t = 0; t < cnt; t++) {
        int j = g_ref_idx[i * MAXR + t];
        acc += g_ref_w[i * MAXR + t] * g_dinv_ref[j] * g_HW[(size_t)j * CL + c];
    }
    float pre = di * acc + pool_b[c];
    red[c] = pre; __syncthreads();
    for (int s = 64; s > 0; s >>= 1) { if (c < s) red[c] = fmaxf(red[c], red[c + s]); __syncthreads(); }
    float mx = red[0]; __syncthreads();
    float e = expf(pre - mx);
    red[c] = e; __syncthreads();
    for (int s = 64; s > 0; s >>= 1) { if (c < s) red[c] += red[c + s]; __syncthreads(); }
    g_S[(size_t)i * CL + c] = e / red[0];
}

__global__ void k_spmmT() {
    int i = blockIdx.x, c = threadIdx.x;
    int cnt = g_ref_cnt[i];
    float acc = 0.f;
    #pragma unroll 4
    for (int t = 0; t < cnt; t++)
        acc += g_ref_w[i * MAXR + t] * g_S[(size_t)g_ref_idx[i * MAXR + t] * CL + c];
    g_T[(size_t)i * CL + c] = acc;
}

__global__ void k_coarse_thr() {
    int gw = (blockIdx.x * blockDim.x + threadIdx.x) >> 5;
    int lane = threadIdx.x & 31;
    if (gw >= 128) return;
    float vv[4];
    #pragma unroll
    for (int s = 0; s < 4; s++) {
        int j = s * 32 + lane;
        vv[s] = (j == gw) ? 0.f : g_Ac[gw * 128 + j];
    }
    float thr = 0.f;
    for (int r = 0; r < 8; r++) {
        float lm = fmaxf(fmaxf(vv[0], vv[1]), fmaxf(vv[2], vv[3]));
        float wm = lm;
        for (int o = 16; o; o >>= 1) wm = fmaxf(wm, __shfl_xor_sync(~0u, wm, o));
        unsigned who = __ballot_sync(~0u, lm == wm);
        if (lane == (__ffs(who) - 1)) {
            #pragma unroll
            for (int s = 0; s < 4; s++) if (vv[s] == wm) { vv[s] = -1e30f; break; }
        }
        thr = wm;
    }
    if (lane == 0) g_cthr[gw] = thr;
}

__global__ void k_coarse_write(float* __restrict__ out) {
    int t = blockIdx.x * blockDim.x + threadIdx.x;
    if (t >= 128 * 128) return;
    int i = t >> 7, j = t & 127;
    if (i == j) { out[t] = 0.f; return; }
    float vij = g_Ac[i * 128 + j];
    float vji = g_Ac[j * 128 + i];
    float a = (vij >= g_cthr[i]) ? vij : 0.f;
    float b = (vji >= g_cthr[j]) ? vji : 0.f;
    out[t] = fmaxf(a, b);
}

// ---------- host ----------
extern "C" void kernel_launch(void* const* d_in, const int* in_sizes, int n_in,
                              void* d_out, int out_size) {
    const float* x       = (const float*)d_in[0];
    const float* A_in    = (const float*)d_in[1];
    const float* A_motif = (const float*)d_in[2];
    const float* coords  = (const float*)d_in[3];
    const float* gat_w   = (const float*)d_in[4];
    const float* gat_as  = (const float*)d_in[5];
    const float* gat_ad  = (const float*)d_in[6];
    const float* gat_b   = (const float*)d_in[7];
    const float* bnAg = (const float*)d_in[8],  *bnAb = (const float*)d_in[9];
    const float* bnAm = (const float*)d_in[10], *bnAv = (const float*)d_in[11];
    const float* gcnMw = (const float*)d_in[12], *gcnMb = (const float*)d_in[13];
    const float* bnMg = (const float*)d_in[14], *bnMb = (const float*)d_in[15];
    const float* bnMm = (const float*)d_in[16], *bnMv = (const float*)d_in[17];
    const float* mu   = (const float*)d_in[18], *tau  = (const float*)d_in[19];
    const float* prune_w = (const float*)d_in[20], *prune_b = (const float*)d_in[21];
    const float* rewire_w = (const float*)d_in[22], *rewire_b = (const float*)d_in[23];
    const float* pool_w = (const float*)d_in[24], *pool_b = (const float*)d_in[25];
    float* out = (float*)d_out;

    float *Wx, *XWM, *h, *HW, *S, *T, *Cpart, *Ac;
    cudaGetSymbolAddress((void**)&Wx, g_Wx);
    cudaGetSymbolAddress((void**)&XWM, g_XWM);
    cudaGetSymbolAddress((void**)&h, g_h);
    cudaGetSymbolAddress((void**)&HW, g_HW);
    cudaGetSymbolAddress((void**)&S, g_S);
    cudaGetSymbolAddress((void**)&T, g_T);
    cudaGetSymbolAddress((void**)&Cpart, g_Cpart);
    cudaGetSymbolAddress((void**)&Ac, g_Ac);

    k_phase1<<<1536, 256>>>(A_in, A_motif, x, gat_w, gcnMw, Wx, XWM);
    k_mfilter<<<512, 256>>>();
    k_attn_coef<<<1024, 256>>>(gat_as, gat_ad);
    k_aggregate<<<NN, 128>>>(gat_b, bnAg, bnAb, bnAm, bnAv, gcnMb,
                             bnMg, bnMb, bnMm, bnMv, mu, prune_w, rewire_w);
    k_cells<<<16, 256>>>(coords);
    k_cells_sort<<<16, 256>>>();
    k_candidates<<<512, 256>>>(coords, A_in, rewire_w, rewire_b, tau);
    k_refined<<<512, 256>>>(prune_w, prune_b, tau);
    k_gemm<<<dim3(CL / 64, NN / 64), 256>>>(h, pool_w, HW, NN, CL, FH);
    k_pool<<<NN, 128>>>(pool_b);
    k_spmmT<<<NN, 128>>>();
    k_gemm_tn<<<dim3(FH / 64, 128 / 64, KS), 256>>>(S, h, Cpart, 128, FH, NN);
    k_reduce_part<<<(128 * FH + 255) / 256, 256>>>(out, 128 * FH);
    k_gemm_tn<<<dim3(CL / 64, 128 / 64, KS), 256>>>(S, T, Cpart, 128, CL, NN);
    k_reduce_part<<<(128 * CL + 255) / 256, 256>>>(Ac, 128 * CL);
    k_coarse_thr<<<16, 256>>>();
    k_coarse_write<<<64, 256>>>(out + 128 * FH);
}

// round 15
// speedup vs baseline: 1.2176x; 1.0519x over previous
#include <cuda_runtime.h>
#include <math.h>

#define NN 4096
#define FH 256
#define CL 128
#define MAXDEG 128
#define MAXM 128
#define MAXC 64
#define MAXR (MAXDEG + MAXC)
#define CELLCAP 32
#define NEGINF (-1e9f)
#define KS 16

// ---------- scratch ----------
__device__ int   g_adj_idx[NN * MAXDEG];
__device__ int   g_adj_cnt[NN];
__device__ int   g_mf_idx[NN * MAXM];
__device__ float g_mf_val[NN * MAXM];
__device__ int   g_mf_cnt[NN];
__device__ float g_m_thr[NN];
__device__ int   g_m_idx[NN * MAXM];
__device__ float g_m_val[NN * MAXM];
__device__ int   g_m_cnt[NN];
__device__ float g_dinvM[NN];
__device__ float g_Wx[NN * FH];
__device__ float g_XWM[NN * FH];
__device__ float g_as[NN * 2];
__device__ float g_ad[NN * 2];
__device__ float g_h[NN * FH];
__device__ float g_pu[NN], g_pv[NN], g_ru[NN], g_rv[NN];
__device__ int   g_cell_cnt[4096];
__device__ int   g_cell_nodes[4096 * CELLCAP];
__device__ int   g_cand_idx[NN * MAXC];
__device__ float g_cand_z[NN * MAXC];
__device__ int   g_cand_cnt[NN];
__device__ float g_thr2[NN];
__device__ int   g_ref_idx[NN * MAXR];
__device__ float g_ref_w[NN * MAXR];
__device__ int   g_ref_cnt[NN];
__device__ float g_dinv_ref[NN];
__device__ float g_HW[NN * CL];
__device__ float g_S[NN * CL];
__device__ float g_T[NN * CL];
__device__ float g_Cpart[KS * 128 * 256];
__device__ float g_Ac[128 * 128];
__device__ float g_cthr[128];

// ---------- helpers ----------
__device__ __forceinline__ float hc_gate(float logit, float tau) {
    float t = fmaxf(tau, 0.1f);
    float s = 1.f / (1.f + expf(-logit / t));
    s = s * 1.2f - 0.1f;
    return fminf(fmaxf(s, 0.f), 1.f);
}
__device__ __forceinline__ float mhat_bs(int i, int j) {
    int c = g_m_cnt[i];
    const int* ip = &g_m_idx[i * MAXM];
    int lo = 0, hi = c;
    while (lo < hi) { int mid = (lo + hi) >> 1; if (ip[mid] < j) lo = mid + 1; else hi = mid; }
    return (lo < c && ip[lo] == j) ? g_m_val[i * MAXM + lo] : 0.f;
}

// ---------- phase-1 device bodies ----------
__device__ void adj_row_body(const float* __restrict__ A, int gw, int lane) {
    const float4* row = (const float4*)(A + (size_t)gw * NN);
    unsigned below = (1u << lane) - 1;
    int c = 0;
    #pragma unroll 4
    for (int b = 0; b < NN / 4; b += 32) {
        float4 v = row[b + lane];
        bool p0 = v.x > 0.f, p1 = v.y > 0.f, p2 = v.z > 0.f, p3 = v.w > 0.f;
        unsigned m0 = __ballot_sync(~0u, p0), m1 = __ballot_sync(~0u, p1);
        unsigned m2 = __ballot_sync(~0u, p2), m3 = __ballot_sync(~0u, p3);
        int base = c + __popc(m0 & below) + __popc(m1 & below) + __popc(m2 & below) + __popc(m3 & below);
        int col = (b + lane) * 4, o = 0;
        if (p0 && base + o < MAXDEG) g_adj_idx[gw * MAXDEG + base + o] = col;
        if (p0) o++;
        if (p1 && base + o < MAXDEG) g_adj_idx[gw * MAXDEG + base + o] = col + 1;
        if (p1) o++;
        if (p2 && base + o < MAXDEG) g_adj_idx[gw * MAXDEG + base + o] = col + 2;
        if (p2) o++;
        if (p3 && base + o < MAXDEG) g_adj_idx[gw * MAXDEG + base + o] = col + 3;
        c += __popc(m0) + __popc(m1) + __popc(m2) + __popc(m3);
    }
    if (lane == 0) g_adj_cnt[gw] = min(c, MAXDEG);
}

__device__ void motif_row_body(const float* __restrict__ A, int gw, int lane) {
    const float4* row = (const float4*)(A + (size_t)gw * NN);
    unsigned below = (1u << lane) - 1;
    int c = 0;
    #pragma unroll 4
    for (int b = 0; b < NN / 4; b += 32) {
        float4 v = row[b + lane];
        bool p0 = v.x > 0.f, p1 = v.y > 0.f, p2 = v.z > 0.f, p3 = v.w > 0.f;
        unsigned m0 = __ballot_sync(~0u, p0), m1 = __ballot_sync(~0u, p1);
        unsigned m2 = __ballot_sync(~0u, p2), m3 = __ballot_sync(~0u, p3);
        int base = c + __popc(m0 & below) + __popc(m1 & below) + __popc(m2 & below) + __popc(m3 & below);
        int col = (b + lane) * 4, o = 0;
        if (p0 && base + o < MAXM) { g_mf_idx[gw * MAXM + base + o] = col;     g_mf_val[gw * MAXM + base + o] = v.x; }
        if (p0) o++;
        if (p1 && base + o < MAXM) { g_mf_idx[gw * MAXM + base + o] = col + 1; g_mf_val[gw * MAXM + base + o] = v.y; }
        if (p1) o++;
        if (p2 && base + o < MAXM) { g_mf_idx[gw * MAXM + base + o] = col + 2; g_mf_val[gw * MAXM + base + o] = v.z; }
        if (p2) o++;
        if (p3 && base + o < MAXM) { g_mf_idx[gw * MAXM + base + o] = col + 3; g_mf_val[gw * MAXM + base + o] = v.w; }
        c += __popc(m0) + __popc(m1) + __popc(m2) + __popc(m3);
    }
    c = min(c, MAXM);
    __syncwarp();
    float vv[4];
    #pragma unroll
    for (int s = 0; s < 4; s++) {
        int t = s * 32 + lane;
        vv[s] = (t < c) ? g_mf_val[gw * MAXM + t] : -2.f;
    }
    float thr = 0.f;
    if (c > 8) {
        for (int r = 0; r < 8; r++) {
            float lm = fmaxf(fmaxf(vv[0], vv[1]), fmaxf(vv[2], vv[3]));
            float wm = lm;
            for (int o = 16; o; o >>= 1) wm = fmaxf(wm, __shfl_xor_sync(~0u, wm, o));
            unsigned who = __ballot_sync(~0u, lm == wm);
            if (lane == (__ffs(who) - 1)) {
                #pragma unroll
                for (int s = 0; s < 4; s++) if (vv[s] == wm) { vv[s] = -2.f; break; }
            }
            thr = wm;
        }
    }
    if (lane == 0) { g_mf_cnt[gw] = c; g_m_thr[gw] = thr; }
}

// R9 double-buffered 64x64 GEMM tile body
__device__ void gemm_tile_body(const float* __restrict__ A, const float* __restrict__ B,
                               float* __restrict__ C, int M, int Nc, int K,
                               int bm, int bn, float (*As)[16][65], float (*Bs)[16][65]) {
    int tid = threadIdx.x, tr = tid >> 4, tc = tid & 15;
    int am[4], ak[4], bk[4], bnn[4];
    float ra[4], rb[4];
    #pragma unroll
    for (int l = 0; l < 4; l++) {
        int e = tid + l * 256;
        am[l] = e >> 4; ak[l] = e & 15;
        bk[l] = e >> 6; bnn[l] = e & 63;
    }
    int nP = K / 16;
    #pragma unroll
    for (int l = 0; l < 4; l++) {
        ra[l] = A[(size_t)(bm + am[l]) * K + ak[l]];
        rb[l] = B[(size_t)bk[l] * Nc + bn + bnn[l]];
    }
    #pragma unroll
    for (int l = 0; l < 4; l++) {
        As[0][ak[l]][am[l]] = ra[l];
        Bs[0][bk[l]][bnn[l]] = rb[l];
    }
    __syncthreads();
    float acc[4][4] = {};
    for (int p = 0; p < nP; p++) {
        int cur = p & 1;
        if (p + 1 < nP) {
            int k0 = (p + 1) * 16;
            #pragma unroll
            for (int l = 0; l < 4; l++) {
                ra[l] = A[(size_t)(bm + am[l]) * K + k0 + ak[l]];
                rb[l] = B[(size_t)(k0 + bk[l]) * Nc + bn + bnn[l]];
            }
        }
        #pragma unroll
        for (int kk = 0; kk < 16; kk++) {
            float a[4], b[4];
            #pragma unroll
            for (int r = 0; r < 4; r++) a[r] = As[cur][kk][tr * 4 + r];
            #pragma unroll
            for (int c = 0; c < 4; c++) b[c] = Bs[cur][kk][tc * 4 + c];
            #pragma unroll
            for (int r = 0; r < 4; r++)
                #pragma unroll
                for (int c = 0; c < 4; c++) acc[r][c] += a[r] * b[c];
        }
        if (p + 1 < nP) {
            #pragma unroll
            for (int l = 0; l < 4; l++) {
                As[cur ^ 1][ak[l]][am[l]] = ra[l];
                Bs[cur ^ 1][bk[l]][bnn[l]] = rb[l];
            }
        }
        __syncthreads();
    }
    #pragma unroll
    for (int r = 0; r < 4; r++)
        #pragma unroll
        for (int c = 0; c < 4; c++)
            C[(size_t)(bm + tr * 4 + r) * Nc + bn + tc * 4 + c] = acc[r][c];
}

// ---------- Phase 1 fused ----------
__global__ void k_phase1(const float* __restrict__ A_in, const float* __restrict__ A_motif,
                         const float* __restrict__ x, const float* __restrict__ gat_w,
                         const float* __restrict__ gcnMw, float* __restrict__ Wx,
                         float* __restrict__ XWM) {
    __shared__ float As[2][16][65], Bs[2][16][65];
    int b = blockIdx.x;
    int lane = threadIdx.x & 31, wid = threadIdx.x >> 5;
    if (b < 512) {
        if (b < 16) g_cell_cnt[b * 256 + threadIdx.x] = 0;
        adj_row_body(A_in, b * 8 + wid, lane);
    } else if (b < 1024) {
        motif_row_body(A_motif, (b - 512) * 8 + wid, lane);
    } else if (b < 1280) {
        int t = b - 1024;
        gemm_tile_body(x, gat_w, Wx, NN, FH, 128, (t >> 2) * 64, (t & 3) * 64, As, Bs);
    } else {
        int t = b - 1280;
        gemm_tile_body(x, gcnMw, XWM, NN, FH, 128, (t >> 2) * 64, (t & 3) * 64, As, Bs);
    }
}

// ---------- Phase 2 fused: mfilter | attn_coef | cells insert ----------
__global__ void k_phase2(const float* __restrict__ coords,
                         const float* __restrict__ asw, const float* __restrict__ adw) {
    int b = blockIdx.x;
    if (b < 512) {                 // mfilter, warp per row
        int gw = b * 8 + (threadIdx.x >> 5), lane = threadIdx.x & 31;
        int i = gw, cnt = g_mf_cnt[i], out = 0;
        float thrI = g_m_thr[i], wsum = 0.f;
        for (int base = 0; base < cnt; base += 32) {
            int t = base + lane; bool ok = t < cnt; int j = 0; float v = 0.f;
            if (ok) {
                j = g_mf_idx[i * MAXM + t]; v = g_mf_val[i * MAXM + t];
                ok = (v >= thrI) || (v >= g_m_thr[j]);
            }
            unsigned m = __ballot_sync(0xffffffffu, ok);
            int pos = out + __popc(m & ((1u << lane) - 1));
            if (ok) { g_m_idx[i * MAXM + pos] = j; g_m_val[i * MAXM + pos] = v; wsum += v; }
            out += __popc(m);
        }
        for (int o = 16; o; o >>= 1) wsum += __shfl_down_sync(0xffffffffu, wsum, o);
        if (lane == 0) { g_m_cnt[i] = out; g_dinvM[i] = (wsum > 0.f) ? rsqrtf(wsum) : 0.f; }
    } else if (b < 1536) {         // attn coef, warp per (node, head)
        int gw = (b - 512) * 8 + (threadIdx.x >> 5), lane = threadIdx.x & 31;
        int node = gw >> 1, hh = gw & 1;
        const float* row = g_Wx + (size_t)node * FH + hh * 128;
        float s = 0.f, d = 0.f;
        for (int k = lane; k < 128; k += 32) {
            float w = row[k];
            s += w * asw[hh * 128 + k];
            d += w * adw[hh * 128 + k];
        }
        for (int o = 16; o; o >>= 1) {
            s += __shfl_down_sync(0xffffffffu, s, o);
            d += __shfl_down_sync(0xffffffffu, d, o);
        }
        if (lane == 0) { g_as[node * 2 + hh] = s; g_ad[node * 2 + hh] = d; }
    } else {                       // cells insert, 16 blocks
        int i = (b - 1536) * 256 + threadIdx.x;
        int cx = (int)coords[2 * i], cy = (int)coords[2 * i + 1];
        int p = atomicAdd(&g_cell_cnt[cx * 64 + cy], 1);
        if (p < CELLCAP) g_cell_nodes[(cx * 64 + cy) * CELLCAP + p] = i;
    }
}

__global__ void k_gemm(const float* __restrict__ A, const float* __restrict__ B,
                       float* __restrict__ C, int M, int Nc, int K) {
    __shared__ float As[2][16][65], Bs[2][16][65];
    gemm_tile_body(A, B, C, M, Nc, K, blockIdx.y * 64, blockIdx.x * 64, As, Bs);
}

__global__ void k_gemm_tn(const float* __restrict__ A, const float* __restrict__ B,
                          float* __restrict__ Cpart, int M, int Nc, int K) {
    __shared__ float As[2][16][65], Bs[2][16][65];
    int ks = blockIdx.z, kbeg = ks * (K / KS);
    int nP = (K / KS) / 16;
    int bm = blockIdx.y * 64, bn = blockIdx.x * 64;
    int tid = threadIdx.x, tr = tid >> 4, tc = tid & 15;
    int lk[4], ln[4];
    float ra[4], rb[4];
    #pragma unroll
    for (int l = 0; l < 4; l++) {
        int e = tid + l * 256;
        lk[l] = e >> 6; ln[l] = e & 63;
    }
    #pragma unroll
    for (int l = 0; l < 4; l++) {
        ra[l] = A[(size_t)(kbeg + lk[l]) * M + bm + ln[l]];
        rb[l] = B[(size_t)(kbeg + lk[l]) * Nc + bn + ln[l]];
    }
    #pragma unroll
    for (int l = 0; l < 4; l++) {
        As[0][lk[l]][ln[l]] = ra[l];
        Bs[0][lk[l]][ln[l]] = rb[l];
    }
    __syncthreads();
    float acc[4][4] = {};
    for (int p = 0; p < nP; p++) {
        int cur = p & 1;
        if (p + 1 < nP) {
            int k0 = kbeg + (p + 1) * 16;
            #pragma unroll
            for (int l = 0; l < 4; l++) {
                ra[l] = A[(size_t)(k0 + lk[l]) * M + bm + ln[l]];
                rb[l] = B[(size_t)(k0 + lk[l]) * Nc + bn + ln[l]];
            }
        }
        #pragma unroll
        for (int kk = 0; kk < 16; kk++) {
            float a[4], b[4];
            #pragma unroll
            for (int r = 0; r < 4; r++) a[r] = As[cur][kk][tr * 4 + r];
            #pragma unroll
            for (int c = 0; c < 4; c++) b[c] = Bs[cur][kk][tc * 4 + c];
            #pragma unroll
            for (int r = 0; r < 4; r++)
                #pragma unroll
                for (int c = 0; c < 4; c++) acc[r][c] += a[r] * b[c];
        }
        if (p + 1 < nP) {
            #pragma unroll
            for (int l = 0; l < 4; l++) {
                As[cur ^ 1][lk[l]][ln[l]] = ra[l];
                Bs[cur ^ 1][lk[l]][ln[l]] = rb[l];
            }
        }
        __syncthreads();
    }
    float* Cp = Cpart + (size_t)ks * M * Nc;
    #pragma unroll
    for (int r = 0; r < 4; r++)
        #pragma unroll
        for (int c = 0; c < 4; c++)
            Cp[(size_t)(bm + tr * 4 + r) * Nc + bn + tc * 4 + c] = acc[r][c];
}

__global__ void k_reduce_part(float* __restrict__ dst, int MN) {
    int t = blockIdx.x * blockDim.x + threadIdx.x;
    if (t >= MN) return;
    float s = 0.f;
    for (int z = 0; z < KS; z++) s += g_Cpart[(size_t)z * MN + t];
    dst[t] = s;
}

// ---------- aggregate (128 thr, 2 dims/thr, reg-capped) + cells_sort tail ----------
__global__ void __launch_bounds__(128, 16) k_aggregate(
    const float* __restrict__ gat_b,
    const float* __restrict__ bnAg, const float* __restrict__ bnAb,
    const float* __restrict__ bnAm, const float* __restrict__ bnAv,
    const float* __restrict__ gcnMb,
    const float* __restrict__ bnMg, const float* __restrict__ bnMb,
    const float* __restrict__ bnMm, const float* __restrict__ bnMv,
    const float* __restrict__ mu_, const float* __restrict__ prune_w,
    const float* __restrict__ rewire_w)
{
    if (blockIdx.x >= NN) {        // cells_sort: 32 blocks x 128 threads = 4096 cells
        int c = (blockIdx.x - NN) * 128 + threadIdx.x;
        int n = min(g_cell_cnt[c], CELLCAP);
        int* a = &g_cell_nodes[c * CELLCAP];
        for (int x = 1; x < n; x++) {
            int v = a[x], y = x - 1;
            while (y >= 0 && a[y] > v) { a[y + 1] = a[y]; y--; }
            a[y + 1] = v;
        }
        return;
    }
    __shared__ float se0[MAXDEG + 1], se1[MAXDEG + 1];
    __shared__ int   sj[MAXDEG + 1];
    __shared__ float2 ps0[MAXDEG + 1], ps1[MAXDEG + 1];
    __shared__ float2 psM[MAXM];
    __shared__ float rA[128], rB[128];
    int i = blockIdx.x, tid = threadIdx.x;
    int deg = g_adj_cnt[i], tot = deg + 1;
    float ad0 = g_ad[2 * i], ad1 = g_ad[2 * i + 1];
    for (int t = tid; t < tot; t += 128) {
        int j = (t < deg) ? g_adj_idx[i * MAXDEG + t] : i;
        sj[t] = j;
        float e0 = ad0 + g_as[2 * j], e1 = ad1 + g_as[2 * j + 1];
        se0[t] = (e0 > 0.f) ? e0 : 0.2f * e0;
        se1[t] = (e1 > 0.f) ? e1 : 0.2f * e1;
    }
    int mc = g_m_cnt[i];
    for (int t = tid; t < mc; t += 128) {
        int j = g_m_idx[i * MAXM + t];
        psM[t] = make_float2(g_m_val[i * MAXM + t] * g_dinvM[j], __int_as_float(j));
    }
    __syncthreads();
    float lm0 = -3.4e38f, lm1 = -3.4e38f;
    for (int t = tid; t < tot; t += 128) { lm0 = fmaxf(lm0, se0[t]); lm1 = fmaxf(lm1, se1[t]); }
    rA[tid] = lm0; rB[tid] = lm1; __syncthreads();
    for (int s = 64; s > 0; s >>= 1) {
        if (tid < s) { rA[tid] = fmaxf(rA[tid], rA[tid + s]); rB[tid] = fmaxf(rB[tid], rB[tid + s]); }
        __syncthreads();
    }
    float M0 = rA[0], M1 = rB[0]; __syncthreads();
    float ls0 = 0.f, ls1 = 0.f;
    for (int t = tid; t < tot; t += 128) {
        float jf = __int_as_float(sj[t]);
        float e0 = expf(se0[t] - M0); ps0[t] = make_float2(e0, jf); ls0 += e0;
        float e1 = expf(se1[t] - M1); ps1[t] = make_float2(e1, jf); ls1 += e1;
    }
    rA[tid] = ls0; rB[tid] = ls1; __syncthreads();
    for (int s = 64; s > 0; s >>= 1) {
        if (tid < s) { rA[tid] += rA[tid + s]; rB[tid] += rB[tid + s]; }
        __syncthreads();
    }
    float D0 = rA[0], D1 = rB[0]; __syncthreads();

    int head = tid >> 6;
    float Dh = head ? D1 : D0;
    const float2* ps = head ? ps1 : ps0;
    const float2* W2 = (const float2*)g_Wx;
    const float2* X2 = (const float2*)g_XWM;
    float2 accA = make_float2(0.f, 0.f);
    #pragma unroll 4
    for (int k = 0; k < tot; k++) {
        float2 p = ps[k];
        float2 v = W2[(size_t)__float_as_int(p.y) * (FH / 2) + tid];
        accA.x += p.x * v.x;
        accA.y += p.x * v.y;
    }
    const float2* gbv = (const float2*)gat_b;
    const float2* Amv = (const float2*)bnAm; const float2* Agv = (const float2*)bnAg;
    const float2* Avv = (const float2*)bnAv; const float2* Abv = (const float2*)bnAb;
    float2 gb = gbv[tid], Am = Amv[tid], Ag = Agv[tid], Av = Avv[tid], Ab = Abv[tid];
    float hA0 = accA.x / Dh + gb.x, hA1 = accA.y / Dh + gb.y;
    hA0 = (hA0 - Am.x) * Ag.x * rsqrtf(Av.x + 1e-5f) + Ab.x;
    hA1 = (hA1 - Am.y) * Ag.y * rsqrtf(Av.y + 1e-5f) + Ab.y;
    hA0 = (hA0 > 0.f) ? hA0 : expm1f(hA0);
    hA1 = (hA1 > 0.f) ? hA1 : expm1f(hA1);

    float2 accM = make_float2(0.f, 0.f);
    #pragma unroll 4
    for (int k = 0; k < mc; k++) {
        float2 p = psM[k];
        float2 v = X2[(size_t)__float_as_int(p.y) * (FH / 2) + tid];
        accM.x += p.x * v.x;
        accM.y += p.x * v.y;
    }
    const float2* Mbv = (const float2*)gcnMb;
    const float2* Mm = (const float2*)bnMm; const float2* Mg = (const float2*)bnMg;
    const float2* Mv = (const float2*)bnMv; const float2* Mb = (const float2*)bnMb;
    float2 mb = Mbv[tid], mm = Mm[tid], mg = Mg[tid], mv = Mv[tid], mbb = Mb[tid];
    float di = g_dinvM[i];
    float hM0 = di * accM.x + mb.x, hM1 = di * accM.y + mb.y;
    hM0 = (hM0 - mm.x) * mg.x * rsqrtf(mv.x + 1e-5f) + mbb.x;
    hM1 = (hM1 - mm.y) * mg.y * rsqrtf(mv.y + 1e-5f) + mbb.y;
    hM0 = (hM0 > 0.f) ? hM0 : expm1f(hM0);
    hM1 = (hM1 > 0.f) ? hM1 : expm1f(hM1);

    float mu = mu_[0];
    float sp = (mu > 20.f) ? mu : log1pf(expf(mu));
    float hv0 = hA0 + sp * hM0, hv1 = hA1 + sp * hM1;
    ((float2*)g_h)[(size_t)i * (FH / 2) + tid] = make_float2(hv0, hv1);

    const float2* pw = (const float2*)prune_w;
    const float2* rw = (const float2*)rewire_w;
    float2 p0 = pw[tid], p1 = pw[128 + tid];
    float2 r0v = rw[tid], r1v = rw[128 + tid];
    rA[tid] = hv0 * p0.x + hv1 * p0.y;
    rB[tid] = hv0 * p1.x + hv1 * p1.y;
    __syncthreads();
    for (int s = 64; s > 0; s >>= 1) {
        if (tid < s) { rA[tid] += rA[tid + s]; rB[tid] += rB[tid + s]; }
        __syncthreads();
    }
    float r0 = rA[0], r1 = rB[0]; __syncthreads();
    rA[tid] = hv0 * r0v.x + hv1 * r0v.y;
    rB[tid] = hv0 * r1v.x + hv1 * r1v.y;
    __syncthreads();
    for (int s = 64; s > 0; s >>= 1) {
        if (tid < s) { rA[tid] += rA[tid + s]; rB[tid] += rB[tid + s]; }
        __syncthreads();
    }
    if (tid == 0) { g_pu[i] = r0; g_pv[i] = r1; g_ru[i] = rA[0]; g_rv[i] = rB[0]; }
}

__global__ void k_candidates(const float* __restrict__ coords, const float* __restrict__ A_in,
                             const float* __restrict__ rw, const float* __restrict__ rb_,
                             const float* __restrict__ tau_) {
    int gw = (blockIdx.x * blockDim.x + threadIdx.x) >> 5;
    int lane = threadIdx.x & 31;
    if (gw >= NN) return;
    int i = gw;
    float tau = tau_[0], rw2 = rw[512], rb = rb_[0];
    int cx = (int)coords[2 * i], cy = (int)coords[2 * i + 1];
    const int ox[12] = {-2,-1,-1,-1, 0, 0, 0, 0, 1, 1, 1, 2};
    const int oy[12] = { 0,-1, 0, 1,-2,-1, 1, 2,-1, 0, 1, 0};
    float rui = g_ru[i], rvi = g_rv[i];
    int cnt = 0;
    float m1 = NEGINF, m2 = NEGINF;
    for (int o = 0; o < 12; o++) {
        int nx = cx + ox[o], ny = cy + oy[o];
        if (nx < 0 || nx >= 64 || ny < 0 || ny >= 64) continue;
        int cell = nx * 64 + ny;
        int cc = min(g_cell_cnt[cell], CELLCAP);
        for (int base = 0; base < cc; base += 32) {
            int t = base + lane;
            bool ok = t < cc;
            int j = 0; float z = 0.f;
            if (ok) {
                j = g_cell_nodes[cell * CELLCAP + t];
                ok = A_in[(size_t)i * NN + j] < 1e-6f;
            }
            if (ok) {
                float ruv = (i < j) ? (rui + g_rv[j]) : (g_ru[j] + rvi);
                z = hc_gate(ruv + rw2 * mhat_bs(i, j) + rb, tau);
                if (z > m1) { m2 = m1; m1 = z; } else if (z > m2) { m2 = z; }
            }
            unsigned m = __ballot_sync(~0u, ok);
            int pos = cnt + __popc(m & ((1u << lane) - 1));
            if (ok && pos < MAXC) { g_cand_idx[i * MAXC + pos] = j; g_cand_z[i * MAXC + pos] = z; }
            cnt += __popc(m);
        }
    }
    for (int o = 16; o; o >>= 1) {
        float om1 = __shfl_xor_sync(~0u, m1, o);
        float om2 = __shfl_xor_sync(~0u, m2, o);
        float hi = fmaxf(m1, om1), lo = fminf(m1, om1);
        m2 = fmaxf(lo, fmaxf(m2, om2));
        m1 = hi;
    }
    if (lane == 0) { g_cand_cnt[i] = min(cnt, MAXC); g_thr2[i] = m2; }
}

__global__ void k_refined(const float* __restrict__ prune_w, const float* __restrict__ prune_b,
                          const float* __restrict__ tau_) {
    int gw = (blockIdx.x * blockDim.x + threadIdx.x) >> 5;
    int lane = threadIdx.x & 31;
    if (gw >= NN) return;
    int i = gw;
    float tau = tau_[0], pw2 = prune_w[512], pb = prune_b[0];
    int deg = g_adj_cnt[i];
    float wsum = 0.f;
    for (int t = lane; t < deg; t += 32) {
        int j = g_adj_idx[i * MAXDEG + t];
        float puv = (i < j) ? (g_pu[i] + g_pv[j]) : (g_pu[j] + g_pv[i]);
        float z = hc_gate(puv + pw2 * mhat_bs(i, j) + pb, tau);
        g_ref_idx[i * MAXR + t] = j;
        g_ref_w[i * MAXR + t] = z;
        wsum += z;
    }
    int cnt = deg;
    float thrI = g_thr2[i];
    int cc = g_cand_cnt[i];
    for (int base = 0; base < cc; base += 32) {
        int t = base + lane; bool ok = false; int j = 0; float z = 0.f;
        if (t < cc) {
            j = g_cand_idx[i * MAXC + t]; z = g_cand_z[i * MAXC + t];
            ok = (z >= thrI) || (z >= g_thr2[j]);
        }
        unsigned m = __ballot_sync(0xffffffffu, ok);
        int pos = cnt + __popc(m & ((1u << lane) - 1));
        if (ok) { g_ref_idx[i * MAXR + pos] = j; g_ref_w[i * MAXR + pos] = 0.5f * z; wsum += 0.5f * z; }
        cnt += __popc(m);
    }
    for (int o = 16; o; o >>= 1) wsum += __shfl_down_sync(0xffffffffu, wsum, o);
    if (lane == 0) { g_ref_cnt[i] = cnt; g_dinv_ref[i] = rsqrtf(wsum + 1.f); }
}

__global__ void k_pool(const float* __restrict__ pool_b) {
    __shared__ float red[128];
    int i = blockIdx.x, c = threadIdx.x;
    float di = g_dinv_ref[i];
    int cnt = g_ref_cnt[i];
    float acc = di * g_HW[(size_t)i * CL + c];
    #pragma unroll 4
    for (int t = 0; t < cnt; t++) {
        int j = g_ref_idx[i * MAXR + t];
        acc += g_ref_w[i * MAXR + t] * g_dinv_ref[j] * g_HW[(size_t)j * CL + c];
    }
    float pre = di * acc + pool_b[c];
    red[c] = pre; __syncthreads();
    for (int s = 64; s > 0; s >>= 1) { if (c < s) red[c] = fmaxf(red[c], red[c + s]); __syncthreads(); }
    float mx = red[0]; __syncthreads();
    float e = expf(pre - mx);
    red[c] = e; __syncthreads();
    for (int s = 64; s > 0; s >>= 1) { if (c < s) red[c] += red[c + s]; __syncthreads(); }
    g_S[(size_t)i * CL + c] = e / red[0];
}

__global__ void k_spmmT() {
    int i = blockIdx.x, c = threadIdx.x;
    int cnt = g_ref_cnt[i];
    float acc = 0.f;
    #pragma unroll 4
    for (int t = 0; t < cnt; t++)
        acc += g_ref_w[i * MAXR + t] * g_S[(size_t)g_ref_idx[i * MAXR + t] * CL + c];
    g_T[(size_t)i * CL + c] = acc;
}

__global__ void k_coarse_thr() {
    int gw = (blockIdx.x * blockDim.x + threadIdx.x) >> 5;
    int lane = threadIdx.x & 31;
    if (gw >= 128) return;
    float vv[4];
    #pragma unroll
    for (int s = 0; s < 4; s++) {
        int j = s * 32 + lane;
        vv[s] = (j == gw) ? 0.f : g_Ac[gw * 128 + j];
    }
    float thr = 0.f;
    for (int r = 0; r < 8; r++) {
        float lm = fmaxf(fmaxf(vv[0], vv[1]), fmaxf(vv[2], vv[3]));
        float wm = lm;
        for (int o = 16; o; o >>= 1) wm = fmaxf(wm, __shfl_xor_sync(~0u, wm, o));
        unsigned who = __ballot_sync(~0u, lm == wm);
        if (lane == (__ffs(who) - 1)) {
            #pragma unroll
            for (int s = 0; s < 4; s++) if (vv[s] == wm) { vv[s] = -1e30f; break; }
        }
        thr = wm;
    }
    if (lane == 0) g_cthr[gw] = thr;
}

__global__ void k_coarse_write(float* __restrict__ out) {
    int t = blockIdx.x * blockDim.x + threadIdx.x;
    if (t >= 128 * 128) return;
    int i = t >> 7, j = t & 127;
    if (i == j) { out[t] = 0.f; return; }
    float vij = g_Ac[i * 128 + j];
    float vji = g_Ac[j * 128 + i];
    float a = (vij >= g_cthr[i]) ? vij : 0.f;
    float b = (vji >= g_cthr[j]) ? vji : 0.f;
    out[t] = fmaxf(a, b);
}

// ---------- host ----------
extern "C" void kernel_launch(void* const* d_in, const int* in_sizes, int n_in,
                              void* d_out, int out_size) {
    const float* x       = (const float*)d_in[0];
    const float* A_in    = (const float*)d_in[1];
    const float* A_motif = (const float*)d_in[2];
    const float* coords  = (const float*)d_in[3];
    const float* gat_w   = (const float*)d_in[4];
    const float* gat_as  = (const float*)d_in[5];
    const float* gat_ad  = (const float*)d_in[6];
    const float* gat_b   = (const float*)d_in[7];
    const float* bnAg = (const float*)d_in[8],  *bnAb = (const float*)d_in[9];
    const float* bnAm = (const float*)d_in[10], *bnAv = (const float*)d_in[11];
    const float* gcnMw = (const float*)d_in[12], *gcnMb = (const float*)d_in[13];
    const float* bnMg = (const float*)d_in[14], *bnMb = (const float*)d_in[15];
    const float* bnMm = (const float*)d_in[16], *bnMv = (const float*)d_in[17];
    const float* mu   = (const float*)d_in[18], *tau  = (const float*)d_in[19];
    const float* prune_w = (const float*)d_in[20], *prune_b = (const float*)d_in[21];
    const float* rewire_w = (const float*)d_in[22], *rewire_b = (const float*)d_in[23];
    const float* pool_w = (const float*)d_in[24], *pool_b = (const float*)d_in[25];
    float* out = (float*)d_out;

    float *Wx, *XWM, *h, *HW, *S, *T, *Cpart, *Ac;
    cudaGetSymbolAddress((void**)&Wx, g_Wx);
    cudaGetSymbolAddress((void**)&XWM, g_XWM);
    cudaGetSymbolAddress((void**)&h, g_h);
    cudaGetSymbolAddress((void**)&HW, g_HW);
    cudaGetSymbolAddress((void**)&S, g_S);
    cudaGetSymbolAddress((void**)&T, g_T);
    cudaGetSymbolAddress((void**)&Cpart, g_Cpart);
    cudaGetSymbolAddress((void**)&Ac, g_Ac);

    k_phase1<<<1536, 256>>>(A_in, A_motif, x, gat_w, gcnMw, Wx, XWM);
    k_phase2<<<1552, 256>>>(coords, gat_as, gat_ad);
    k_aggregate<<<NN + 32, 128>>>(gat_b, bnAg, bnAb, bnAm, bnAv, gcnMb,
                                  bnMg, bnMb, bnMm, bnMv, mu, prune_w, rewire_w);
    k_candidates<<<512, 256>>>(coords, A_in, rewire_w, rewire_b, tau);
    k_refined<<<512, 256>>>(prune_w, prune_b, tau);
    k_gemm<<<dim3(CL / 64, NN / 64), 256>>>(h, pool_w, HW, NN, CL, FH);
    k_pool<<<NN, 128>>>(pool_b);
    k_spmmT<<<NN, 128>>>();
    k_gemm_tn<<<dim3(FH / 64, 128 / 64, KS), 256>>>(S, h, Cpart, 128, FH, NN);
    k_reduce_part<<<(128 * FH + 255) / 256, 256>>>(out, 128 * FH);
    k_gemm_tn<<<dim3(CL / 64, 128 / 64, KS), 256>>>(S, T, Cpart, 128, CL, NN);
    k_reduce_part<<<(128 * CL + 255) / 256, 256>>>(Ac, 128 * CL);
    k_coarse_thr<<<16, 256>>>();
    k_coarse_write<<<64, 256>>>(out + 128 * FH);
}

// round 16
// speedup vs baseline: 1.2820x; 1.0529x over previous
#include <cuda_runtime.h>
#include <math.h>

#define NN 4096
#define FH 256
#define CL 128
#define MAXDEG 128
#define MAXM 128
#define MAXC 64
#define MAXR (MAXDEG + MAXC)
#define CELLCAP 32
#define NEGINF (-1e9f)
#define KS 16

// ---------- scratch ----------
__device__ int   g_adj_idx[NN * MAXDEG];
__device__ int   g_adj_cnt[NN];
__device__ int   g_mf_idx[NN * MAXM];
__device__ float g_mf_val[NN * MAXM];
__device__ int   g_mf_cnt[NN];
__device__ float g_m_thr[NN];
__device__ int   g_m_idx[NN * MAXM];
__device__ float g_m_val[NN * MAXM];
__device__ int   g_m_cnt[NN];
__device__ float g_dinvM[NN];
__device__ float g_Wx[NN * FH];
__device__ float g_XWM[NN * FH];
__device__ float g_as[NN * 2];
__device__ float g_ad[NN * 2];
__device__ float g_h[NN * FH];
__device__ float g_pu[NN], g_pv[NN], g_ru[NN], g_rv[NN];
__device__ int   g_cell_cnt[4096];
__device__ int   g_cell_nodes[4096 * CELLCAP];
__device__ int   g_cand_idx[NN * MAXC];
__device__ float g_cand_z[NN * MAXC];
__device__ int   g_cand_cnt[NN];
__device__ float g_thr2[NN];
__device__ int   g_ref_idx[NN * MAXR];
__device__ float g_ref_w[NN * MAXR];
__device__ int   g_ref_cnt[NN];
__device__ float g_dinv_ref[NN];
__device__ float g_HW[NN * CL];
__device__ float g_S[NN * CL];
__device__ float g_T[NN * CL];
__device__ float g_Cpart[KS * 128 * 256];
__device__ float g_Ac[128 * 128];
__device__ float g_cthr[128];

// ---------- helpers ----------
__device__ __forceinline__ float hc_gate(float logit, float tau) {
    float t = fmaxf(tau, 0.1f);
    float s = 1.f / (1.f + expf(-logit / t));
    s = s * 1.2f - 0.1f;
    return fminf(fmaxf(s, 0.f), 1.f);
}
__device__ __forceinline__ float mhat_bs(int i, int j) {
    int c = g_m_cnt[i];
    const int* ip = &g_m_idx[i * MAXM];
    int lo = 0, hi = c;
    while (lo < hi) { int mid = (lo + hi) >> 1; if (ip[mid] < j) lo = mid + 1; else hi = mid; }
    return (lo < c && ip[lo] == j) ? g_m_val[i * MAXM + lo] : 0.f;
}

// ---------- phase-1 device bodies ----------
__device__ void adj_row_body(const float* __restrict__ A, int gw, int lane) {
    const float4* row = (const float4*)(A + (size_t)gw * NN);
    unsigned below = (1u << lane) - 1;
    int c = 0;
    #pragma unroll 4
    for (int b = 0; b < NN / 4; b += 32) {
        float4 v = row[b + lane];
        bool p0 = v.x > 0.f, p1 = v.y > 0.f, p2 = v.z > 0.f, p3 = v.w > 0.f;
        unsigned m0 = __ballot_sync(~0u, p0), m1 = __ballot_sync(~0u, p1);
        unsigned m2 = __ballot_sync(~0u, p2), m3 = __ballot_sync(~0u, p3);
        int base = c + __popc(m0 & below) + __popc(m1 & below) + __popc(m2 & below) + __popc(m3 & below);
        int col = (b + lane) * 4, o = 0;
        if (p0 && base + o < MAXDEG) g_adj_idx[gw * MAXDEG + base + o] = col;
        if (p0) o++;
        if (p1 && base + o < MAXDEG) g_adj_idx[gw * MAXDEG + base + o] = col + 1;
        if (p1) o++;
        if (p2 && base + o < MAXDEG) g_adj_idx[gw * MAXDEG + base + o] = col + 2;
        if (p2) o++;
        if (p3 && base + o < MAXDEG) g_adj_idx[gw * MAXDEG + base + o] = col + 3;
        c += __popc(m0) + __popc(m1) + __popc(m2) + __popc(m3);
    }
    if (lane == 0) g_adj_cnt[gw] = min(c, MAXDEG);
}

__device__ void motif_row_body(const float* __restrict__ A, int gw, int lane) {
    const float4* row = (const float4*)(A + (size_t)gw * NN);
    unsigned below = (1u << lane) - 1;
    int c = 0;
    #pragma unroll 4
    for (int b = 0; b < NN / 4; b += 32) {
        float4 v = row[b + lane];
        bool p0 = v.x > 0.f, p1 = v.y > 0.f, p2 = v.z > 0.f, p3 = v.w > 0.f;
        unsigned m0 = __ballot_sync(~0u, p0), m1 = __ballot_sync(~0u, p1);
        unsigned m2 = __ballot_sync(~0u, p2), m3 = __ballot_sync(~0u, p3);
        int base = c + __popc(m0 & below) + __popc(m1 & below) + __popc(m2 & below) + __popc(m3 & below);
        int col = (b + lane) * 4, o = 0;
        if (p0 && base + o < MAXM) { g_mf_idx[gw * MAXM + base + o] = col;     g_mf_val[gw * MAXM + base + o] = v.x; }
        if (p0) o++;
        if (p1 && base + o < MAXM) { g_mf_idx[gw * MAXM + base + o] = col + 1; g_mf_val[gw * MAXM + base + o] = v.y; }
        if (p1) o++;
        if (p2 && base + o < MAXM) { g_mf_idx[gw * MAXM + base + o] = col + 2; g_mf_val[gw * MAXM + base + o] = v.z; }
        if (p2) o++;
        if (p3 && base + o < MAXM) { g_mf_idx[gw * MAXM + base + o] = col + 3; g_mf_val[gw * MAXM + base + o] = v.w; }
        c += __popc(m0) + __popc(m1) + __popc(m2) + __popc(m3);
    }
    c = min(c, MAXM);
    __syncwarp();
    float vv[4];
    #pragma unroll
    for (int s = 0; s < 4; s++) {
        int t = s * 32 + lane;
        vv[s] = (t < c) ? g_mf_val[gw * MAXM + t] : -2.f;
    }
    float thr = 0.f;
    if (c > 8) {
        for (int r = 0; r < 8; r++) {
            float lm = fmaxf(fmaxf(vv[0], vv[1]), fmaxf(vv[2], vv[3]));
            float wm = lm;
            for (int o = 16; o; o >>= 1) wm = fmaxf(wm, __shfl_xor_sync(~0u, wm, o));
            unsigned who = __ballot_sync(~0u, lm == wm);
            if (lane == (__ffs(who) - 1)) {
                #pragma unroll
                for (int s = 0; s < 4; s++) if (vv[s] == wm) { vv[s] = -2.f; break; }
            }
            thr = wm;
        }
    }
    if (lane == 0) { g_mf_cnt[gw] = c; g_m_thr[gw] = thr; }
}

// R9 double-buffered 64x64 GEMM tile body
__device__ void gemm_tile_body(const float* __restrict__ A, const float* __restrict__ B,
                               float* __restrict__ C, int M, int Nc, int K,
                               int bm, int bn, float (*As)[16][65], float (*Bs)[16][65]) {
    int tid = threadIdx.x, tr = tid >> 4, tc = tid & 15;
    int am[4], ak[4], bk[4], bnn[4];
    float ra[4], rb[4];
    #pragma unroll
    for (int l = 0; l < 4; l++) {
        int e = tid + l * 256;
        am[l] = e >> 4; ak[l] = e & 15;
        bk[l] = e >> 6; bnn[l] = e & 63;
    }
    int nP = K / 16;
    #pragma unroll
    for (int l = 0; l < 4; l++) {
        ra[l] = A[(size_t)(bm + am[l]) * K + ak[l]];
        rb[l] = B[(size_t)bk[l] * Nc + bn + bnn[l]];
    }
    #pragma unroll
    for (int l = 0; l < 4; l++) {
        As[0][ak[l]][am[l]] = ra[l];
        Bs[0][bk[l]][bnn[l]] = rb[l];
    }
    __syncthreads();
    float acc[4][4] = {};
    for (int p = 0; p < nP; p++) {
        int cur = p & 1;
        if (p + 1 < nP) {
            int k0 = (p + 1) * 16;
            #pragma unroll
            for (int l = 0; l < 4; l++) {
                ra[l] = A[(size_t)(bm + am[l]) * K + k0 + ak[l]];
                rb[l] = B[(size_t)(k0 + bk[l]) * Nc + bn + bnn[l]];
            }
        }
        #pragma unroll
        for (int kk = 0; kk < 16; kk++) {
            float a[4], b[4];
            #pragma unroll
            for (int r = 0; r < 4; r++) a[r] = As[cur][kk][tr * 4 + r];
            #pragma unroll
            for (int c = 0; c < 4; c++) b[c] = Bs[cur][kk][tc * 4 + c];
            #pragma unroll
            for (int r = 0; r < 4; r++)
                #pragma unroll
                for (int c = 0; c < 4; c++) acc[r][c] += a[r] * b[c];
        }
        if (p + 1 < nP) {
            #pragma unroll
            for (int l = 0; l < 4; l++) {
                As[cur ^ 1][ak[l]][am[l]] = ra[l];
                Bs[cur ^ 1][bk[l]][bnn[l]] = rb[l];
            }
        }
        __syncthreads();
    }
    #pragma unroll
    for (int r = 0; r < 4; r++)
        #pragma unroll
        for (int c = 0; c < 4; c++)
            C[(size_t)(bm + tr * 4 + r) * Nc + bn + tc * 4 + c] = acc[r][c];
}

// ---------- Phase 1 fused ----------
__global__ void k_phase1(const float* __restrict__ A_in, const float* __restrict__ A_motif,
                         const float* __restrict__ x, const float* __restrict__ gat_w,
                         const float* __restrict__ gcnMw, float* __restrict__ Wx,
                         float* __restrict__ XWM) {
    __shared__ float As[2][16][65], Bs[2][16][65];
    int b = blockIdx.x;
    int lane = threadIdx.x & 31, wid = threadIdx.x >> 5;
    if (b < 512) {
        if (b < 16) g_cell_cnt[b * 256 + threadIdx.x] = 0;
        adj_row_body(A_in, b * 8 + wid, lane);
    } else if (b < 1024) {
        motif_row_body(A_motif, (b - 512) * 8 + wid, lane);
    } else if (b < 1280) {
        int t = b - 1024;
        gemm_tile_body(x, gat_w, Wx, NN, FH, 128, (t >> 2) * 64, (t & 3) * 64, As, Bs);
    } else {
        int t = b - 1280;
        gemm_tile_body(x, gcnMw, XWM, NN, FH, 128, (t >> 2) * 64, (t & 3) * 64, As, Bs);
    }
}

// ---------- Phase 2 fused: mfilter | attn_coef | cells insert ----------
__global__ void k_phase2(const float* __restrict__ coords,
                         const float* __restrict__ asw, const float* __restrict__ adw) {
    int b = blockIdx.x;
    if (b < 512) {
        int gw = b * 8 + (threadIdx.x >> 5), lane = threadIdx.x & 31;
        int i = gw, cnt = g_mf_cnt[i], out = 0;
        float thrI = g_m_thr[i], wsum = 0.f;
        for (int base = 0; base < cnt; base += 32) {
            int t = base + lane; bool ok = t < cnt; int j = 0; float v = 0.f;
            if (ok) {
                j = g_mf_idx[i * MAXM + t]; v = g_mf_val[i * MAXM + t];
                ok = (v >= thrI) || (v >= g_m_thr[j]);
            }
            unsigned m = __ballot_sync(0xffffffffu, ok);
            int pos = out + __popc(m & ((1u << lane) - 1));
            if (ok) { g_m_idx[i * MAXM + pos] = j; g_m_val[i * MAXM + pos] = v; wsum += v; }
            out += __popc(m);
        }
        for (int o = 16; o; o >>= 1) wsum += __shfl_down_sync(0xffffffffu, wsum, o);
        if (lane == 0) { g_m_cnt[i] = out; g_dinvM[i] = (wsum > 0.f) ? rsqrtf(wsum) : 0.f; }
    } else if (b < 1536) {
        int gw = (b - 512) * 8 + (threadIdx.x >> 5), lane = threadIdx.x & 31;
        int node = gw >> 1, hh = gw & 1;
        const float* row = g_Wx + (size_t)node * FH + hh * 128;
        float s = 0.f, d = 0.f;
        for (int k = lane; k < 128; k += 32) {
            float w = row[k];
            s += w * asw[hh * 128 + k];
            d += w * adw[hh * 128 + k];
        }
        for (int o = 16; o; o >>= 1) {
            s += __shfl_down_sync(0xffffffffu, s, o);
            d += __shfl_down_sync(0xffffffffu, d, o);
        }
        if (lane == 0) { g_as[node * 2 + hh] = s; g_ad[node * 2 + hh] = d; }
    } else {
        int i = (b - 1536) * 256 + threadIdx.x;
        int cx = (int)coords[2 * i], cy = (int)coords[2 * i + 1];
        int p = atomicAdd(&g_cell_cnt[cx * 64 + cy], 1);
        if (p < CELLCAP) g_cell_nodes[(cx * 64 + cy) * CELLCAP + p] = i;
    }
}

__global__ void k_gemm(const float* __restrict__ A, const float* __restrict__ B,
                       float* __restrict__ C, int M, int Nc, int K) {
    __shared__ float As[2][16][65], Bs[2][16][65];
    gemm_tile_body(A, B, C, M, Nc, K, blockIdx.y * 64, blockIdx.x * 64, As, Bs);
}

__global__ void k_gemm_tn(const float* __restrict__ A, const float* __restrict__ B,
                          float* __restrict__ Cpart, int M, int Nc, int K) {
    __shared__ float As[2][16][65], Bs[2][16][65];
    int ks = blockIdx.z, kbeg = ks * (K / KS);
    int nP = (K / KS) / 16;
    int bm = blockIdx.y * 64, bn = blockIdx.x * 64;
    int tid = threadIdx.x, tr = tid >> 4, tc = tid & 15;
    int lk[4], ln[4];
    float ra[4], rb[4];
    #pragma unroll
    for (int l = 0; l < 4; l++) {
        int e = tid + l * 256;
        lk[l] = e >> 6; ln[l] = e & 63;
    }
    #pragma unroll
    for (int l = 0; l < 4; l++) {
        ra[l] = A[(size_t)(kbeg + lk[l]) * M + bm + ln[l]];
        rb[l] = B[(size_t)(kbeg + lk[l]) * Nc + bn + ln[l]];
    }
    #pragma unroll
    for (int l = 0; l < 4; l++) {
        As[0][lk[l]][ln[l]] = ra[l];
        Bs[0][lk[l]][ln[l]] = rb[l];
    }
    __syncthreads();
    float acc[4][4] = {};
    for (int p = 0; p < nP; p++) {
        int cur = p & 1;
        if (p + 1 < nP) {
            int k0 = kbeg + (p + 1) * 16;
            #pragma unroll
            for (int l = 0; l < 4; l++) {
                ra[l] = A[(size_t)(k0 + lk[l]) * M + bm + ln[l]];
                rb[l] = B[(size_t)(k0 + lk[l]) * Nc + bn + ln[l]];
            }
        }
        #pragma unroll
        for (int kk = 0; kk < 16; kk++) {
            float a[4], b[4];
            #pragma unroll
            for (int r = 0; r < 4; r++) a[r] = As[cur][kk][tr * 4 + r];
            #pragma unroll
            for (int c = 0; c < 4; c++) b[c] = Bs[cur][kk][tc * 4 + c];
            #pragma unroll
            for (int r = 0; r < 4; r++)
                #pragma unroll
                for (int c = 0; c < 4; c++) acc[r][c] += a[r] * b[c];
        }
        if (p + 1 < nP) {
            #pragma unroll
            for (int l = 0; l < 4; l++) {
                As[cur ^ 1][lk[l]][ln[l]] = ra[l];
                Bs[cur ^ 1][lk[l]][ln[l]] = rb[l];
            }
        }
        __syncthreads();
    }
    float* Cp = Cpart + (size_t)ks * M * Nc;
    #pragma unroll
    for (int r = 0; r < 4; r++)
        #pragma unroll
        for (int c = 0; c < 4; c++)
            Cp[(size_t)(bm + tr * 4 + r) * Nc + bn + tc * 4 + c] = acc[r][c];
}

__global__ void k_reduce_part(float* __restrict__ dst, int MN) {
    int t = blockIdx.x * blockDim.x + threadIdx.x;
    if (t >= MN) return;
    float s = 0.f;
    for (int z = 0; z < KS; z++) s += g_Cpart[(size_t)z * MN + t];
    dst[t] = s;
}

// ---------- aggregate (128 thr, 2 dims/thr, reg-capped) + cells_sort tail ----------
__global__ void __launch_bounds__(128, 16) k_aggregate(
    const float* __restrict__ gat_b,
    const float* __restrict__ bnAg, const float* __restrict__ bnAb,
    const float* __restrict__ bnAm, const float* __restrict__ bnAv,
    const float* __restrict__ gcnMb,
    const float* __restrict__ bnMg, const float* __restrict__ bnMb,
    const float* __restrict__ bnMm, const float* __restrict__ bnMv,
    const float* __restrict__ mu_, const float* __restrict__ prune_w,
    const float* __restrict__ rewire_w)
{
    if (blockIdx.x >= NN) {
        int c = (blockIdx.x - NN) * 128 + threadIdx.x;
        int n = min(g_cell_cnt[c], CELLCAP);
        int* a = &g_cell_nodes[c * CELLCAP];
        for (int x = 1; x < n; x++) {
            int v = a[x], y = x - 1;
            while (y >= 0 && a[y] > v) { a[y + 1] = a[y]; y--; }
            a[y + 1] = v;
        }
        return;
    }
    __shared__ float se0[MAXDEG + 1], se1[MAXDEG + 1];
    __shared__ int   sj[MAXDEG + 1];
    __shared__ float2 ps0[MAXDEG + 1], ps1[MAXDEG + 1];
    __shared__ float2 psM[MAXM];
    __shared__ float rA[128], rB[128];
    int i = blockIdx.x, tid = threadIdx.x;
    int deg = g_adj_cnt[i], tot = deg + 1;
    float ad0 = g_ad[2 * i], ad1 = g_ad[2 * i + 1];
    for (int t = tid; t < tot; t += 128) {
        int j = (t < deg) ? g_adj_idx[i * MAXDEG + t] : i;
        sj[t] = j;
        float e0 = ad0 + g_as[2 * j], e1 = ad1 + g_as[2 * j + 1];
        se0[t] = (e0 > 0.f) ? e0 : 0.2f * e0;
        se1[t] = (e1 > 0.f) ? e1 : 0.2f * e1;
    }
    int mc = g_m_cnt[i];
    for (int t = tid; t < mc; t += 128) {
        int j = g_m_idx[i * MAXM + t];
        psM[t] = make_float2(g_m_val[i * MAXM + t] * g_dinvM[j], __int_as_float(j));
    }
    __syncthreads();
    float lm0 = -3.4e38f, lm1 = -3.4e38f;
    for (int t = tid; t < tot; t += 128) { lm0 = fmaxf(lm0, se0[t]); lm1 = fmaxf(lm1, se1[t]); }
    rA[tid] = lm0; rB[tid] = lm1; __syncthreads();
    for (int s = 64; s > 0; s >>= 1) {
        if (tid < s) { rA[tid] = fmaxf(rA[tid], rA[tid + s]); rB[tid] = fmaxf(rB[tid], rB[tid + s]); }
        __syncthreads();
    }
    float M0 = rA[0], M1 = rB[0]; __syncthreads();
    float ls0 = 0.f, ls1 = 0.f;
    for (int t = tid; t < tot; t += 128) {
        float jf = __int_as_float(sj[t]);
        float e0 = expf(se0[t] - M0); ps0[t] = make_float2(e0, jf); ls0 += e0;
        float e1 = expf(se1[t] - M1); ps1[t] = make_float2(e1, jf); ls1 += e1;
    }
    rA[tid] = ls0; rB[tid] = ls1; __syncthreads();
    for (int s = 64; s > 0; s >>= 1) {
        if (tid < s) { rA[tid] += rA[tid + s]; rB[tid] += rB[tid + s]; }
        __syncthreads();
    }
    float D0 = rA[0], D1 = rB[0]; __syncthreads();

    int head = tid >> 6;
    float Dh = head ? D1 : D0;
    const float2* ps = head ? ps1 : ps0;
    const float2* W2 = (const float2*)g_Wx;
    const float2* X2 = (const float2*)g_XWM;
    float2 accA = make_float2(0.f, 0.f);
    #pragma unroll 4
    for (int k = 0; k < tot; k++) {
        float2 p = ps[k];
        float2 v = W2[(size_t)__float_as_int(p.y) * (FH / 2) + tid];
        accA.x += p.x * v.x;
        accA.y += p.x * v.y;
    }
    const float2* gbv = (const float2*)gat_b;
    const float2* Amv = (const float2*)bnAm; const float2* Agv = (const float2*)bnAg;
    const float2* Avv = (const float2*)bnAv; const float2* Abv = (const float2*)bnAb;
    float2 gb = gbv[tid], Am = Amv[tid], Ag = Agv[tid], Av = Avv[tid], Ab = Abv[tid];
    float hA0 = accA.x / Dh + gb.x, hA1 = accA.y / Dh + gb.y;
    hA0 = (hA0 - Am.x) * Ag.x * rsqrtf(Av.x + 1e-5f) + Ab.x;
    hA1 = (hA1 - Am.y) * Ag.y * rsqrtf(Av.y + 1e-5f) + Ab.y;
    hA0 = (hA0 > 0.f) ? hA0 : expm1f(hA0);
    hA1 = (hA1 > 0.f) ? hA1 : expm1f(hA1);

    float2 accM = make_float2(0.f, 0.f);
    #pragma unroll 4
    for (int k = 0; k < mc; k++) {
        float2 p = psM[k];
        float2 v = X2[(size_t)__float_as_int(p.y) * (FH / 2) + tid];
        accM.x += p.x * v.x;
        accM.y += p.x * v.y;
    }
    const float2* Mbv = (const float2*)gcnMb;
    const float2* Mm = (const float2*)bnMm; const float2* Mg = (const float2*)bnMg;
    const float2* Mv = (const float2*)bnMv; const float2* Mb = (const float2*)bnMb;
    float2 mb = Mbv[tid], mm = Mm[tid], mg = Mg[tid], mv = Mv[tid], mbb = Mb[tid];
    float di = g_dinvM[i];
    float hM0 = di * accM.x + mb.x, hM1 = di * accM.y + mb.y;
    hM0 = (hM0 - mm.x) * mg.x * rsqrtf(mv.x + 1e-5f) + mbb.x;
    hM1 = (hM1 - mm.y) * mg.y * rsqrtf(mv.y + 1e-5f) + mbb.y;
    hM0 = (hM0 > 0.f) ? hM0 : expm1f(hM0);
    hM1 = (hM1 > 0.f) ? hM1 : expm1f(hM1);

    float mu = mu_[0];
    float sp = (mu > 20.f) ? mu : log1pf(expf(mu));
    float hv0 = hA0 + sp * hM0, hv1 = hA1 + sp * hM1;
    ((float2*)g_h)[(size_t)i * (FH / 2) + tid] = make_float2(hv0, hv1);

    const float2* pw = (const float2*)prune_w;
    const float2* rw = (const float2*)rewire_w;
    float2 p0 = pw[tid], p1 = pw[128 + tid];
    float2 r0v = rw[tid], r1v = rw[128 + tid];
    rA[tid] = hv0 * p0.x + hv1 * p0.y;
    rB[tid] = hv0 * p1.x + hv1 * p1.y;
    __syncthreads();
    for (int s = 64; s > 0; s >>= 1) {
        if (tid < s) { rA[tid] += rA[tid + s]; rB[tid] += rB[tid + s]; }
        __syncthreads();
    }
    float r0 = rA[0], r1 = rB[0]; __syncthreads();
    rA[tid] = hv0 * r0v.x + hv1 * r0v.y;
    rB[tid] = hv0 * r1v.x + hv1 * r1v.y;
    __syncthreads();
    for (int s = 64; s > 0; s >>= 1) {
        if (tid < s) { rA[tid] += rA[tid + s]; rB[tid] += rB[tid + s]; }
        __syncthreads();
    }
    if (tid == 0) { g_pu[i] = r0; g_pv[i] = r1; g_ru[i] = rA[0]; g_rv[i] = rB[0]; }
}

// ---------- candidates: flattened rank->(cell,offset) mapping, parallel probes ----------
__global__ void k_candidates(const float* __restrict__ coords, const float* __restrict__ A_in,
                             const float* __restrict__ rw, const float* __restrict__ rb_,
                             const float* __restrict__ tau_) {
    int gw = (blockIdx.x * blockDim.x + threadIdx.x) >> 5;
    int lane = threadIdx.x & 31;
    if (gw >= NN) return;
    int i = gw;
    float tau = tau_[0], rw2 = rw[512], rb = rb_[0];
    int cx = (int)coords[2 * i], cy = (int)coords[2 * i + 1];
    const int ox[12] = {-2,-1,-1,-1, 0, 0, 0, 0, 1, 1, 1, 2};
    const int oy[12] = { 0,-1, 0, 1,-2,-1, 1, 2,-1, 0, 1, 0};
    // lane o<12 owns cell o's (id, count)
    int mycell = -1, mycc = 0;
    if (lane < 12) {
        int nx = cx + ox[lane], ny = cy + oy[lane];
        if (nx >= 0 && nx < 64 && ny >= 0 && ny < 64) {
            mycell = nx * 64 + ny;
            mycc = min(g_cell_cnt[mycell], CELLCAP);
        }
    }
    int tot = mycc;
    for (int o = 16; o; o >>= 1) tot += __shfl_xor_sync(~0u, tot, o);
    float rui = g_ru[i], rvi = g_rv[i];
    int cnt = 0;
    float m1 = NEGINF, m2 = NEGINF;
    for (int base = 0; base < tot; base += 32) {
        int r = base + lane;
        int cell = -1, off = 0, rr = r;
        #pragma unroll
        for (int o = 0; o < 12; o++) {
            int cc_o = __shfl_sync(~0u, mycc, o);
            int cell_o = __shfl_sync(~0u, mycell, o);
            if (rr >= 0 && rr < cc_o) { cell = cell_o; off = rr; }
            rr -= cc_o;
        }
        bool ok = (r < tot) && (cell >= 0);
        int j = 0; float z = 0.f;
        if (ok) {
            j = g_cell_nodes[cell * CELLCAP + off];
            ok = A_in[(size_t)i * NN + j] < 1e-6f;
        }
        if (ok) {
            float ruv = (i < j) ? (rui + g_rv[j]) : (g_ru[j] + rvi);
            z = hc_gate(ruv + rw2 * mhat_bs(i, j) + rb, tau);
            if (z > m1) { m2 = m1; m1 = z; } else if (z > m2) { m2 = z; }
        }
        unsigned m = __ballot_sync(~0u, ok);
        int pos = cnt + __popc(m & ((1u << lane) - 1));
        if (ok && pos < MAXC) { g_cand_idx[i * MAXC + pos] = j; g_cand_z[i * MAXC + pos] = z; }
        cnt += __popc(m);
    }
    for (int o = 16; o; o >>= 1) {
        float om1 = __shfl_xor_sync(~0u, m1, o);
        float om2 = __shfl_xor_sync(~0u, m2, o);
        float hi = fmaxf(m1, om1), lo = fminf(m1, om1);
        m2 = fmaxf(lo, fmaxf(m2, om2));
        m1 = hi;
    }
    if (lane == 0) { g_cand_cnt[i] = min(cnt, MAXC); g_thr2[i] = m2; }
}

__global__ void k_refined(const float* __restrict__ prune_w, const float* __restrict__ prune_b,
                          const float* __restrict__ tau_) {
    int gw = (blockIdx.x * blockDim.x + threadIdx.x) >> 5;
    int lane = threadIdx.x & 31;
    if (gw >= NN) return;
    int i = gw;
    float tau = tau_[0], pw2 = prune_w[512], pb = prune_b[0];
    int deg = g_adj_cnt[i];
    float wsum = 0.f;
    for (int t = lane; t < deg; t += 32) {
        int j = g_adj_idx[i * MAXDEG + t];
        float puv = (i < j) ? (g_pu[i] + g_pv[j]) : (g_pu[j] + g_pv[i]);
        float z = hc_gate(puv + pw2 * mhat_bs(i, j) + pb, tau);
        g_ref_idx[i * MAXR + t] = j;
        g_ref_w[i * MAXR + t] = z;
        wsum += z;
    }
    int cnt = deg;
    float thrI = g_thr2[i];
    int cc = g_cand_cnt[i];
    for (int base = 0; base < cc; base += 32) {
        int t = base + lane; bool ok = false; int j = 0; float z = 0.f;
        if (t < cc) {
            j = g_cand_idx[i * MAXC + t]; z = g_cand_z[i * MAXC + t];
            ok = (z >= thrI) || (z >= g_thr2[j]);
        }
        unsigned m = __ballot_sync(0xffffffffu, ok);
        int pos = cnt + __popc(m & ((1u << lane) - 1));
        if (ok) { g_ref_idx[i * MAXR + pos] = j; g_ref_w[i * MAXR + pos] = 0.5f * z; wsum += 0.5f * z; }
        cnt += __popc(m);
    }
    for (int o = 16; o; o >>= 1) wsum += __shfl_down_sync(0xffffffffu, wsum, o);
    if (lane == 0) { g_ref_cnt[i] = cnt; g_dinv_ref[i] = rsqrtf(wsum + 1.f); }
}

__global__ void k_pool(const float* __restrict__ pool_b) {
    __shared__ float red[128];
    int i = blockIdx.x, c = threadIdx.x;
    float di = g_dinv_ref[i];
    int cnt = g_ref_cnt[i];
    float acc = di * g_HW[(size_t)i * CL + c];
    #pragma unroll 4
    for (int t = 0; t < cnt; t++) {
        int j = g_ref_idx[i * MAXR + t];
        acc += g_ref_w[i * MAXR + t] * g_dinv_ref[j] * g_HW[(size_t)j * CL + c];
    }
    float pre = di * acc + pool_b[c];
    red[c] = pre; __syncthreads();
    for (int s = 64; s > 0; s >>= 1) { if (c < s) red[c] = fmaxf(red[c], red[c + s]); __syncthreads(); }
    float mx = red[0]; __syncthreads();
    float e = expf(pre - mx);
    red[c] = e; __syncthreads();
    for (int s = 64; s > 0; s >>= 1) { if (c < s) red[c] += red[c + s]; __syncthreads(); }
    g_S[(size_t)i * CL + c] = e / red[0];
}

__global__ void k_spmmT() {
    int i = blockIdx.x, c = threadIdx.x;
    int cnt = g_ref_cnt[i];
    float acc = 0.f;
    #pragma unroll 4
    for (int t = 0; t < cnt; t++)
        acc += g_ref_w[i * MAXR + t] * g_S[(size_t)g_ref_idx[i * MAXR + t] * CL + c];
    g_T[(size_t)i * CL + c] = acc;
}

__global__ void k_coarse_thr() {
    int gw = (blockIdx.x * blockDim.x + threadIdx.x) >> 5;
    int lane = threadIdx.x & 31;
    if (gw >= 128) return;
    float vv[4];
    #pragma unroll
    for (int s = 0; s < 4; s++) {
        int j = s * 32 + lane;
        vv[s] = (j == gw) ? 0.f : g_Ac[gw * 128 + j];
    }
    float thr = 0.f;
    for (int r = 0; r < 8; r++) {
        float lm = fmaxf(fmaxf(vv[0], vv[1]), fmaxf(vv[2], vv[3]));
        float wm = lm;
        for (int o = 16; o; o >>= 1) wm = fmaxf(wm, __shfl_xor_sync(~0u, wm, o));
        unsigned who = __ballot_sync(~0u, lm == wm);
        if (lane == (__ffs(who) - 1)) {
            #pragma unroll
            for (int s = 0; s < 4; s++) if (vv[s] == wm) { vv[s] = -1e30f; break; }
        }
        thr = wm;
    }
    if (lane == 0) g_cthr[gw] = thr;
}

__global__ void k_coarse_write(float* __restrict__ out) {
    int t = blockIdx.x * blockDim.x + threadIdx.x;
    if (t >= 128 * 128) return;
    int i = t >> 7, j = t & 127;
    if (i == j) { out[t] = 0.f; return; }
    float vij = g_Ac[i * 128 + j];
    float vji = g_Ac[j * 128 + i];
    float a = (vij >= g_cthr[i]) ? vij : 0.f;
    float b = (vji >= g_cthr[j]) ? vji : 0.f;
    out[t] = fmaxf(a, b);
}

// ---------- host ----------
extern "C" void kernel_launch(void* const* d_in, const int* in_sizes, int n_in,
                              void* d_out, int out_size) {
    const float* x       = (const float*)d_in[0];
    const float* A_in    = (const float*)d_in[1];
    const float* A_motif = (const float*)d_in[2];
    const float* coords  = (const float*)d_in[3];
    const float* gat_w   = (const float*)d_in[4];
    const float* gat_as  = (const float*)d_in[5];
    const float* gat_ad  = (const float*)d_in[6];
    const float* gat_b   = (const float*)d_in[7];
    const float* bnAg = (const float*)d_in[8],  *bnAb = (const float*)d_in[9];
    const float* bnAm = (const float*)d_in[10], *bnAv = (const float*)d_in[11];
    const float* gcnMw = (const float*)d_in[12], *gcnMb = (const float*)d_in[13];
    const float* bnMg = (const float*)d_in[14], *bnMb = (const float*)d_in[15];
    const float* bnMm = (const float*)d_in[16], *bnMv = (const float*)d_in[17];
    const float* mu   = (const float*)d_in[18], *tau  = (const float*)d_in[19];
    const float* prune_w = (const float*)d_in[20], *prune_b = (const float*)d_in[21];
    const float* rewire_w = (const float*)d_in[22], *rewire_b = (const float*)d_in[23];
    const float* pool_w = (const float*)d_in[24], *pool_b = (const float*)d_in[25];
    float* out = (float*)d_out;

    float *Wx, *XWM, *h, *HW, *S, *T, *Cpart, *Ac;
    cudaGetSymbolAddress((void**)&Wx, g_Wx);
    cudaGetSymbolAddress((void**)&XWM, g_XWM);
    cudaGetSymbolAddress((void**)&h, g_h);
    cudaGetSymbolAddress((void**)&HW, g_HW);
    cudaGetSymbolAddress((void**)&S, g_S);
    cudaGetSymbolAddress((void**)&T, g_T);
    cudaGetSymbolAddress((void**)&Cpart, g_Cpart);
    cudaGetSymbolAddress((void**)&Ac, g_Ac);

    k_phase1<<<1536, 256>>>(A_in, A_motif, x, gat_w, gcnMw, Wx, XWM);
    k_phase2<<<1552, 256>>>(coords, gat_as, gat_ad);
    k_aggregate<<<NN + 32, 128>>>(gat_b, bnAg, bnAb, bnAm, bnAv, gcnMb,
                                  bnMg, bnMb, bnMm, bnMv, mu, prune_w, rewire_w);
    k_candidates<<<512, 256>>>(coords, A_in, rewire_w, rewire_b, tau);
    k_refined<<<512, 256>>>(prune_w, prune_b, tau);
    k_gemm<<<dim3(CL / 64, NN / 64), 256>>>(h, pool_w, HW, NN, CL, FH);
    k_pool<<<NN, 128>>>(pool_b);
    k_spmmT<<<NN, 128>>>();
    k_gemm_tn<<<dim3(FH / 64, 128 / 64, KS), 256>>>(S, h, Cpart, 128, FH, NN);
    k_reduce_part<<<(128 * FH + 255) / 256, 256>>>(out, 128 * FH);
    k_gemm_tn<<<dim3(CL / 64, 128 / 64, KS), 256>>>(S, T, Cpart, 128, CL, NN);
    k_reduce_part<<<(128 * CL + 255) / 256, 256>>>(Ac, 128 * CL);
    k_coarse_thr<<<16, 256>>>();
    k_coarse_write<<<64, 256>>>(out + 128 * FH);
}

// round 17
// speedup vs baseline: 1.2929x; 1.0085x over previous
#include <cuda_runtime.h>
#include <math.h>

#define NN 4096
#define FH 256
#define CL 128
#define MAXDEG 128
#define MAXM 128
#define MAXC 64
#define MAXR (MAXDEG + MAXC)
#define CELLCAP 32
#define NEGINF (-1e9f)
#define KS 16

// ---------- scratch ----------
__device__ int   g_adj_idx[NN * MAXDEG];
__device__ int   g_adj_cnt[NN];
__device__ int   g_mf_idx[NN * MAXM];
__device__ float g_mf_val[NN * MAXM];
__device__ int   g_mf_cnt[NN];
__device__ float g_m_thr[NN];
__device__ int   g_m_idx[NN * MAXM];
__device__ float g_m_val[NN * MAXM];
__device__ int   g_m_cnt[NN];
__device__ float g_dinvM[NN];
__device__ float g_Wx[NN * FH];
__device__ float g_XWM[NN * FH];
__device__ float g_as[NN * 2];
__device__ float g_ad[NN * 2];
__device__ float g_h[NN * FH];
__device__ float g_pu[NN], g_pv[NN], g_ru[NN], g_rv[NN];
__device__ int   g_cell_cnt[4096];
__device__ int   g_cell_nodes[4096 * CELLCAP];
__device__ int   g_cand_idx[NN * MAXC];
__device__ float g_cand_z[NN * MAXC];
__device__ int   g_cand_cnt[NN];
__device__ float g_thr2[NN];
__device__ int   g_ref_idx[NN * MAXR];
__device__ float g_ref_w[NN * MAXR];
__device__ int   g_ref_cnt[NN];
__device__ float g_dinv_ref[NN];
__device__ float g_HW[NN * CL];
__device__ float g_S[NN * CL];
__device__ float g_T[NN * CL];
__device__ float g_Cpart[KS * 128 * 256];
__device__ float g_Ac[128 * 128];
__device__ float g_cthr[128];

// ---------- helpers ----------
__device__ __forceinline__ float hc_gate(float logit, float tau) {
    float t = fmaxf(tau, 0.1f);
    float s = 1.f / (1.f + expf(-logit / t));
    s = s * 1.2f - 0.1f;
    return fminf(fmaxf(s, 0.f), 1.f);
}

// warp-cooperative M_hat lookup: whole warp serves row i; each lane resolves
// its own j (j=-1 -> no match). Coalesced row load + shuffle broadcast scan.
// Must be called convergently by all 32 lanes.
__device__ __forceinline__ float mhat_warp(int i, int j, int lane) {
    int c = g_m_cnt[i];
    float val = 0.f;
    for (int base = 0; base < c; base += 32) {
        int t = base + lane;
        int idx = (t < c) ? g_m_idx[i * MAXM + t] : -2;
        float v  = (t < c) ? g_m_val[i * MAXM + t] : 0.f;
        int lim = min(c - base, 32);
        for (int o = 0; o < lim; o++) {
            int oi = __shfl_sync(~0u, idx, o);
            float ov = __shfl_sync(~0u, v, o);
            if (oi == j) val = ov;
        }
    }
    return val;
}

// ---------- phase-1 device bodies ----------
__device__ void adj_row_body(const float* __restrict__ A, int gw, int lane) {
    const float4* row = (const float4*)(A + (size_t)gw * NN);
    unsigned below = (1u << lane) - 1;
    int c = 0;
    #pragma unroll 4
    for (int b = 0; b < NN / 4; b += 32) {
        float4 v = row[b + lane];
        bool p0 = v.x > 0.f, p1 = v.y > 0.f, p2 = v.z > 0.f, p3 = v.w > 0.f;
        unsigned m0 = __ballot_sync(~0u, p0), m1 = __ballot_sync(~0u, p1);
        unsigned m2 = __ballot_sync(~0u, p2), m3 = __ballot_sync(~0u, p3);
        int base = c + __popc(m0 & below) + __popc(m1 & below) + __popc(m2 & below) + __popc(m3 & below);
        int col = (b + lane) * 4, o = 0;
        if (p0 && base + o < MAXDEG) g_adj_idx[gw * MAXDEG + base + o] = col;
        if (p0) o++;
        if (p1 && base + o < MAXDEG) g_adj_idx[gw * MAXDEG + base + o] = col + 1;
        if (p1) o++;
        if (p2 && base + o < MAXDEG) g_adj_idx[gw * MAXDEG + base + o] = col + 2;
        if (p2) o++;
        if (p3 && base + o < MAXDEG) g_adj_idx[gw * MAXDEG + base + o] = col + 3;
        c += __popc(m0) + __popc(m1) + __popc(m2) + __popc(m3);
    }
    if (lane == 0) g_adj_cnt[gw] = min(c, MAXDEG);
}

__device__ void motif_row_body(const float* __restrict__ A, int gw, int lane) {
    const float4* row = (const float4*)(A + (size_t)gw * NN);
    unsigned below = (1u << lane) - 1;
    int c = 0;
    #pragma unroll 4
    for (int b = 0; b < NN / 4; b += 32) {
        float4 v = row[b + lane];
        bool p0 = v.x > 0.f, p1 = v.y > 0.f, p2 = v.z > 0.f, p3 = v.w > 0.f;
        unsigned m0 = __ballot_sync(~0u, p0), m1 = __ballot_sync(~0u, p1);
        unsigned m2 = __ballot_sync(~0u, p2), m3 = __ballot_sync(~0u, p3);
        int base = c + __popc(m0 & below) + __popc(m1 & below) + __popc(m2 & below) + __popc(m3 & below);
        int col = (b + lane) * 4, o = 0;
        if (p0 && base + o < MAXM) { g_mf_idx[gw * MAXM + base + o] = col;     g_mf_val[gw * MAXM + base + o] = v.x; }
        if (p0) o++;
        if (p1 && base + o < MAXM) { g_mf_idx[gw * MAXM + base + o] = col + 1; g_mf_val[gw * MAXM + base + o] = v.y; }
        if (p1) o++;
        if (p2 && base + o < MAXM) { g_mf_idx[gw * MAXM + base + o] = col + 2; g_mf_val[gw * MAXM + base + o] = v.z; }
        if (p2) o++;
        if (p3 && base + o < MAXM) { g_mf_idx[gw * MAXM + base + o] = col + 3; g_mf_val[gw * MAXM + base + o] = v.w; }
        c += __popc(m0) + __popc(m1) + __popc(m2) + __popc(m3);
    }
    c = min(c, MAXM);
    __syncwarp();
    float vv[4];
    #pragma unroll
    for (int s = 0; s < 4; s++) {
        int t = s * 32 + lane;
        vv[s] = (t < c) ? g_mf_val[gw * MAXM + t] : -2.f;
    }
    float thr = 0.f;
    if (c > 8) {
        for (int r = 0; r < 8; r++) {
            float lm = fmaxf(fmaxf(vv[0], vv[1]), fmaxf(vv[2], vv[3]));
            float wm = lm;
            for (int o = 16; o; o >>= 1) wm = fmaxf(wm, __shfl_xor_sync(~0u, wm, o));
            unsigned who = __ballot_sync(~0u, lm == wm);
            if (lane == (__ffs(who) - 1)) {
                #pragma unroll
                for (int s = 0; s < 4; s++) if (vv[s] == wm) { vv[s] = -2.f; break; }
            }
            thr = wm;
        }
    }
    if (lane == 0) { g_mf_cnt[gw] = c; g_m_thr[gw] = thr; }
}

// R9 double-buffered 64x64 GEMM tile body
__device__ void gemm_tile_body(const float* __restrict__ A, const float* __restrict__ B,
                               float* __restrict__ C, int M, int Nc, int K,
                               int bm, int bn, float (*As)[16][65], float (*Bs)[16][65]) {
    int tid = threadIdx.x, tr = tid >> 4, tc = tid & 15;
    int am[4], ak[4], bk[4], bnn[4];
    float ra[4], rb[4];
    #pragma unroll
    for (int l = 0; l < 4; l++) {
        int e = tid + l * 256;
        am[l] = e >> 4; ak[l] = e & 15;
        bk[l] = e >> 6; bnn[l] = e & 63;
    }
    int nP = K / 16;
    #pragma unroll
    for (int l = 0; l < 4; l++) {
        ra[l] = A[(size_t)(bm + am[l]) * K + ak[l]];
        rb[l] = B[(size_t)bk[l] * Nc + bn + bnn[l]];
    }
    #pragma unroll
    for (int l = 0; l < 4; l++) {
        As[0][ak[l]][am[l]] = ra[l];
        Bs[0][bk[l]][bnn[l]] = rb[l];
    }
    __syncthreads();
    float acc[4][4] = {};
    for (int p = 0; p < nP; p++) {
        int cur = p & 1;
        if (p + 1 < nP) {
            int k0 = (p + 1) * 16;
            #pragma unroll
            for (int l = 0; l < 4; l++) {
                ra[l] = A[(size_t)(bm + am[l]) * K + k0 + ak[l]];
                rb[l] = B[(size_t)(k0 + bk[l]) * Nc + bn + bnn[l]];
            }
        }
        #pragma unroll
        for (int kk = 0; kk < 16; kk++) {
            float a[4], b[4];
            #pragma unroll
            for (int r = 0; r < 4; r++) a[r] = As[cur][kk][tr * 4 + r];
            #pragma unroll
            for (int c = 0; c < 4; c++) b[c] = Bs[cur][kk][tc * 4 + c];
            #pragma unroll
            for (int r = 0; r < 4; r++)
                #pragma unroll
                for (int c = 0; c < 4; c++) acc[r][c] += a[r] * b[c];
        }
        if (p + 1 < nP) {
            #pragma unroll
            for (int l = 0; l < 4; l++) {
                As[cur ^ 1][ak[l]][am[l]] = ra[l];
                Bs[cur ^ 1][bk[l]][bnn[l]] = rb[l];
            }
        }
        __syncthreads();
    }
    #pragma unroll
    for (int r = 0; r < 4; r++)
        #pragma unroll
        for (int c = 0; c < 4; c++)
            C[(size_t)(bm + tr * 4 + r) * Nc + bn + tc * 4 + c] = acc[r][c];
}

// ---------- Phase 1 fused ----------
__global__ void k_phase1(const float* __restrict__ A_in, const float* __restrict__ A_motif,
                         const float* __restrict__ x, const float* __restrict__ gat_w,
                         const float* __restrict__ gcnMw, float* __restrict__ Wx,
                         float* __restrict__ XWM) {
    __shared__ float As[2][16][65], Bs[2][16][65];
    int b = blockIdx.x;
    int lane = threadIdx.x & 31, wid = threadIdx.x >> 5;
    if (b < 512) {
        if (b < 16) g_cell_cnt[b * 256 + threadIdx.x] = 0;
        adj_row_body(A_in, b * 8 + wid, lane);
    } else if (b < 1024) {
        motif_row_body(A_motif, (b - 512) * 8 + wid, lane);
    } else if (b < 1280) {
        int t = b - 1024;
        gemm_tile_body(x, gat_w, Wx, NN, FH, 128, (t >> 2) * 64, (t & 3) * 64, As, Bs);
    } else {
        int t = b - 1280;
        gemm_tile_body(x, gcnMw, XWM, NN, FH, 128, (t >> 2) * 64, (t & 3) * 64, As, Bs);
    }
}

// ---------- Phase 2 fused: mfilter | attn_coef | cells insert ----------
__global__ void k_phase2(const float* __restrict__ coords,
                         const float* __restrict__ asw, const float* __restrict__ adw) {
    int b = blockIdx.x;
    if (b < 512) {
        int gw = b * 8 + (threadIdx.x >> 5), lane = threadIdx.x & 31;
        int i = gw, cnt = g_mf_cnt[i], out = 0;
        float thrI = g_m_thr[i], wsum = 0.f;
        for (int base = 0; base < cnt; base += 32) {
            int t = base + lane; bool ok = t < cnt; int j = 0; float v = 0.f;
            if (ok) {
                j = g_mf_idx[i * MAXM + t]; v = g_mf_val[i * MAXM + t];
                ok = (v >= thrI) || (v >= g_m_thr[j]);
            }
            unsigned m = __ballot_sync(0xffffffffu, ok);
            int pos = out + __popc(m & ((1u << lane) - 1));
            if (ok) { g_m_idx[i * MAXM + pos] = j; g_m_val[i * MAXM + pos] = v; wsum += v; }
            out += __popc(m);
        }
        for (int o = 16; o; o >>= 1) wsum += __shfl_down_sync(0xffffffffu, wsum, o);
        if (lane == 0) { g_m_cnt[i] = out; g_dinvM[i] = (wsum > 0.f) ? rsqrtf(wsum) : 0.f; }
    } else if (b < 1536) {
        int gw = (b - 512) * 8 + (threadIdx.x >> 5), lane = threadIdx.x & 31;
        int node = gw >> 1, hh = gw & 1;
        const float* row = g_Wx + (size_t)node * FH + hh * 128;
        float s = 0.f, d = 0.f;
        for (int k = lane; k < 128; k += 32) {
            float w = row[k];
            s += w * asw[hh * 128 + k];
            d += w * adw[hh * 128 + k];
        }
        for (int o = 16; o; o >>= 1) {
            s += __shfl_down_sync(0xffffffffu, s, o);
            d += __shfl_down_sync(0xffffffffu, d, o);
        }
        if (lane == 0) { g_as[node * 2 + hh] = s; g_ad[node * 2 + hh] = d; }
    } else {
        int i = (b - 1536) * 256 + threadIdx.x;
        int cx = (int)coords[2 * i], cy = (int)coords[2 * i + 1];
        int p = atomicAdd(&g_cell_cnt[cx * 64 + cy], 1);
        if (p < CELLCAP) g_cell_nodes[(cx * 64 + cy) * CELLCAP + p] = i;
    }
}

__global__ void k_gemm(const float* __restrict__ A, const float* __restrict__ B,
                       float* __restrict__ C, int M, int Nc, int K) {
    __shared__ float As[2][16][65], Bs[2][16][65];
    gemm_tile_body(A, B, C, M, Nc, K, blockIdx.y * 64, blockIdx.x * 64, As, Bs);
}

__global__ void k_gemm_tn(const float* __restrict__ A, const float* __restrict__ B,
                          float* __restrict__ Cpart, int M, int Nc, int K) {
    __shared__ float As[2][16][65], Bs[2][16][65];
    int ks = blockIdx.z, kbeg = ks * (K / KS);
    int nP = (K / KS) / 16;
    int bm = blockIdx.y * 64, bn = blockIdx.x * 64;
    int tid = threadIdx.x, tr = tid >> 4, tc = tid & 15;
    int lk[4], ln[4];
    float ra[4], rb[4];
    #pragma unroll
    for (int l = 0; l < 4; l++) {
        int e = tid + l * 256;
        lk[l] = e >> 6; ln[l] = e & 63;
    }
    #pragma unroll
    for (int l = 0; l < 4; l++) {
        ra[l] = A[(size_t)(kbeg + lk[l]) * M + bm + ln[l]];
        rb[l] = B[(size_t)(kbeg + lk[l]) * Nc + bn + ln[l]];
    }
    #pragma unroll
    for (int l = 0; l < 4; l++) {
        As[0][lk[l]][ln[l]] = ra[l];
        Bs[0][lk[l]][ln[l]] = rb[l];
    }
    __syncthreads();
    float acc[4][4] = {};
    for (int p = 0; p < nP; p++) {
        int cur = p & 1;
        if (p + 1 < nP) {
            int k0 = kbeg + (p + 1) * 16;
            #pragma unroll
            for (int l = 0; l < 4; l++) {
                ra[l] = A[(size_t)(k0 + lk[l]) * M + bm + ln[l]];
                rb[l] = B[(size_t)(k0 + lk[l]) * Nc + bn + ln[l]];
            }
        }
        #pragma unroll
        for (int kk = 0; kk < 16; kk++) {
            float a[4], b[4];
            #pragma unroll
            for (int r = 0; r < 4; r++) a[r] = As[cur][kk][tr * 4 + r];
            #pragma unroll
            for (int c = 0; c < 4; c++) b[c] = Bs[cur][kk][tc * 4 + c];
            #pragma unroll
            for (int r = 0; r < 4; r++)
                #pragma unroll
                for (int c = 0; c < 4; c++) acc[r][c] += a[r] * b[c];
        }
        if (p + 1 < nP) {
            #pragma unroll
            for (int l = 0; l < 4; l++) {
                As[cur ^ 1][lk[l]][ln[l]] = ra[l];
                Bs[cur ^ 1][lk[l]][ln[l]] = rb[l];
            }
        }
        __syncthreads();
    }
    float* Cp = Cpart + (size_t)ks * M * Nc;
    #pragma unroll
    for (int r = 0; r < 4; r++)
        #pragma unroll
        for (int c = 0; c < 4; c++)
            Cp[(size_t)(bm + tr * 4 + r) * Nc + bn + tc * 4 + c] = acc[r][c];
}

__global__ void k_reduce_part(float* __restrict__ dst, int MN) {
    int t = blockIdx.x * blockDim.x + threadIdx.x;
    if (t >= MN) return;
    float s = 0.f;
    for (int z = 0; z < KS; z++) s += g_Cpart[(size_t)z * MN + t];
    dst[t] = s;
}

// ---------- aggregate (128 thr, 2 dims/thr, reg-capped) + cells_sort tail ----------
__global__ void __launch_bounds__(128, 16) k_aggregate(
    const float* __restrict__ gat_b,
    const float* __restrict__ bnAg, const float* __restrict__ bnAb,
    const float* __restrict__ bnAm, const float* __restrict__ bnAv,
    const float* __restrict__ gcnMb,
    const float* __restrict__ bnMg, const float* __restrict__ bnMb,
    const float* __restrict__ bnMm, const float* __restrict__ bnMv,
    const float* __restrict__ mu_, const float* __restrict__ prune_w,
    const float* __restrict__ rewire_w)
{
    if (blockIdx.x >= NN) {
        int c = (blockIdx.x - NN) * 128 + threadIdx.x;
        int n = min(g_cell_cnt[c], CELLCAP);
        int* a = &g_cell_nodes[c * CELLCAP];
        for (int x = 1; x < n; x++) {
            int v = a[x], y = x - 1;
            while (y >= 0 && a[y] > v) { a[y + 1] = a[y]; y--; }
            a[y + 1] = v;
        }
        return;
    }
    __shared__ float se0[MAXDEG + 1], se1[MAXDEG + 1];
    __shared__ int   sj[MAXDEG + 1];
    __shared__ float2 ps0[MAXDEG + 1], ps1[MAXDEG + 1];
    __shared__ float2 psM[MAXM];
    __shared__ float rA[128], rB[128];
    int i = blockIdx.x, tid = threadIdx.x;
    int deg = g_adj_cnt[i], tot = deg + 1;
    float ad0 = g_ad[2 * i], ad1 = g_ad[2 * i + 1];
    for (int t = tid; t < tot; t += 128) {
        int j = (t < deg) ? g_adj_idx[i * MAXDEG + t] : i;
        sj[t] = j;
        float e0 = ad0 + g_as[2 * j], e1 = ad1 + g_as[2 * j + 1];
        se0[t] = (e0 > 0.f) ? e0 : 0.2f * e0;
        se1[t] = (e1 > 0.f) ? e1 : 0.2f * e1;
    }
    int mc = g_m_cnt[i];
    for (int t = tid; t < mc; t += 128) {
        int j = g_m_idx[i * MAXM + t];
        psM[t] = make_float2(g_m_val[i * MAXM + t] * g_dinvM[j], __int_as_float(j));
    }
    __syncthreads();
    float lm0 = -3.4e38f, lm1 = -3.4e38f;
    for (int t = tid; t < tot; t += 128) { lm0 = fmaxf(lm0, se0[t]); lm1 = fmaxf(lm1, se1[t]); }
    rA[tid] = lm0; rB[tid] = lm1; __syncthreads();
    for (int s = 64; s > 0; s >>= 1) {
        if (tid < s) { rA[tid] = fmaxf(rA[tid], rA[tid + s]); rB[tid] = fmaxf(rB[tid], rB[tid + s]); }
        __syncthreads();
    }
    float M0 = rA[0], M1 = rB[0]; __syncthreads();
    float ls0 = 0.f, ls1 = 0.f;
    for (int t = tid; t < tot; t += 128) {
        float jf = __int_as_float(sj[t]);
        float e0 = expf(se0[t] - M0); ps0[t] = make_float2(e0, jf); ls0 += e0;
        float e1 = expf(se1[t] - M1); ps1[t] = make_float2(e1, jf); ls1 += e1;
    }
    rA[tid] = ls0; rB[tid] = ls1; __syncthreads();
    for (int s = 64; s > 0; s >>= 1) {
        if (tid < s) { rA[tid] += rA[tid + s]; rB[tid] += rB[tid + s]; }
        __syncthreads();
    }
    float D0 = rA[0], D1 = rB[0]; __syncthreads();

    int head = tid >> 6;
    float Dh = head ? D1 : D0;
    const float2* ps = head ? ps1 : ps0;
    const float2* W2 = (const float2*)g_Wx;
    const float2* X2 = (const float2*)g_XWM;
    float2 accA = make_float2(0.f, 0.f);
    #pragma unroll 4
    for (int k = 0; k < tot; k++) {
        float2 p = ps[k];
        float2 v = W2[(size_t)__float_as_int(p.y) * (FH / 2) + tid];
        accA.x += p.x * v.x;
        accA.y += p.x * v.y;
    }
    const float2* gbv = (const float2*)gat_b;
    const float2* Amv = (const float2*)bnAm; const float2* Agv = (const float2*)bnAg;
    const float2* Avv = (const float2*)bnAv; const float2* Abv = (const float2*)bnAb;
    float2 gb = gbv[tid], Am = Amv[tid], Ag = Agv[tid], Av = Avv[tid], Ab = Abv[tid];
    float hA0 = accA.x / Dh + gb.x, hA1 = accA.y / Dh + gb.y;
    hA0 = (hA0 - Am.x) * Ag.x * rsqrtf(Av.x + 1e-5f) + Ab.x;
    hA1 = (hA1 - Am.y) * Ag.y * rsqrtf(Av.y + 1e-5f) + Ab.y;
    hA0 = (hA0 > 0.f) ? hA0 : expm1f(hA0);
    hA1 = (hA1 > 0.f) ? hA1 : expm1f(hA1);

    float2 accM = make_float2(0.f, 0.f);
    #pragma unroll 4
    for (int k = 0; k < mc; k++) {
        float2 p = psM[k];
        float2 v = X2[(size_t)__float_as_int(p.y) * (FH / 2) + tid];
        accM.x += p.x * v.x;
        accM.y += p.x * v.y;
    }
    const float2* Mbv = (const float2*)gcnMb;
    const float2* Mm = (const float2*)bnMm; const float2* Mg = (const float2*)bnMg;
    const float2* Mv = (const float2*)bnMv; const float2* Mb = (const float2*)bnMb;
    float2 mb = Mbv[tid], mm = Mm[tid], mg = Mg[tid], mv = Mv[tid], mbb = Mb[tid];
    float di = g_dinvM[i];
    float hM0 = di * accM.x + mb.x, hM1 = di * accM.y + mb.y;
    hM0 = (hM0 - mm.x) * mg.x * rsqrtf(mv.x + 1e-5f) + mbb.x;
    hM1 = (hM1 - mm.y) * mg.y * rsqrtf(mv.y + 1e-5f) + mbb.y;
    hM0 = (hM0 > 0.f) ? hM0 : expm1f(hM0);
    hM1 = (hM1 > 0.f) ? hM1 : expm1f(hM1);

    float mu = mu_[0];
    float sp = (mu > 20.f) ? mu : log1pf(expf(mu));
    float hv0 = hA0 + sp * hM0, hv1 = hA1 + sp * hM1;
    ((float2*)g_h)[(size_t)i * (FH / 2) + tid] = make_float2(hv0, hv1);

    const float2* pw = (const float2*)prune_w;
    const float2* rw = (const float2*)rewire_w;
    float2 p0 = pw[tid], p1 = pw[128 + tid];
    float2 r0v = rw[tid], r1v = rw[128 + tid];
    rA[tid] = hv0 * p0.x + hv1 * p0.y;
    rB[tid] = hv0 * p1.x + hv1 * p1.y;
    __syncthreads();
    for (int s = 64; s > 0; s >>= 1) {
        if (tid < s) { rA[tid] += rA[tid + s]; rB[tid] += rB[tid + s]; }
        __syncthreads();
    }
    float r0 = rA[0], r1 = rB[0]; __syncthreads();
    rA[tid] = hv0 * r0v.x + hv1 * r0v.y;
    rB[tid] = hv0 * r1v.x + hv1 * r1v.y;
    __syncthreads();
    for (int s = 64; s > 0; s >>= 1) {
        if (tid < s) { rA[tid] += rA[tid + s]; rB[tid] += rB[tid + s]; }
        __syncthreads();
    }
    if (tid == 0) { g_pu[i] = r0; g_pv[i] = r1; g_ru[i] = rA[0]; g_rv[i] = rB[0]; }
}

// ---------- candidates: flattened mapping + warp-coop mhat ----------
__global__ void k_candidates(const float* __restrict__ coords, const float* __restrict__ A_in,
                             const float* __restrict__ rw, const float* __restrict__ rb_,
                             const float* __restrict__ tau_) {
    int gw = (blockIdx.x * blockDim.x + threadIdx.x) >> 5;
    int lane = threadIdx.x & 31;
    if (gw >= NN) return;
    int i = gw;
    float tau = tau_[0], rw2 = rw[512], rb = rb_[0];
    int cx = (int)coords[2 * i], cy = (int)coords[2 * i + 1];
    const int ox[12] = {-2,-1,-1,-1, 0, 0, 0, 0, 1, 1, 1, 2};
    const int oy[12] = { 0,-1, 0, 1,-2,-1, 1, 2,-1, 0, 1, 0};
    int mycell = -1, mycc = 0;
    if (lane < 12) {
        int nx = cx + ox[lane], ny = cy + oy[lane];
        if (nx >= 0 && nx < 64 && ny >= 0 && ny < 64) {
            mycell = nx * 64 + ny;
            mycc = min(g_cell_cnt[mycell], CELLCAP);
        }
    }
    int tot = mycc;
    for (int o = 16; o; o >>= 1) tot += __shfl_xor_sync(~0u, tot, o);
    float rui = g_ru[i], rvi = g_rv[i];
    int cnt = 0;
    float m1 = NEGINF, m2 = NEGINF;
    for (int base = 0; base < tot; base += 32) {
        int r = base + lane;
        int cell = -1, off = 0, rr = r;
        #pragma unroll
        for (int o = 0; o < 12; o++) {
            int cc_o = __shfl_sync(~0u, mycc, o);
            int cell_o = __shfl_sync(~0u, mycell, o);
            if (rr >= 0 && rr < cc_o) { cell = cell_o; off = rr; }
            rr -= cc_o;
        }
        bool ok = (r < tot) && (cell >= 0);
        int j = -1;
        if (ok) {
            j = g_cell_nodes[cell * CELLCAP + off];
            ok = A_in[(size_t)i * NN + j] < 1e-6f;
            if (!ok) j = -1;
        }
        float mh = mhat_warp(i, j, lane);   // convergent; j=-1 -> 0
        float z = 0.f;
        if (ok) {
            float ruv = (i < j) ? (rui + g_rv[j]) : (g_ru[j] + rvi);
            z = hc_gate(ruv + rw2 * mh + rb, tau);
            if (z > m1) { m2 = m1; m1 = z; } else if (z > m2) { m2 = z; }
        }
        unsigned m = __ballot_sync(~0u, ok);
        int pos = cnt + __popc(m & ((1u << lane) - 1));
        if (ok && pos < MAXC) { g_cand_idx[i * MAXC + pos] = j; g_cand_z[i * MAXC + pos] = z; }
        cnt += __popc(m);
    }
    for (int o = 16; o; o >>= 1) {
        float om1 = __shfl_xor_sync(~0u, m1, o);
        float om2 = __shfl_xor_sync(~0u, m2, o);
        float hi = fmaxf(m1, om1), lo = fminf(m1, om1);
        m2 = fmaxf(lo, fmaxf(m2, om2));
        m1 = hi;
    }
    if (lane == 0) { g_cand_cnt[i] = min(cnt, MAXC); g_thr2[i] = m2; }
}

// ---------- refined: warp-coop mhat (chunked, convergent) ----------
__global__ void k_refined(const float* __restrict__ prune_w, const float* __restrict__ prune_b,
                          const float* __restrict__ tau_) {
    int gw = (blockIdx.x * blockDim.x + threadIdx.x) >> 5;
    int lane = threadIdx.x & 31;
    if (gw >= NN) return;
    int i = gw;
    float tau = tau_[0], pw2 = prune_w[512], pb = prune_b[0];
    int deg = g_adj_cnt[i];
    float wsum = 0.f;
    for (int base = 0; base < deg; base += 32) {
        int t = base + lane;
        bool act = t < deg;
        int j = act ? g_adj_idx[i * MAXDEG + t] : -1;
        float mh = mhat_warp(i, j, lane);
        if (act) {
            float puv = (i < j) ? (g_pu[i] + g_pv[j]) : (g_pu[j] + g_pv[i]);
            float z = hc_gate(puv + pw2 * mh + pb, tau);
            g_ref_idx[i * MAXR + t] = j;
            g_ref_w[i * MAXR + t] = z;
            wsum += z;
        }
    }
    int cnt = deg;
    float thrI = g_thr2[i];
    int cc = g_cand_cnt[i];
    for (int base = 0; base < cc; base += 32) {
        int t = base + lane; bool ok = false; int j = 0; float z = 0.f;
        if (t < cc) {
            j = g_cand_idx[i * MAXC + t]; z = g_cand_z[i * MAXC + t];
            ok = (z >= thrI) || (z >= g_thr2[j]);
        }
        unsigned m = __ballot_sync(0xffffffffu, ok);
        int pos = cnt + __popc(m & ((1u << lane) - 1));
        if (ok) { g_ref_idx[i * MAXR + pos] = j; g_ref_w[i * MAXR + pos] = 0.5f * z; wsum += 0.5f * z; }
        cnt += __popc(m);
    }
    for (int o = 16; o; o >>= 1) wsum += __shfl_down_sync(0xffffffffu, wsum, o);
    if (lane == 0) { g_ref_cnt[i] = cnt; g_dinv_ref[i] = rsqrtf(wsum + 1.f); }
}

__global__ void k_pool(const float* __restrict__ pool_b) {
    __shared__ float red[128];
    int i = blockIdx.x, c = threadIdx.x;
    float di = g_dinv_ref[i];
    int cnt = g_ref_cnt[i];
    float acc = di * g_HW[(size_t)i * CL + c];
    #pragma unroll 4
    for (int t = 0; t < cnt; t++) {
        int j = g_ref_idx[i * MAXR + t];
        acc += g_ref_w[i * MAXR + t] * g_dinv_ref[j] * g_HW[(size_t)j * CL + c];
    }
    float pre = di * acc + pool_b[c];
    red[c] = pre; __syncthreads();
    for (int s = 64; s > 0; s >>= 1) { if (c < s) red[c] = fmaxf(red[c], red[c + s]); __syncthreads(); }
    float mx = red[0]; __syncthreads();
    float e = expf(pre - mx);
    red[c] = e; __syncthreads();
    for (int s = 64; s > 0; s >>= 1) { if (c < s) red[c] += red[c + s]; __syncthreads(); }
    g_S[(size_t)i * CL + c] = e / red[0];
}

__global__ void k_spmmT() {
    int i = blockIdx.x, c = threadIdx.x;
    int cnt = g_ref_cnt[i];
    float acc = 0.f;
    #pragma unroll 4
    for (int t = 0; t < cnt; t++)
        acc += g_ref_w[i * MAXR + t] * g_S[(size_t)g_ref_idx[i * MAXR + t] * CL + c];
    g_T[(size_t)i * CL + c] = acc;
}

__global__ void k_coarse_thr() {
    int gw = (blockIdx.x * blockDim.x + threadIdx.x) >> 5;
    int lane = threadIdx.x & 31;
    if (gw >= 128) return;
    float vv[4];
    #pragma unroll
    for (int s = 0; s < 4; s++) {
        int j = s * 32 + lane;
        vv[s] = (j == gw) ? 0.f : g_Ac[gw * 128 + j];
    }
    float thr = 0.f;
    for (int r = 0; r < 8; r++) {
        float lm = fmaxf(fmaxf(vv[0], vv[1]), fmaxf(vv[2], vv[3]));
        float wm = lm;
        for (int o = 16; o; o >>= 1) wm = fmaxf(wm, __shfl_xor_sync(~0u, wm, o));
        unsigned who = __ballot_sync(~0u, lm == wm);
        if (lane == (__ffs(who) - 1)) {
            #pragma unroll
            for (int s = 0; s < 4; s++) if (vv[s] == wm) { vv[s] = -1e30f; break; }
        }
        thr = wm;
    }
    if (lane == 0) g_cthr[gw] = thr;
}

__global__ void k_coarse_write(float* __restrict__ out) {
    int t = blockIdx.x * blockDim.x + threadIdx.x;
    if (t >= 128 * 128) return;
    int i = t >> 7, j = t & 127;
    if (i == j) { out[t] = 0.f; return; }
    float vij = g_Ac[i * 128 + j];
    float vji = g_Ac[j * 128 + i];
    float a = (vij >= g_cthr[i]) ? vij : 0.f;
    float b = (vji >= g_cthr[j]) ? vji : 0.f;
    out[t] = fmaxf(a, b);
}

// ---------- host ----------
extern "C" void kernel_launch(void* const* d_in, const int* in_sizes, int n_in,
                              void* d_out, int out_size) {
    const float* x       = (const float*)d_in[0];
    const float* A_in    = (const float*)d_in[1];
    const float* A_motif = (const float*)d_in[2];
    const float* coords  = (const float*)d_in[3];
    const float* gat_w   = (const float*)d_in[4];
    const float* gat_as  = (const float*)d_in[5];
    const float* gat_ad  = (const float*)d_in[6];
    const float* gat_b   = (const float*)d_in[7];
    const float* bnAg = (const float*)d_in[8],  *bnAb = (const float*)d_in[9];
    const float* bnAm = (const float*)d_in[10], *bnAv = (const float*)d_in[11];
    const float* gcnMw = (const float*)d_in[12], *gcnMb = (const float*)d_in[13];
    const float* bnMg = (const float*)d_in[14], *bnMb = (const float*)d_in[15];
    const float* bnMm = (const float*)d_in[16], *bnMv = (const float*)d_in[17];
    const float* mu   = (const float*)d_in[18], *tau  = (const float*)d_in[19];
    const float* prune_w = (const float*)d_in[20], *prune_b = (const float*)d_in[21];
    const float* rewire_w = (const float*)d_in[22], *rewire_b = (const float*)d_in[23];
    const float* pool_w = (const float*)d_in[24], *pool_b = (const float*)d_in[25];
    float* out = (float*)d_out;

    float *Wx, *XWM, *h, *HW, *S, *T, *Cpart, *Ac;
    cudaGetSymbolAddress((void**)&Wx, g_Wx);
    cudaGetSymbolAddress((void**)&XWM, g_XWM);
    cudaGetSymbolAddress((void**)&h, g_h);
    cudaGetSymbolAddress((void**)&HW, g_HW);
    cudaGetSymbolAddress((void**)&S, g_S);
    cudaGetSymbolAddress((void**)&T, g_T);
    cudaGetSymbolAddress((void**)&Cpart, g_Cpart);
    cudaGetSymbolAddress((void**)&Ac, g_Ac);

    k_phase1<<<1536, 256>>>(A_in, A_motif, x, gat_w, gcnMw, Wx, XWM);
    k_phase2<<<1552, 256>>>(coords, gat_as, gat_ad);
    k_aggregate<<<NN + 32, 128>>>(gat_b, bnAg, bnAb, bnAm, bnAv, gcnMb,
                                  bnMg, bnMb, bnMm, bnMv, mu, prune_w, rewire_w);
    k_candidates<<<512, 256>>>(coords, A_in, rewire_w, rewire_b, tau);
    k_refined<<<512, 256>>>(prune_w, prune_b, tau);
    k_gemm<<<dim3(CL / 64, NN / 64), 256>>>(h, pool_w, HW, NN, CL, FH);
    k_pool<<<NN, 128>>>(pool_b);
    k_spmmT<<<NN, 128>>>();
    k_gemm_tn<<<dim3(FH / 64, 128 / 64, KS), 256>>>(S, h, Cpart, 128, FH, NN);
    k_reduce_part<<<(128 * FH + 255) / 256, 256>>>(out, 128 * FH);
    k_gemm_tn<<<dim3(CL / 64, 128 / 64, KS), 256>>>(S, T, Cpart, 128, CL, NN);
    k_reduce_part<<<(128 * CL + 255) / 256, 256>>>(Ac, 128 * CL);
    k_coarse_thr<<<16, 256>>>();
    k_coarse_write<<<64, 256>>>(out + 128 * FH);
}